// round 10
// baseline (speedup 1.0000x reference)
#include <cuda_runtime.h>
#include <cuda.h>
#include <cuda_fp16.h>
#include <math.h>
#include <stdint.h>

#define HW_   4096
#define NPIX_ 16384

#if defined(__CUDA_ARCH__) && (defined(__CUDA_ARCH_FEAT_SM103_ALL) || defined(__CUDA_ARCH_FEAT_SM100_ALL))
#define HAS_TC 1
#else
#define HAS_TC 0
#endif

#define WSCALE     64.0f
#define INV_WSCALE 0.015625f

// ---------------------------------------------------------------------------
// Scratch (device globals; allocation is forbidden). TMA sources aligned.
// ---------------------------------------------------------------------------
__device__ float g_featsA[4 * 512 * 4096];
__device__ float g_featsB[4 * 512 * 4096];
__device__ float g_v[4 * 512 * 4096];
__device__ float g_qk[4 * 128 * 4096];
__device__ float g_attn[4 * 4096 * 128];
__device__ float g_bqk[128];
__device__ __align__(128) __half g_xh[4 * 4096 * 2048];
__device__ __align__(128) __half g_fh[4 * 4096 * 512];
__device__ __align__(128) __half g_w1hi[9 * 512 * 2048];
__device__ __align__(128) __half g_w1lo[9 * 512 * 2048];
__device__ __align__(128) __half g_w2hi[9 * 512 * 512];
__device__ __align__(128) __half g_w2lo[9 * 512 * 512];
__device__ __align__(128) __half g_wqkhi[128 * 512];
__device__ __align__(128) __half g_wqklo[128 * 512];
__device__ __align__(128) __half g_wvhi[512 * 512];
__device__ __align__(128) __half g_wvlo[512 * 512];

// ---------------------------------------------------------------------------
// Generic helpers
// ---------------------------------------------------------------------------
__device__ __forceinline__ unsigned smem_u32(const void* p) {
    unsigned a;
    asm("{ .reg .u64 t; cvta.to.shared.u64 t, %1; cvt.u32.u64 %0, t; }"
        : "=r"(a) : "l"(p));
    return a;
}
__device__ __forceinline__ unsigned elect_one() {
    unsigned p;
    asm volatile("{ .reg .pred p; elect.sync _|p, 0xFFFFFFFF; selp.b32 %0, 1, 0, p; }"
                 : "=r"(p));
    return p;
}
#define SW128(o) ((o) ^ (((o) >> 3) & 0x70))
__device__ __forceinline__ void mbar_init(unsigned mbar, unsigned cnt) {
    asm volatile("mbarrier.init.shared.b64 [%0], %1;" :: "r"(mbar), "r"(cnt) : "memory");
}
__device__ __forceinline__ void mbar_wait(unsigned mbar, unsigned phase) {
    asm volatile(
        "{\n\t.reg .pred P;\n\t"
        "WL_%=:\n\t"
        "mbarrier.try_wait.parity.acquire.cta.shared::cta.b64 P, [%0], %1, 0x989680;\n\t"
        "@P bra.uni WD_%=;\n\t"
        "bra.uni WL_%=;\n\t"
        "WD_%=:\n\t}"
        :: "r"(mbar), "r"(phase) : "memory");
}
__device__ __forceinline__ void fence_async_shared() {
    asm volatile("fence.proxy.async;" ::: "memory");
}

// ---------------------------------------------------------------------------
// tcgen05 / TMA / cluster helpers (arch-specific pass only)
// ---------------------------------------------------------------------------
#if HAS_TC
static constexpr unsigned long long SMEM_DESC_BASE_SW128 =
    (2ull << 61) | (1ull << 46) | (64ull << 32) | (1ull << 16);
__device__ __forceinline__ unsigned long long make_desc(unsigned addr) {
    return SMEM_DESC_BASE_SW128 | ((unsigned long long)(addr >> 4) & 0x3FFFull);
}
__device__ __forceinline__ void cluster_sync_() {
    asm volatile("barrier.cluster.arrive.aligned;" ::: "memory");
    asm volatile("barrier.cluster.wait.aligned;" ::: "memory");
}
__device__ __forceinline__ void mbar_expect_tx(unsigned mbar, unsigned bytes) {
    asm volatile("mbarrier.arrive.expect_tx.shared.b64 _, [%0], %1;"
                 :: "r"(mbar), "r"(bytes) : "memory");
}
__device__ __forceinline__ void tmem_alloc_cg1(unsigned dst_smem, unsigned ncols) {
    asm volatile("tcgen05.alloc.cta_group::1.sync.aligned.shared::cta.b32 [%0], %1;"
                 :: "r"(dst_smem), "r"(ncols) : "memory");
}
__device__ __forceinline__ void tmem_dealloc_cg1(unsigned tmem, unsigned ncols) {
    asm volatile("tcgen05.dealloc.cta_group::1.sync.aligned.b32 %0, %1;"
                 :: "r"(tmem), "r"(ncols));
}
__device__ __forceinline__ void tmem_alloc_cg2(unsigned dst_smem, unsigned ncols) {
    asm volatile("tcgen05.alloc.cta_group::2.sync.aligned.shared::cta.b32 [%0], %1;"
                 :: "r"(dst_smem), "r"(ncols) : "memory");
}
__device__ __forceinline__ void tmem_dealloc_cg2(unsigned tmem, unsigned ncols) {
    asm volatile("tcgen05.dealloc.cta_group::2.sync.aligned.b32 %0, %1;"
                 :: "r"(tmem), "r"(ncols));
}
__device__ __forceinline__ void tc_relinquish_cg2() {
    asm volatile("tcgen05.relinquish_alloc_permit.cta_group::2.sync.aligned;");
}
__device__ __forceinline__ void tc_commit_cg1(unsigned mbar) {
    asm volatile("tcgen05.commit.cta_group::1.mbarrier::arrive::one.shared::cluster.b64 [%0];"
                 :: "r"(mbar) : "memory");
}
__device__ __forceinline__ void tc_commit_mc_cg2(unsigned mbar, unsigned short mask) {
    asm volatile("tcgen05.commit.cta_group::2.mbarrier::arrive::one.shared::cluster.multicast::cluster.b64 [%0], %1;"
                 :: "r"(mbar), "h"(mask) : "memory");
}
__device__ __forceinline__ void tc_fence_after() {
    asm volatile("tcgen05.fence::after_thread_sync;" ::: "memory");
}
__device__ __forceinline__ void tc_wait_ld() {
    asm volatile("tcgen05.wait::ld.sync.aligned;" ::: "memory");
}
__device__ __forceinline__ void mma_cg1(unsigned d, unsigned long long ad,
                                        unsigned long long bd, unsigned idesc, unsigned en) {
    asm volatile(
        "{\n\t.reg .pred p;\n\tsetp.ne.u32 p, %4, 0;\n\t"
        "tcgen05.mma.cta_group::1.kind::f16 [%0], %1, %2, %3, {%5, %5, %5, %5}, p;\n\t}"
        :: "r"(d), "l"(ad), "l"(bd), "r"(idesc), "r"(en), "r"(0u) : "memory");
}
__device__ __forceinline__ void mma_cg2(unsigned d, unsigned long long ad,
                                        unsigned long long bd, unsigned idesc, unsigned en) {
    asm volatile(
        "{\n\t.reg .pred p;\n\tsetp.ne.u32 p, %4, 0;\n\t"
        "tcgen05.mma.cta_group::2.kind::f16 [%0], %1, %2, %3, "
        "{%5, %5, %5, %5, %5, %5, %5, %5}, p;\n\t}"
        :: "r"(d), "l"(ad), "l"(bd), "r"(idesc), "r"(en), "r"(0u) : "memory");
}
__device__ __forceinline__ void tmem_ld32(unsigned* r, unsigned addr) {
    asm volatile(
        "tcgen05.ld.sync.aligned.32x32b.x32.b32 "
        "{%0, %1, %2, %3, %4, %5, %6, %7, "
        " %8, %9, %10, %11, %12, %13, %14, %15, "
        " %16, %17, %18, %19, %20, %21, %22, %23, "
        " %24, %25, %26, %27, %28, %29, %30, %31}, [%32];"
        : "=r"(r[0]),  "=r"(r[1]),  "=r"(r[2]),  "=r"(r[3]),
          "=r"(r[4]),  "=r"(r[5]),  "=r"(r[6]),  "=r"(r[7]),
          "=r"(r[8]),  "=r"(r[9]),  "=r"(r[10]), "=r"(r[11]),
          "=r"(r[12]), "=r"(r[13]), "=r"(r[14]), "=r"(r[15]),
          "=r"(r[16]), "=r"(r[17]), "=r"(r[18]), "=r"(r[19]),
          "=r"(r[20]), "=r"(r[21]), "=r"(r[22]), "=r"(r[23]),
          "=r"(r[24]), "=r"(r[25]), "=r"(r[26]), "=r"(r[27]),
          "=r"(r[28]), "=r"(r[29]), "=r"(r[30]), "=r"(r[31])
        : "r"(addr));
}
__device__ __forceinline__ void tma3d_cg2(unsigned dst, const CUtensorMap* m,
                                          int x, int y, int z, unsigned bar) {
    asm volatile(
        "{\n\t.reg .b32 lb;\n\tand.b32 lb, %5, 0xFEFFFFFF;\n\t"
        "cp.async.bulk.tensor.3d.cta_group::2.shared::cluster.global"
        ".tile.mbarrier::complete_tx::bytes [%0], [%1, {%2, %3, %4}], [lb];\n\t}"
        :: "r"(dst), "l"(m), "r"(x), "r"(y), "r"(z), "r"(bar) : "memory");
}
__device__ __forceinline__ void tma4d_cg2(unsigned dst, const CUtensorMap* m,
                                          int x, int y, int z, int w, unsigned bar) {
    asm volatile(
        "{\n\t.reg .b32 lb;\n\tand.b32 lb, %6, 0xFEFFFFFF;\n\t"
        "cp.async.bulk.tensor.4d.cta_group::2.shared::cluster.global"
        ".tile.mbarrier::complete_tx::bytes [%0], [%1, {%2, %3, %4, %5}], [lb];\n\t}"
        :: "r"(dst), "l"(m), "r"(x), "r"(y), "r"(z), "r"(w), "r"(bar) : "memory");
}
#endif

// ---------------------------------------------------------------------------
// Prep kernels
// ---------------------------------------------------------------------------
__device__ __forceinline__ void split_half(float x, __half& h, __half& l) {
    h = __float2half(x);
    l = __float2half(x - __half2float(h));
}

__global__ void prep_act(const float* __restrict__ src,
                         __half* __restrict__ dh, int CIN) {
    __shared__ float t[32][33];
    const int b = blockIdx.z, ct = blockIdx.y * 32, pt = blockIdx.x * 32;
    const int tx = threadIdx.x, ty = threadIdx.y;
    for (int i = ty; i < 32; i += 8)
        t[i][tx] = src[((size_t)(b * CIN + ct + i)) * HW_ + pt + tx];
    __syncthreads();
    for (int i = ty; i < 32; i += 8) {
        size_t o = ((size_t)(b * HW_ + pt + i)) * CIN + ct + tx;
        dh[o] = __float2half(t[tx][i]);
    }
}

__global__ void prep_wconv(const float* __restrict__ W,
                           __half* __restrict__ dhi,
                           __half* __restrict__ dlo, int M, int CIN) {
    int idx = blockIdx.x * 256 + threadIdx.x;
    if (idx >= M * CIN) return;
#pragma unroll
    for (int tap = 0; tap < 9; tap++) {
        float x = W[(size_t)idx * 9 + tap] * WSCALE;
        __half h, l;
        split_half(x, h, l);
        size_t o = (size_t)tap * M * CIN + idx;
        dhi[o] = h;
        dlo[o] = l;
    }
}

__global__ void prep_wlin(const float* __restrict__ W,
                          __half* __restrict__ dhi,
                          __half* __restrict__ dlo, int n) {
    int i = blockIdx.x * 256 + threadIdx.x;
    if (i >= n) return;
    __half h, l;
    split_half(W[i] * WSCALE, h, l);
    dhi[i] = h;
    dlo[i] = l;
}

__global__ void prep_wqk(const float* __restrict__ qw, const float* __restrict__ kw,
                         const float* __restrict__ qb, const float* __restrict__ kb,
                         __half* __restrict__ dhi, __half* __restrict__ dlo,
                         float* __restrict__ bias) {
    int i = blockIdx.x * 256 + threadIdx.x;
    if (i < 128) bias[i] = (i < 64) ? qb[i] : kb[i - 64];
    if (i >= 128 * 512) return;
    float x = ((i < 64 * 512) ? qw[i] : kw[i - 64 * 512]) * WSCALE;
    __half h, l;
    split_half(x, h, l);
    dhi[i] = h;
    dlo[i] = l;
}

// ---------------------------------------------------------------------------
// cg2 implicit-conv GEMM, TMA pipeline with 2-chunk lead (3-stage ring).
// ---------------------------------------------------------------------------
template<int CIN, int TAPS, int EPI>
__global__ void __launch_bounds__(256, 1) __cluster_dims__(2, 1, 1)
mma_conv_tma(const __grid_constant__ CUtensorMap tWhi,
             const __grid_constant__ CUtensorMap tWlo,
             const __grid_constant__ CUtensorMap tX,
             const float* __restrict__ e0, const float* __restrict__ e1,
             const float* __restrict__ e2, const float* __restrict__ e3,
             float* __restrict__ Y, int Mtot)
{
#if HAS_TC
    constexpr int NCHUNK = TAPS * (CIN / 64);
    constexpr int NST   = 3;
    constexpr int A_HI  = 0;
    constexpr int A_LO  = 16384;
    constexpr int B_0   = 32768;
    constexpr int STAGE = 65536;
    constexpr unsigned IDESC2 = (1u << 4) | (16u << 17) | (16u << 24);
    static_assert(NCHUNK >= 3, "pipeline needs >=3 chunks");

    extern __shared__ char dyn_smem[];
    __shared__ __align__(8) unsigned long long s_full[NST];
    __shared__ __align__(8) unsigned long long s_done[NST];
    __shared__ unsigned s_tmem[1];

    char* sm = (char*)((((uintptr_t)dyn_smem) + 1023) & ~(uintptr_t)1023);
    const unsigned sbase = smem_u32(sm);

    const int tid  = threadIdx.x;
    const int wid  = tid >> 5;
    const int lane = tid & 31;
    const unsigned rank = blockIdx.x & 1;
    const int m_base = (blockIdx.x >> 1) * 256;
    const int n_base = blockIdx.y * 512;
    const int bb    = n_base >> 12;
    const int sp00  = n_base & 4095;
    const int hrow0 = sp00 >> 6;

    if (wid == 0) tmem_alloc_cg2(smem_u32(&s_tmem[0]), 512);
    if (tid == 0) {
#pragma unroll
        for (int s = 0; s < NST; ++s) {
            mbar_init(smem_u32(&s_full[s]), 1);
            mbar_init(smem_u32(&s_done[s]), 1);
        }
    }
    __syncthreads();
    unsigned tmem;
    asm volatile("ld.shared.b32 %0, [%1];" : "=r"(tmem) : "r"(smem_u32(&s_tmem[0])));
    unsigned fullb[NST], doneb[NST];
#pragma unroll
    for (int s = 0; s < NST; ++s) {
        fullb[s] = smem_u32(&s_full[s]);
        doneb[s] = smem_u32(&s_done[s]);
    }
    cluster_sync_();

    if (tid == 0) {
        int dph[NST] = {0, 0, 0};
        int fph[NST] = {0, 0, 0};

        auto issue_tma = [&](int i) {
            const int s   = i % NST;
            const int tap = (TAPS == 1) ? 0 : i / (CIN / 64);
            const int cb  = (TAPS == 1) ? i * 64 : (i % (CIN / 64)) * 64;
            const int dh  = (TAPS == 9) ? (tap / 3 - 1) : 0;
            const int dw  = (TAPS == 9) ? (tap % 3 - 1) : 0;
            const unsigned stg = sbase + s * STAGE;
            tma3d_cg2(stg + A_HI, &tWhi, cb, m_base + (int)rank * 128, tap, fullb[s]);
            tma3d_cg2(stg + A_LO, &tWlo, cb, m_base + (int)rank * 128, tap, fullb[s]);
#pragma unroll
            for (int t = 0; t < 4; ++t)
                tma4d_cg2(stg + B_0 + t * 8192, &tX,
                          cb, dw, hrow0 + 2 * t + (int)rank + dh, bb, fullb[s]);
        };

        // prologue: chunks 0 and 1 in flight
        for (int i = 0; i < 2; ++i) {
            if (rank == 0) mbar_expect_tx(fullb[i % NST], 2 * STAGE);
            issue_tma(i);
        }

        for (int i = 0; i < NCHUNK; ++i) {
            const int s = i % NST;
            if (rank == 0) {
                mbar_wait(fullb[s], fph[s]); fph[s] ^= 1;
                const unsigned sg = sbase + s * STAGE;
                unsigned long long dAh = make_desc(sg + A_HI);
                unsigned long long dAl = make_desc(sg + A_LO);
#pragma unroll
                for (int t = 0; t < 4; ++t) {
                    unsigned d = tmem + t * 128;
                    unsigned long long dB = make_desc(sg + B_0 + t * 8192);
#pragma unroll
                    for (int kk = 0; kk < 4; ++kk) {
                        unsigned en0 = (i > 0 || kk > 0) ? 1u : 0u;
                        mma_cg2(d, dAh + kk * 2, dB + kk * 2, IDESC2, en0);
                        mma_cg2(d, dAl + kk * 2, dB + kk * 2, IDESC2, 1u);
                    }
                }
                tc_commit_mc_cg2(doneb[s], 0x3);
            }
            const int nx = i + 2;
            if (nx < NCHUNK) {
                const int sn = nx % NST;      // == (i-1) % NST
                if (i >= 1) { mbar_wait(doneb[sn], dph[sn]); dph[sn] ^= 1; }
                if (rank == 0) mbar_expect_tx(fullb[sn], 2 * STAGE);
                issue_tma(nx);
            }
        }
        // final drain: last chunk's done (all prior commits for its stage were waited)
        const int sl = (NCHUNK - 1) % NST;
        mbar_wait(doneb[sl], dph[sl]);
    }
    __syncthreads();
    tc_fence_after();

    // --- epilogue ---
    {
        const int wg = wid >> 2;
        const int mg = m_base + (int)rank * 128 + (wid & 3) * 32 + lane;
        float sc, sh;
        if (EPI == 1) {
            float tt = e0[mg] * rsqrtf(e3[mg] + 1e-5f);
            sc = tt * INV_WSCALE;
            sh = e1[mg] - e2[mg] * tt;
        } else {
            sc = INV_WSCALE;
            sh = e0[mg];
        }
        float* yrow = Y + ((size_t)(bb * Mtot + mg)) * HW_ + sp00;
#pragma unroll
        for (int ti = 0; ti < 2; ++ti) {
            int t = wg * 2 + ti;
#pragma unroll
            for (int cb4 = 0; cb4 < 4; ++cb4) {
                unsigned r[32];
                tmem_ld32(r, tmem + t * 128 + cb4 * 32);
                tc_wait_ld();
#pragma unroll
                for (int j = 0; j < 32; j += 4) {
                    float4 v;
                    v.x = fmaf(__uint_as_float(r[j + 0]), sc, sh);
                    v.y = fmaf(__uint_as_float(r[j + 1]), sc, sh);
                    v.z = fmaf(__uint_as_float(r[j + 2]), sc, sh);
                    v.w = fmaf(__uint_as_float(r[j + 3]), sc, sh);
                    if (EPI == 1) {
                        v.x = fmaxf(v.x, 0.f); v.y = fmaxf(v.y, 0.f);
                        v.z = fmaxf(v.z, 0.f); v.w = fmaxf(v.w, 0.f);
                    }
                    *(float4*)(yrow + t * 128 + cb4 * 32 + j) = v;
                }
            }
        }
    }
    __syncthreads();
    if (wid == 0) {
        tc_relinquish_cg2();
        tmem_dealloc_cg2(tmem, 512);
    }
    cluster_sync_();
#endif
}

// ---------------------------------------------------------------------------
// cg1 GEMM for the stacked q/k projection (M=128), fp16 2-MMA scheme (proven)
// ---------------------------------------------------------------------------
template<int CIN>
__global__ void __launch_bounds__(256, 1)
mma_proj_cg1(const __half* __restrict__ Whi, const __half* __restrict__ Wlo,
             const __half* __restrict__ Xh,
             const float* __restrict__ e0, float* __restrict__ Y, int Mtot)
{
#if HAS_TC
    constexpr int A_BYTES = 128 * 128;
    constexpr int B_BYTES = 128 * 128;
    constexpr int STAGE   = 2 * A_BYTES + B_BYTES;
    constexpr int NCHUNK  = CIN / 64;
    constexpr unsigned IDESC = (1u << 4) | (16u << 17) | (8u << 24);

    extern __shared__ char dyn_smem[];
    __shared__ __align__(8) unsigned long long s_mbar[2];
    __shared__ unsigned s_tmem[1];

    char* sm = (char*)((((uintptr_t)dyn_smem) + 1023) & ~(uintptr_t)1023);
    const unsigned sbase = smem_u32(sm);
    const int tid = threadIdx.x;
    const int wid = tid >> 5;
    const int lane = tid & 31;

    if (wid == 0) tmem_alloc_cg1(smem_u32(&s_tmem[0]), 256);
    if (tid == 0) { mbar_init(smem_u32(&s_mbar[0]), 1); mbar_init(smem_u32(&s_mbar[1]), 1); }
    __syncthreads();
    unsigned tmem;
    asm volatile("ld.shared.b32 %0, [%1];" : "=r"(tmem) : "r"(smem_u32(&s_tmem[0])));
    const unsigned mbar[2] = { smem_u32(&s_mbar[0]), smem_u32(&s_mbar[1]) };

    const int n_base = blockIdx.y * 128;
    const int bb  = n_base >> 12;
    const int sp0 = n_base & 4095;
    int ph[2] = {0, 0};

    for (int chunk = 0; chunk < NCHUNK; ++chunk) {
        const int s  = chunk & 1;
        const int cb = chunk * 64;
        if (chunk >= 2) { mbar_wait(mbar[s], ph[s]); ph[s] ^= 1; }

        char* aHi = sm + s * STAGE;
        char* aLo = aHi + A_BYTES;
        char* bH  = aLo + A_BYTES;
#pragma unroll
        for (int u = 0; u < 4; ++u) {
            int l = u * 256 + tid;
            int row = l >> 3, c16 = l & 7;
            size_t go = (size_t)row * CIN + cb + c16 * 8;
            unsigned so = SW128((unsigned)(row * 128 + c16 * 16));
            *(uint4*)(aHi + so) = *(const uint4*)(Whi + go);
            *(uint4*)(aLo + so) = *(const uint4*)(Wlo + go);
        }
#pragma unroll
        for (int u = 0; u < 4; ++u) {
            int l = u * 256 + tid;
            int row = l >> 3, c16 = l & 7;
            size_t go = ((size_t)(bb * HW_ + sp0 + row)) * CIN + cb + c16 * 8;
            unsigned so = SW128((unsigned)(row * 128 + c16 * 16));
            *(uint4*)(bH + so) = *(const uint4*)(Xh + go);
        }
        fence_async_shared();
        __syncthreads();

        if (wid == 0 && elect_one()) {
            unsigned long long dAh = make_desc(sbase + s * STAGE);
            unsigned long long dAl = dAh + (A_BYTES >> 4);
            unsigned long long dB  = make_desc(sbase + s * STAGE + 2 * A_BYTES);
#pragma unroll
            for (int kk = 0; kk < 4; ++kk) {
                unsigned en0 = (chunk > 0 || kk > 0) ? 1u : 0u;
                mma_cg1(tmem, dAh + kk * 2, dB + kk * 2, IDESC, en0);
                mma_cg1(tmem, dAl + kk * 2, dB + kk * 2, IDESC, 1u);
            }
            tc_commit_cg1(mbar[s]);
        }
    }
    {
        int s0 = (NCHUNK - 2) & 1, s1 = (NCHUNK - 1) & 1;
        mbar_wait(mbar[s0], ph[s0]); ph[s0] ^= 1;
        mbar_wait(mbar[s1], ph[s1]); ph[s1] ^= 1;
    }
    tc_fence_after();

    if (wid < 4) {
        const int mg = wid * 32 + lane;
        float sh = e0[mg];
        float* yrow = Y + ((size_t)(bb * Mtot + mg)) * HW_ + sp0;
#pragma unroll
        for (int cb4 = 0; cb4 < 4; ++cb4) {
            unsigned r[32];
            tmem_ld32(r, tmem + cb4 * 32);
            tc_wait_ld();
#pragma unroll
            for (int j = 0; j < 32; j += 4) {
                float4 v;
                v.x = fmaf(__uint_as_float(r[j + 0]), INV_WSCALE, sh);
                v.y = fmaf(__uint_as_float(r[j + 1]), INV_WSCALE, sh);
                v.z = fmaf(__uint_as_float(r[j + 2]), INV_WSCALE, sh);
                v.w = fmaf(__uint_as_float(r[j + 3]), INV_WSCALE, sh);
                *(float4*)(yrow + cb4 * 32 + j) = v;
            }
        }
    }
    __syncthreads();
    if (wid == 0) tmem_dealloc_cg1(tmem, 256);
#endif
}

// ---------------------------------------------------------------------------
// CCA kernels (R6 scalar versions — proven)
// ---------------------------------------------------------------------------
__global__ void __launch_bounds__(256) energyH_kernel(
    const float* __restrict__ qk, float* __restrict__ attn)
{
    const int w = blockIdx.x, b = blockIdx.y;
    __shared__ float Qs[64][65];
    __shared__ float Ks[64][65];
    const int tid = threadIdx.x;
    for (int l = tid; l < 4096; l += 256) {
        int c = l >> 6, h = l & 63;
        Qs[c][h] = qk[((size_t)(b * 128 + c)) * HW_ + h * 64 + w];
        Ks[c][h] = qk[((size_t)(b * 128 + 64 + c)) * HW_ + h * 64 + w];
    }
    __syncthreads();
    const int hh = tid & 63, ig = tid >> 6;
    float acc[16];
#pragma unroll
    for (int i = 0; i < 16; i++) acc[i] = 0.f;
    for (int c = 0; c < 64; c++) {
        float qv = Qs[c][hh];
#pragma unroll
        for (int i = 0; i < 16; i++) acc[i] += qv * Ks[c][ig * 16 + i];
    }
    float* orow = attn + (size_t)(((b * 64 + hh) * 64 + w)) * 128;
#pragma unroll
    for (int i = 0; i < 16; i++) {
        int ii = ig * 16 + i;
        orow[ii] = acc[i] + ((ii == hh) ? -1000000000.0f : 0.f);
    }
}

__global__ void __launch_bounds__(256) energyW_kernel(
    const float* __restrict__ qk, float* __restrict__ attn)
{
    const int h = blockIdx.x, b = blockIdx.y;
    __shared__ float Qs[64][65];
    __shared__ float Ks[64][65];
    const int tid = threadIdx.x;
    for (int l = tid; l < 4096; l += 256) {
        int c = l >> 6, w = l & 63;
        Qs[c][w] = qk[((size_t)(b * 128 + c)) * HW_ + h * 64 + w];
        Ks[c][w] = qk[((size_t)(b * 128 + 64 + c)) * HW_ + h * 64 + w];
    }
    __syncthreads();
    const int wq = tid & 63, jg = tid >> 6;
    float acc[16];
#pragma unroll
    for (int j = 0; j < 16; j++) acc[j] = 0.f;
    for (int c = 0; c < 64; c++) {
        float qv = Qs[c][wq];
#pragma unroll
        for (int j = 0; j < 16; j++) acc[j] += qv * Ks[c][jg * 16 + j];
    }
    float* orow = attn + (size_t)(((b * 64 + h) * 64 + wq)) * 128 + 64;
#pragma unroll
    for (int j = 0; j < 16; j++) orow[jg * 16 + j] = acc[j];
}

__global__ void __launch_bounds__(256) softmax_kernel(float* __restrict__ attn)
{
    int gw = (blockIdx.x * blockDim.x + threadIdx.x) >> 5;
    if (gw >= NPIX_) return;
    int lane = threadIdx.x & 31;
    float* row = attn + (size_t)gw * 128;
    float v0 = row[lane], v1 = row[lane + 32], v2 = row[lane + 64], v3 = row[lane + 96];
    float mx = fmaxf(fmaxf(v0, v1), fmaxf(v2, v3));
#pragma unroll
    for (int o = 16; o > 0; o >>= 1) mx = fmaxf(mx, __shfl_xor_sync(0xffffffffu, mx, o));
    v0 = expf(v0 - mx); v1 = expf(v1 - mx); v2 = expf(v2 - mx); v3 = expf(v3 - mx);
    float s = v0 + v1 + v2 + v3;
#pragma unroll
    for (int o = 16; o > 0; o >>= 1) s += __shfl_xor_sync(0xffffffffu, s, o);
    float inv = 1.0f / s;
    row[lane] = v0 * inv; row[lane + 32] = v1 * inv;
    row[lane + 64] = v2 * inv; row[lane + 96] = v3 * inv;
}

__global__ void __launch_bounds__(256) aggH_kernel(
    const float* __restrict__ v, const float* __restrict__ attn,
    const float* __restrict__ fin, float* __restrict__ fout,
    const float* __restrict__ gptr)
{
    const int w = blockIdx.x, b = blockIdx.y, cbk = blockIdx.z * 64;
    __shared__ float Vs[64][65];
    __shared__ float Am[64][65];
    const int tid = threadIdx.x;
    for (int l = tid; l < 4096; l += 256) {
        int c = l >> 6, i = l & 63;
        Vs[c][i] = v[(size_t)((b * 512 + cbk + c) * 64 + i) * 64 + w];
    }
    for (int l = tid; l < 4096; l += 256) {
        int h = l >> 6, i = l & 63;
        Am[h][i] = attn[(size_t)(((b * 64 + h) * 64 + w)) * 128 + i];
    }
    __syncthreads();
    const int tc = tid & 63, hg = tid >> 6;
    float acc[16];
#pragma unroll
    for (int t = 0; t < 16; t++) acc[t] = 0.f;
    for (int i = 0; i < 64; i++) {
        float vv = Vs[tc][i];
#pragma unroll
        for (int t = 0; t < 16; t++) acc[t] += vv * Am[hg * 16 + t][i];
    }
    const float g = *gptr;
#pragma unroll
    for (int t = 0; t < 16; t++) {
        int h = hg * 16 + t;
        size_t idx = (size_t)((b * 512 + cbk + tc) * 64 + h) * 64 + w;
        fout[idx] = fin[idx] + g * acc[t];
    }
}

__global__ void __launch_bounds__(256) aggW_kernel(
    const float* __restrict__ v, const float* __restrict__ attn,
    float* __restrict__ fout, const float* __restrict__ gptr)
{
    const int h = blockIdx.x, b = blockIdx.y, cbk = blockIdx.z * 64;
    __shared__ float Vs[64][65];
    __shared__ float Am[64][65];
    const int tid = threadIdx.x;
    for (int l = tid; l < 4096; l += 256) {
        int c = l >> 6, j = l & 63;
        Vs[c][j] = v[(size_t)((b * 512 + cbk + c) * 64 + h) * 64 + j];
    }
    for (int l = tid; l < 4096; l += 256) {
        int w = l >> 6, j = l & 63;
        Am[w][j] = attn[(size_t)(((b * 64 + h) * 64 + w)) * 128 + 64 + j];
    }
    __syncthreads();
    const int tc = tid & 63, wg = tid >> 6;
    float acc[16];
#pragma unroll
    for (int t = 0; t < 16; t++) acc[t] = 0.f;
    for (int j = 0; j < 64; j++) {
        float vv = Vs[tc][j];
#pragma unroll
        for (int t = 0; t < 16; t++) acc[t] += vv * Am[wg * 16 + t][j];
    }
    const float g = *gptr;
#pragma unroll
    for (int t = 0; t < 16; t++) {
        int w = wg * 16 + t;
        size_t idx = (size_t)((b * 512 + cbk + tc) * 64 + h) * 64 + w;
        fout[idx] += g * acc[t];
    }
}

// ---------------------------------------------------------------------------
// Host: tensor-map encoding via runtime driver-entry-point
// ---------------------------------------------------------------------------
typedef CUresult (*EncodeTiledFn)(
    CUtensorMap*, CUtensorMapDataType, cuuint32_t, void*,
    const cuuint64_t*, const cuuint64_t*, const cuuint32_t*, const cuuint32_t*,
    CUtensorMapInterleave, CUtensorMapSwizzle, CUtensorMapL2promotion,
    CUtensorMapFloatOOBfill);

static EncodeTiledFn get_encode_fn() {
    static EncodeTiledFn fn = nullptr;
    if (!fn) {
        void* p = nullptr;
        cudaDriverEntryPointQueryResult st;
        cudaGetDriverEntryPointByVersion("cuTensorMapEncodeTiled", &p, 12000,
                                         cudaEnableDefault, &st);
        fn = (EncodeTiledFn)p;
    }
    return fn;
}

static void encode_w3d(CUtensorMap* tm, void* ptr,
                       unsigned long long cin, unsigned long long m,
                       unsigned long long taps) {
    cuuint64_t dims[3] = {cin, m, taps};
    cuuint64_t strides[2] = {cin * 2, cin * m * 2};
    cuuint32_t box[3] = {64, 128, 1};
    cuuint32_t es[3] = {1, 1, 1};
    get_encode_fn()(tm, CU_TENSOR_MAP_DATA_TYPE_FLOAT16, 3, ptr, dims, strides,
                    box, es, CU_TENSOR_MAP_INTERLEAVE_NONE,
                    CU_TENSOR_MAP_SWIZZLE_128B,
                    CU_TENSOR_MAP_L2_PROMOTION_L2_128B,
                    CU_TENSOR_MAP_FLOAT_OOB_FILL_NONE);
}

static void encode_x4d(CUtensorMap* tm, void* ptr, unsigned long long C) {
    cuuint64_t dims[4] = {C, 64, 64, 4};
    cuuint64_t strides[3] = {C * 2, 64 * C * 2, 64ull * 64 * C * 2};
    cuuint32_t box[4] = {64, 64, 1, 1};
    cuuint32_t es[4] = {1, 1, 1, 1};
    get_encode_fn()(tm, CU_TENSOR_MAP_DATA_TYPE_FLOAT16, 4, ptr, dims, strides,
                    box, es, CU_TENSOR_MAP_INTERLEAVE_NONE,
                    CU_TENSOR_MAP_SWIZZLE_128B,
                    CU_TENSOR_MAP_L2_PROMOTION_L2_128B,
                    CU_TENSOR_MAP_FLOAT_OOB_FILL_NONE);
}

// ---------------------------------------------------------------------------
// Launch
// ---------------------------------------------------------------------------
extern "C" void kernel_launch(void* const* d_in, const int* in_sizes, int n_in,
                              void* d_out, int out_size)
{
    const float* x     = (const float*)d_in[0];
    const float* c1w   = (const float*)d_in[1];
    const float* bn1g  = (const float*)d_in[2];
    const float* bn1b  = (const float*)d_in[3];
    const float* bn1m  = (const float*)d_in[4];
    const float* bn1v  = (const float*)d_in[5];
    const float* qw    = (const float*)d_in[6];
    const float* qb    = (const float*)d_in[7];
    const float* kw    = (const float*)d_in[8];
    const float* kb    = (const float*)d_in[9];
    const float* vw    = (const float*)d_in[10];
    const float* vb    = (const float*)d_in[11];
    const float* gamma = (const float*)d_in[12];
    const float* c2w   = (const float*)d_in[13];
    const float* bn2g  = (const float*)d_in[14];
    const float* bn2b  = (const float*)d_in[15];
    const float* bn2m  = (const float*)d_in[16];
    const float* bn2v  = (const float*)d_in[17];
    float* out = (float*)d_out;

    float *fA, *fB, *gv, *gqk, *gat, *gbqk;
    __half *xh, *fh, *w1hi, *w1lo, *w2hi, *w2lo, *wqkhi, *wqklo, *wvhi, *wvlo;
    cudaGetSymbolAddress((void**)&fA, g_featsA);
    cudaGetSymbolAddress((void**)&fB, g_featsB);
    cudaGetSymbolAddress((void**)&gv, g_v);
    cudaGetSymbolAddress((void**)&gqk, g_qk);
    cudaGetSymbolAddress((void**)&gat, g_attn);
    cudaGetSymbolAddress((void**)&gbqk, g_bqk);
    cudaGetSymbolAddress((void**)&xh, g_xh);
    cudaGetSymbolAddress((void**)&fh, g_fh);
    cudaGetSymbolAddress((void**)&w1hi, g_w1hi);
    cudaGetSymbolAddress((void**)&w1lo, g_w1lo);
    cudaGetSymbolAddress((void**)&w2hi, g_w2hi);
    cudaGetSymbolAddress((void**)&w2lo, g_w2lo);
    cudaGetSymbolAddress((void**)&wqkhi, g_wqkhi);
    cudaGetSymbolAddress((void**)&wqklo, g_wqklo);
    cudaGetSymbolAddress((void**)&wvhi, g_wvhi);
    cudaGetSymbolAddress((void**)&wvlo, g_wvlo);

    static CUtensorMap tW1hi, tW1lo, tW2hi, tW2lo, tWvhi, tWvlo, tXh, tFh;
    encode_w3d(&tW1hi, w1hi, 2048, 512, 9);
    encode_w3d(&tW1lo, w1lo, 2048, 512, 9);
    encode_w3d(&tW2hi, w2hi, 512, 512, 9);
    encode_w3d(&tW2lo, w2lo, 512, 512, 9);
    encode_w3d(&tWvhi, wvhi, 512, 512, 1);
    encode_w3d(&tWvlo, wvlo, 512, 512, 1);
    encode_x4d(&tXh, xh, 2048);
    encode_x4d(&tFh, fh, 512);

    const int SMEM_TMA = 3 * 65536 + 1024;
    const int SMEM_P1  = 2 * 49152 + 1024;
    cudaFuncSetAttribute(mma_conv_tma<2048, 9, 1>, cudaFuncAttributeMaxDynamicSharedMemorySize, SMEM_TMA);
    cudaFuncSetAttribute(mma_conv_tma<512, 9, 1>,  cudaFuncAttributeMaxDynamicSharedMemorySize, SMEM_TMA);
    cudaFuncSetAttribute(mma_conv_tma<512, 1, 0>,  cudaFuncAttributeMaxDynamicSharedMemorySize, SMEM_TMA);
    cudaFuncSetAttribute(mma_proj_cg1<512>,        cudaFuncAttributeMaxDynamicSharedMemorySize, SMEM_P1);

    // ncu captures OUR launch index 3 -> conv1 stays there
    prep_wconv<<<(512 * 2048 + 255) / 256, 256>>>(c1w, w1hi, w1lo, 512, 2048);   // 0
    prep_act<<<dim3(128, 64, 4), dim3(32, 8)>>>(x, xh, 2048);                    // 1
    prep_wqk<<<256, 256>>>(qw, kw, qb, kb, wqkhi, wqklo, gbqk);                  // 2
    mma_conv_tma<2048, 9, 1><<<dim3(4, 32), 256, SMEM_TMA>>>(                    // 3: conv1
        tW1hi, tW1lo, tXh, bn1g, bn1b, bn1m, bn1v, fA, 512);
    prep_wlin<<<(512 * 512 + 255) / 256, 256>>>(vw, wvhi, wvlo, 512 * 512);      // 4
    prep_wconv<<<(512 * 512 + 255) / 256, 256>>>(c2w, w2hi, w2lo, 512, 512);     // 5

    // --- 2x criss-cross attention ---
    float* cur = fA;
    float* nxt = fB;
    for (int it = 0; it < 2; ++it) {
        prep_act<<<dim3(128, 16, 4), dim3(32, 8)>>>(cur, fh, 512);
        mma_proj_cg1<512><<<dim3(1, 128), 256, SMEM_P1>>>(
            wqkhi, wqklo, fh, gbqk, gqk, 128);
        mma_conv_tma<512, 1, 0><<<dim3(4, 32), 256, SMEM_TMA>>>(
            tWvhi, tWvlo, tFh, vb, nullptr, nullptr, nullptr, gv, 512);
        energyH_kernel<<<dim3(64, 4), 256>>>(gqk, gat);
        energyW_kernel<<<dim3(64, 4), 256>>>(gqk, gat);
        softmax_kernel<<<NPIX_ / 8, 256>>>(gat);
        aggH_kernel<<<dim3(64, 4, 8), 256>>>(gv, gat, cur, nxt, gamma);
        aggW_kernel<<<dim3(64, 4, 8), 256>>>(gv, gat, nxt, gamma);
        float* tmp = cur; cur = nxt; nxt = tmp;
    }

    // --- conv2 + BN + ReLU ---
    prep_act<<<dim3(128, 16, 4), dim3(32, 8)>>>(cur, fh, 512);
    mma_conv_tma<512, 9, 1><<<dim3(4, 32), 256, SMEM_TMA>>>(
        tW2hi, tW2lo, tFh, bn2g, bn2b, bn2m, bn2v, out, 512);
}

// round 11
// speedup vs baseline: 1.0740x; 1.0740x over previous
#include <cuda_runtime.h>
#include <cuda.h>
#include <cuda_fp16.h>
#include <math.h>
#include <stdint.h>

#define HW_   4096
#define NPIX_ 16384

#if defined(__CUDA_ARCH__) && (defined(__CUDA_ARCH_FEAT_SM103_ALL) || defined(__CUDA_ARCH_FEAT_SM100_ALL))
#define HAS_TC 1
#else
#define HAS_TC 0
#endif

#define WSCALE     64.0f
#define INV_WSCALE 0.015625f

// ---------------------------------------------------------------------------
// Scratch (device globals; allocation is forbidden). TMA sources aligned.
// ---------------------------------------------------------------------------
__device__ float g_featsA[4 * 512 * 4096];
__device__ float g_featsB[4 * 512 * 4096];
__device__ float g_v[4 * 512 * 4096];
__device__ float g_qk[4 * 128 * 4096];
__device__ float g_attn[4 * 4096 * 128];
__device__ float g_bqk[128];
__device__ __align__(128) __half g_xh[4 * 4096 * 2048];
__device__ __align__(128) __half g_fh[4 * 4096 * 512];
__device__ __align__(128) __half g_w1hi[9 * 512 * 2048];
__device__ __align__(128) __half g_w1lo[9 * 512 * 2048];
__device__ __align__(128) __half g_w2hi[9 * 512 * 512];
__device__ __align__(128) __half g_w2lo[9 * 512 * 512];
__device__ __align__(128) __half g_wqkhi[128 * 512];
__device__ __align__(128) __half g_wqklo[128 * 512];
__device__ __align__(128) __half g_wvhi[512 * 512];
__device__ __align__(128) __half g_wvlo[512 * 512];

// ---------------------------------------------------------------------------
// Generic helpers
// ---------------------------------------------------------------------------
__device__ __forceinline__ unsigned smem_u32(const void* p) {
    unsigned a;
    asm("{ .reg .u64 t; cvta.to.shared.u64 t, %1; cvt.u32.u64 %0, t; }"
        : "=r"(a) : "l"(p));
    return a;
}
__device__ __forceinline__ unsigned elect_one() {
    unsigned p;
    asm volatile("{ .reg .pred p; elect.sync _|p, 0xFFFFFFFF; selp.b32 %0, 1, 0, p; }"
                 : "=r"(p));
    return p;
}
#define SW128(o) ((o) ^ (((o) >> 3) & 0x70))
__device__ __forceinline__ void mbar_init(unsigned mbar, unsigned cnt) {
    asm volatile("mbarrier.init.shared.b64 [%0], %1;" :: "r"(mbar), "r"(cnt) : "memory");
}
__device__ __forceinline__ void mbar_wait(unsigned mbar, unsigned phase) {
    asm volatile(
        "{\n\t.reg .pred P;\n\t"
        "WL_%=:\n\t"
        "mbarrier.try_wait.parity.acquire.cta.shared::cta.b64 P, [%0], %1, 0x989680;\n\t"
        "@P bra.uni WD_%=;\n\t"
        "bra.uni WL_%=;\n\t"
        "WD_%=:\n\t}"
        :: "r"(mbar), "r"(phase) : "memory");
}
__device__ __forceinline__ void fence_async_shared() {
    asm volatile("fence.proxy.async;" ::: "memory");
}

// ---------------------------------------------------------------------------
// tcgen05 / TMA / cluster helpers (arch-specific pass only)
// ---------------------------------------------------------------------------
#if HAS_TC
static constexpr unsigned long long SMEM_DESC_BASE_SW128 =
    (2ull << 61) | (1ull << 46) | (64ull << 32) | (1ull << 16);
__device__ __forceinline__ unsigned long long make_desc(unsigned addr) {
    return SMEM_DESC_BASE_SW128 | ((unsigned long long)(addr >> 4) & 0x3FFFull);
}
__device__ __forceinline__ void cluster_sync_() {
    asm volatile("barrier.cluster.arrive.aligned;" ::: "memory");
    asm volatile("barrier.cluster.wait.aligned;" ::: "memory");
}
__device__ __forceinline__ void mbar_expect_tx(unsigned mbar, unsigned bytes) {
    asm volatile("mbarrier.arrive.expect_tx.shared.b64 _, [%0], %1;"
                 :: "r"(mbar), "r"(bytes) : "memory");
}
__device__ __forceinline__ void tmem_alloc_cg1(unsigned dst_smem, unsigned ncols) {
    asm volatile("tcgen05.alloc.cta_group::1.sync.aligned.shared::cta.b32 [%0], %1;"
                 :: "r"(dst_smem), "r"(ncols) : "memory");
}
__device__ __forceinline__ void tmem_dealloc_cg1(unsigned tmem, unsigned ncols) {
    asm volatile("tcgen05.dealloc.cta_group::1.sync.aligned.b32 %0, %1;"
                 :: "r"(tmem), "r"(ncols));
}
__device__ __forceinline__ void tmem_alloc_cg2(unsigned dst_smem, unsigned ncols) {
    asm volatile("tcgen05.alloc.cta_group::2.sync.aligned.shared::cta.b32 [%0], %1;"
                 :: "r"(dst_smem), "r"(ncols) : "memory");
}
__device__ __forceinline__ void tmem_dealloc_cg2(unsigned tmem, unsigned ncols) {
    asm volatile("tcgen05.dealloc.cta_group::2.sync.aligned.b32 %0, %1;"
                 :: "r"(tmem), "r"(ncols));
}
__device__ __forceinline__ void tc_relinquish_cg2() {
    asm volatile("tcgen05.relinquish_alloc_permit.cta_group::2.sync.aligned;");
}
__device__ __forceinline__ void tc_commit_cg1(unsigned mbar) {
    asm volatile("tcgen05.commit.cta_group::1.mbarrier::arrive::one.shared::cluster.b64 [%0];"
                 :: "r"(mbar) : "memory");
}
__device__ __forceinline__ void tc_commit_mc_cg2(unsigned mbar, unsigned short mask) {
    asm volatile("tcgen05.commit.cta_group::2.mbarrier::arrive::one.shared::cluster.multicast::cluster.b64 [%0], %1;"
                 :: "r"(mbar), "h"(mask) : "memory");
}
__device__ __forceinline__ void tc_fence_after() {
    asm volatile("tcgen05.fence::after_thread_sync;" ::: "memory");
}
__device__ __forceinline__ void tc_wait_ld() {
    asm volatile("tcgen05.wait::ld.sync.aligned;" ::: "memory");
}
__device__ __forceinline__ void mma_cg1(unsigned d, unsigned long long ad,
                                        unsigned long long bd, unsigned idesc, unsigned en) {
    asm volatile(
        "{\n\t.reg .pred p;\n\tsetp.ne.u32 p, %4, 0;\n\t"
        "tcgen05.mma.cta_group::1.kind::f16 [%0], %1, %2, %3, {%5, %5, %5, %5}, p;\n\t}"
        :: "r"(d), "l"(ad), "l"(bd), "r"(idesc), "r"(en), "r"(0u) : "memory");
}
__device__ __forceinline__ void mma_cg2(unsigned d, unsigned long long ad,
                                        unsigned long long bd, unsigned idesc, unsigned en) {
    asm volatile(
        "{\n\t.reg .pred p;\n\tsetp.ne.u32 p, %4, 0;\n\t"
        "tcgen05.mma.cta_group::2.kind::f16 [%0], %1, %2, %3, "
        "{%5, %5, %5, %5, %5, %5, %5, %5}, p;\n\t}"
        :: "r"(d), "l"(ad), "l"(bd), "r"(idesc), "r"(en), "r"(0u) : "memory");
}
__device__ __forceinline__ void tmem_ld32(unsigned* r, unsigned addr) {
    asm volatile(
        "tcgen05.ld.sync.aligned.32x32b.x32.b32 "
        "{%0, %1, %2, %3, %4, %5, %6, %7, "
        " %8, %9, %10, %11, %12, %13, %14, %15, "
        " %16, %17, %18, %19, %20, %21, %22, %23, "
        " %24, %25, %26, %27, %28, %29, %30, %31}, [%32];"
        : "=r"(r[0]),  "=r"(r[1]),  "=r"(r[2]),  "=r"(r[3]),
          "=r"(r[4]),  "=r"(r[5]),  "=r"(r[6]),  "=r"(r[7]),
          "=r"(r[8]),  "=r"(r[9]),  "=r"(r[10]), "=r"(r[11]),
          "=r"(r[12]), "=r"(r[13]), "=r"(r[14]), "=r"(r[15]),
          "=r"(r[16]), "=r"(r[17]), "=r"(r[18]), "=r"(r[19]),
          "=r"(r[20]), "=r"(r[21]), "=r"(r[22]), "=r"(r[23]),
          "=r"(r[24]), "=r"(r[25]), "=r"(r[26]), "=r"(r[27]),
          "=r"(r[28]), "=r"(r[29]), "=r"(r[30]), "=r"(r[31])
        : "r"(addr));
}
__device__ __forceinline__ void tma3d_cg2(unsigned dst, const CUtensorMap* m,
                                          int x, int y, int z, unsigned bar) {
    asm volatile(
        "{\n\t.reg .b32 lb;\n\tand.b32 lb, %5, 0xFEFFFFFF;\n\t"
        "cp.async.bulk.tensor.3d.cta_group::2.shared::cluster.global"
        ".tile.mbarrier::complete_tx::bytes [%0], [%1, {%2, %3, %4}], [lb];\n\t}"
        :: "r"(dst), "l"(m), "r"(x), "r"(y), "r"(z), "r"(bar) : "memory");
}
__device__ __forceinline__ void tma4d_cg2(unsigned dst, const CUtensorMap* m,
                                          int x, int y, int z, int w, unsigned bar) {
    asm volatile(
        "{\n\t.reg .b32 lb;\n\tand.b32 lb, %6, 0xFEFFFFFF;\n\t"
        "cp.async.bulk.tensor.4d.cta_group::2.shared::cluster.global"
        ".tile.mbarrier::complete_tx::bytes [%0], [%1, {%2, %3, %4, %5}], [lb];\n\t}"
        :: "r"(dst), "l"(m), "r"(x), "r"(y), "r"(z), "r"(w), "r"(bar) : "memory");
}
#endif

// ---------------------------------------------------------------------------
// Prep kernels
// ---------------------------------------------------------------------------
__device__ __forceinline__ void split_half(float x, __half& h, __half& l) {
    h = __float2half(x);
    l = __float2half(x - __half2float(h));
}

__global__ void prep_act(const float* __restrict__ src,
                         __half* __restrict__ dh, int CIN) {
    __shared__ float t[32][33];
    const int b = blockIdx.z, ct = blockIdx.y * 32, pt = blockIdx.x * 32;
    const int tx = threadIdx.x, ty = threadIdx.y;
    for (int i = ty; i < 32; i += 8)
        t[i][tx] = src[((size_t)(b * CIN + ct + i)) * HW_ + pt + tx];
    __syncthreads();
    for (int i = ty; i < 32; i += 8) {
        size_t o = ((size_t)(b * HW_ + pt + i)) * CIN + ct + tx;
        dh[o] = __float2half(t[tx][i]);
    }
}

__global__ void prep_wconv(const float* __restrict__ W,
                           __half* __restrict__ dhi,
                           __half* __restrict__ dlo, int M, int CIN) {
    int idx = blockIdx.x * 256 + threadIdx.x;
    if (idx >= M * CIN) return;
#pragma unroll
    for (int tap = 0; tap < 9; tap++) {
        float x = W[(size_t)idx * 9 + tap] * WSCALE;
        __half h, l;
        split_half(x, h, l);
        size_t o = (size_t)tap * M * CIN + idx;
        dhi[o] = h;
        dlo[o] = l;
    }
}

__global__ void prep_wlin(const float* __restrict__ W,
                          __half* __restrict__ dhi,
                          __half* __restrict__ dlo, int n) {
    int i = blockIdx.x * 256 + threadIdx.x;
    if (i >= n) return;
    __half h, l;
    split_half(W[i] * WSCALE, h, l);
    dhi[i] = h;
    dlo[i] = l;
}

__global__ void prep_wqk(const float* __restrict__ qw, const float* __restrict__ kw,
                         const float* __restrict__ qb, const float* __restrict__ kb,
                         __half* __restrict__ dhi, __half* __restrict__ dlo,
                         float* __restrict__ bias) {
    int i = blockIdx.x * 256 + threadIdx.x;
    if (i < 128) bias[i] = (i < 64) ? qb[i] : kb[i - 64];
    if (i >= 128 * 512) return;
    float x = ((i < 64 * 512) ? qw[i] : kw[i - 64 * 512]) * WSCALE;
    __half h, l;
    split_half(x, h, l);
    dhi[i] = h;
    dlo[i] = l;
}

// ---------------------------------------------------------------------------
// cg2 implicit-conv GEMM, TMA pipeline (exact R9 structure — best measured)
// ---------------------------------------------------------------------------
template<int CIN, int TAPS, int EPI>
__global__ void __launch_bounds__(256, 1) __cluster_dims__(2, 1, 1)
mma_conv_tma(const __grid_constant__ CUtensorMap tWhi,
             const __grid_constant__ CUtensorMap tWlo,
             const __grid_constant__ CUtensorMap tX,
             const float* __restrict__ e0, const float* __restrict__ e1,
             const float* __restrict__ e2, const float* __restrict__ e3,
             float* __restrict__ Y, int Mtot)
{
#if HAS_TC
    constexpr int NCHUNK = TAPS * (CIN / 64);
    constexpr int NST   = 3;
    constexpr int A_HI  = 0;
    constexpr int A_LO  = 16384;
    constexpr int B_0   = 32768;
    constexpr int STAGE = 65536;
    constexpr unsigned IDESC2 = (1u << 4) | (16u << 17) | (16u << 24);

    extern __shared__ char dyn_smem[];
    __shared__ __align__(8) unsigned long long s_full[NST];
    __shared__ __align__(8) unsigned long long s_done[NST];
    __shared__ unsigned s_tmem[1];

    char* sm = (char*)((((uintptr_t)dyn_smem) + 1023) & ~(uintptr_t)1023);
    const unsigned sbase = smem_u32(sm);

    const int tid  = threadIdx.x;
    const int wid  = tid >> 5;
    const int lane = tid & 31;
    const unsigned rank = blockIdx.x & 1;
    const int m_base = (blockIdx.x >> 1) * 256;
    const int n_base = blockIdx.y * 512;
    const int bb    = n_base >> 12;
    const int sp00  = n_base & 4095;
    const int hrow0 = sp00 >> 6;

    if (wid == 0) tmem_alloc_cg2(smem_u32(&s_tmem[0]), 512);
    if (tid == 0) {
#pragma unroll
        for (int s = 0; s < NST; ++s) {
            mbar_init(smem_u32(&s_full[s]), 1);
            mbar_init(smem_u32(&s_done[s]), 1);
        }
    }
    __syncthreads();
    unsigned tmem;
    asm volatile("ld.shared.b32 %0, [%1];" : "=r"(tmem) : "r"(smem_u32(&s_tmem[0])));
    unsigned fullb[NST], doneb[NST];
#pragma unroll
    for (int s = 0; s < NST; ++s) {
        fullb[s] = smem_u32(&s_full[s]);
        doneb[s] = smem_u32(&s_done[s]);
    }
    cluster_sync_();

    if (tid == 0) {
        int dph[NST] = {0, 0, 0};
        int fph[NST] = {0, 0, 0};
        for (int i = 0; i < NCHUNK; ++i) {
            const int s = i % NST;
            if (i >= NST) { mbar_wait(doneb[s], dph[s]); dph[s] ^= 1; }

            if (rank == 0) mbar_expect_tx(fullb[s], 2 * STAGE);

            const int tap = (TAPS == 1) ? 0 : i / (CIN / 64);
            const int cb  = (TAPS == 1) ? i * 64 : (i % (CIN / 64)) * 64;
            const int dh  = (TAPS == 9) ? (tap / 3 - 1) : 0;
            const int dw  = (TAPS == 9) ? (tap % 3 - 1) : 0;
            const unsigned stg = sbase + s * STAGE;

            tma3d_cg2(stg + A_HI, &tWhi, cb, m_base + (int)rank * 128, tap, fullb[s]);
            tma3d_cg2(stg + A_LO, &tWlo, cb, m_base + (int)rank * 128, tap, fullb[s]);
#pragma unroll
            for (int t = 0; t < 4; ++t)
                tma4d_cg2(stg + B_0 + t * 8192, &tX,
                          cb, dw, hrow0 + 2 * t + (int)rank + dh, bb, fullb[s]);

            if (rank == 0 && i >= 1) {
                const int j = i - 1, sj = j % NST;
                mbar_wait(fullb[sj], fph[sj]); fph[sj] ^= 1;
                const unsigned sg = sbase + sj * STAGE;
                unsigned long long dAh = make_desc(sg + A_HI);
                unsigned long long dAl = make_desc(sg + A_LO);
#pragma unroll
                for (int t = 0; t < 4; ++t) {
                    unsigned d = tmem + t * 128;
                    unsigned long long dB = make_desc(sg + B_0 + t * 8192);
#pragma unroll
                    for (int kk = 0; kk < 4; ++kk) {
                        unsigned en0 = (j > 0 || kk > 0) ? 1u : 0u;
                        mma_cg2(d, dAh + kk * 2, dB + kk * 2, IDESC2, en0);
                        mma_cg2(d, dAl + kk * 2, dB + kk * 2, IDESC2, 1u);
                    }
                }
                tc_commit_mc_cg2(doneb[sj], 0x3);
            }
        }
        if (rank == 0) {
            const int j = NCHUNK - 1, sj = j % NST;
            mbar_wait(fullb[sj], fph[sj]); fph[sj] ^= 1;
            const unsigned sg = sbase + sj * STAGE;
            unsigned long long dAh = make_desc(sg + A_HI);
            unsigned long long dAl = make_desc(sg + A_LO);
#pragma unroll
            for (int t = 0; t < 4; ++t) {
                unsigned d = tmem + t * 128;
                unsigned long long dB = make_desc(sg + B_0 + t * 8192);
#pragma unroll
                for (int kk = 0; kk < 4; ++kk) {
                    mma_cg2(d, dAh + kk * 2, dB + kk * 2, IDESC2, 1u);
                    mma_cg2(d, dAl + kk * 2, dB + kk * 2, IDESC2, 1u);
                }
            }
            tc_commit_mc_cg2(doneb[sj], 0x3);
        }
        const int sl = (NCHUNK - 1) % NST;
        mbar_wait(doneb[sl], dph[sl]);
    }
    __syncthreads();
    tc_fence_after();

    // --- epilogue ---
    {
        const int wg = wid >> 2;
        const int mg = m_base + (int)rank * 128 + (wid & 3) * 32 + lane;
        float sc, sh;
        if (EPI == 1) {
            float tt = e0[mg] * rsqrtf(e3[mg] + 1e-5f);
            sc = tt * INV_WSCALE;
            sh = e1[mg] - e2[mg] * tt;
        } else {
            sc = INV_WSCALE;
            sh = e0[mg];
        }
        float* yrow = Y + ((size_t)(bb * Mtot + mg)) * HW_ + sp00;
#pragma unroll
        for (int ti = 0; ti < 2; ++ti) {
            int t = wg * 2 + ti;
#pragma unroll
            for (int cb4 = 0; cb4 < 4; ++cb4) {
                unsigned r[32];
                tmem_ld32(r, tmem + t * 128 + cb4 * 32);
                tc_wait_ld();
#pragma unroll
                for (int j = 0; j < 32; j += 4) {
                    float4 v;
                    v.x = fmaf(__uint_as_float(r[j + 0]), sc, sh);
                    v.y = fmaf(__uint_as_float(r[j + 1]), sc, sh);
                    v.z = fmaf(__uint_as_float(r[j + 2]), sc, sh);
                    v.w = fmaf(__uint_as_float(r[j + 3]), sc, sh);
                    if (EPI == 1) {
                        v.x = fmaxf(v.x, 0.f); v.y = fmaxf(v.y, 0.f);
                        v.z = fmaxf(v.z, 0.f); v.w = fmaxf(v.w, 0.f);
                    }
                    *(float4*)(yrow + t * 128 + cb4 * 32 + j) = v;
                }
            }
        }
    }
    __syncthreads();
    if (wid == 0) {
        tc_relinquish_cg2();
        tmem_dealloc_cg2(tmem, 512);
    }
    cluster_sync_();
#endif
}

// ---------------------------------------------------------------------------
// cg1 GEMM for the stacked q/k projection (M=128)
// ---------------------------------------------------------------------------
template<int CIN>
__global__ void __launch_bounds__(256, 1)
mma_proj_cg1(const __half* __restrict__ Whi, const __half* __restrict__ Wlo,
             const __half* __restrict__ Xh,
             const float* __restrict__ e0, float* __restrict__ Y, int Mtot)
{
#if HAS_TC
    constexpr int A_BYTES = 128 * 128;
    constexpr int B_BYTES = 128 * 128;
    constexpr int STAGE   = 2 * A_BYTES + B_BYTES;
    constexpr int NCHUNK  = CIN / 64;
    constexpr unsigned IDESC = (1u << 4) | (16u << 17) | (8u << 24);

    extern __shared__ char dyn_smem[];
    __shared__ __align__(8) unsigned long long s_mbar[2];
    __shared__ unsigned s_tmem[1];

    char* sm = (char*)((((uintptr_t)dyn_smem) + 1023) & ~(uintptr_t)1023);
    const unsigned sbase = smem_u32(sm);
    const int tid = threadIdx.x;
    const int wid = tid >> 5;
    const int lane = tid & 31;

    if (wid == 0) tmem_alloc_cg1(smem_u32(&s_tmem[0]), 256);
    if (tid == 0) { mbar_init(smem_u32(&s_mbar[0]), 1); mbar_init(smem_u32(&s_mbar[1]), 1); }
    __syncthreads();
    unsigned tmem;
    asm volatile("ld.shared.b32 %0, [%1];" : "=r"(tmem) : "r"(smem_u32(&s_tmem[0])));
    const unsigned mbar[2] = { smem_u32(&s_mbar[0]), smem_u32(&s_mbar[1]) };

    const int n_base = blockIdx.y * 128;
    const int bb  = n_base >> 12;
    const int sp0 = n_base & 4095;
    int ph[2] = {0, 0};

    for (int chunk = 0; chunk < NCHUNK; ++chunk) {
        const int s  = chunk & 1;
        const int cb = chunk * 64;
        if (chunk >= 2) { mbar_wait(mbar[s], ph[s]); ph[s] ^= 1; }

        char* aHi = sm + s * STAGE;
        char* aLo = aHi + A_BYTES;
        char* bH  = aLo + A_BYTES;
#pragma unroll
        for (int u = 0; u < 4; ++u) {
            int l = u * 256 + tid;
            int row = l >> 3, c16 = l & 7;
            size_t go = (size_t)row * CIN + cb + c16 * 8;
            unsigned so = SW128((unsigned)(row * 128 + c16 * 16));
            *(uint4*)(aHi + so) = *(const uint4*)(Whi + go);
            *(uint4*)(aLo + so) = *(const uint4*)(Wlo + go);
        }
#pragma unroll
        for (int u = 0; u < 4; ++u) {
            int l = u * 256 + tid;
            int row = l >> 3, c16 = l & 7;
            size_t go = ((size_t)(bb * HW_ + sp0 + row)) * CIN + cb + c16 * 8;
            unsigned so = SW128((unsigned)(row * 128 + c16 * 16));
            *(uint4*)(bH + so) = *(const uint4*)(Xh + go);
        }
        fence_async_shared();
        __syncthreads();

        if (wid == 0 && elect_one()) {
            unsigned long long dAh = make_desc(sbase + s * STAGE);
            unsigned long long dAl = dAh + (A_BYTES >> 4);
            unsigned long long dB  = make_desc(sbase + s * STAGE + 2 * A_BYTES);
#pragma unroll
            for (int kk = 0; kk < 4; ++kk) {
                unsigned en0 = (chunk > 0 || kk > 0) ? 1u : 0u;
                mma_cg1(tmem, dAh + kk * 2, dB + kk * 2, IDESC, en0);
                mma_cg1(tmem, dAl + kk * 2, dB + kk * 2, IDESC, 1u);
            }
            tc_commit_cg1(mbar[s]);
        }
    }
    {
        int s0 = (NCHUNK - 2) & 1, s1 = (NCHUNK - 1) & 1;
        mbar_wait(mbar[s0], ph[s0]); ph[s0] ^= 1;
        mbar_wait(mbar[s1], ph[s1]); ph[s1] ^= 1;
    }
    tc_fence_after();

    if (wid < 4) {
        const int mg = wid * 32 + lane;
        float sh = e0[mg];
        float* yrow = Y + ((size_t)(bb * Mtot + mg)) * HW_ + sp0;
#pragma unroll
        for (int cb4 = 0; cb4 < 4; ++cb4) {
            unsigned r[32];
            tmem_ld32(r, tmem + cb4 * 32);
            tc_wait_ld();
#pragma unroll
            for (int j = 0; j < 32; j += 4) {
                float4 v;
                v.x = fmaf(__uint_as_float(r[j + 0]), INV_WSCALE, sh);
                v.y = fmaf(__uint_as_float(r[j + 1]), INV_WSCALE, sh);
                v.z = fmaf(__uint_as_float(r[j + 2]), INV_WSCALE, sh);
                v.w = fmaf(__uint_as_float(r[j + 3]), INV_WSCALE, sh);
                *(float4*)(yrow + cb4 * 32 + j) = v;
            }
        }
    }
    __syncthreads();
    if (wid == 0) tmem_dealloc_cg1(tmem, 256);
#endif
}

// ---------------------------------------------------------------------------
// CCA kernels — register-tiled 4x4 outer products (8 LDS per 16 FMA)
// ---------------------------------------------------------------------------
__global__ void __launch_bounds__(256) energyH_kernel(
    const float* __restrict__ qk, float* __restrict__ attn)
{
    const int w = blockIdx.x, b = blockIdx.y;
    __shared__ float Qs[64][65];
    __shared__ float Ks[64][65];
    const int tid = threadIdx.x;
    for (int l = tid; l < 4096; l += 256) {
        int c = l >> 6, h = l & 63;
        Qs[c][h] = qk[((size_t)(b * 128 + c)) * HW_ + h * 64 + w];
        Ks[c][h] = qk[((size_t)(b * 128 + 64 + c)) * HW_ + h * 64 + w];
    }
    __syncthreads();
    const int i4 = (tid & 15) * 4, h4 = (tid >> 4) * 4;
    float acc[4][4];
#pragma unroll
    for (int a = 0; a < 4; a++)
#pragma unroll
        for (int d = 0; d < 4; d++) acc[a][d] = 0.f;
    for (int c = 0; c < 64; c++) {
        float q0 = Qs[c][h4], q1 = Qs[c][h4 + 1], q2 = Qs[c][h4 + 2], q3 = Qs[c][h4 + 3];
        float k0 = Ks[c][i4], k1 = Ks[c][i4 + 1], k2 = Ks[c][i4 + 2], k3 = Ks[c][i4 + 3];
        acc[0][0] += q0 * k0; acc[0][1] += q0 * k1; acc[0][2] += q0 * k2; acc[0][3] += q0 * k3;
        acc[1][0] += q1 * k0; acc[1][1] += q1 * k1; acc[1][2] += q1 * k2; acc[1][3] += q1 * k3;
        acc[2][0] += q2 * k0; acc[2][1] += q2 * k1; acc[2][2] += q2 * k2; acc[2][3] += q2 * k3;
        acc[3][0] += q3 * k0; acc[3][1] += q3 * k1; acc[3][2] += q3 * k2; acc[3][3] += q3 * k3;
    }
#pragma unroll
    for (int a = 0; a < 4; a++) {
        int h = h4 + a;
        float4 o;
        o.x = acc[a][0] + ((i4 + 0 == h) ? -1000000000.0f : 0.f);
        o.y = acc[a][1] + ((i4 + 1 == h) ? -1000000000.0f : 0.f);
        o.z = acc[a][2] + ((i4 + 2 == h) ? -1000000000.0f : 0.f);
        o.w = acc[a][3] + ((i4 + 3 == h) ? -1000000000.0f : 0.f);
        *(float4*)(attn + (size_t)(((b * 64 + h) * 64 + w)) * 128 + i4) = o;
    }
}

__global__ void __launch_bounds__(256) energyW_kernel(
    const float* __restrict__ qk, float* __restrict__ attn)
{
    const int h = blockIdx.x, b = blockIdx.y;
    __shared__ float Qs[64][65];
    __shared__ float Ks[64][65];
    const int tid = threadIdx.x;
    for (int l = tid; l < 4096; l += 256) {
        int c = l >> 6, w = l & 63;
        Qs[c][w] = qk[((size_t)(b * 128 + c)) * HW_ + h * 64 + w];
        Ks[c][w] = qk[((size_t)(b * 128 + 64 + c)) * HW_ + h * 64 + w];
    }
    __syncthreads();
    const int j4 = (tid & 15) * 4, w4 = (tid >> 4) * 4;
    float acc[4][4];
#pragma unroll
    for (int a = 0; a < 4; a++)
#pragma unroll
        for (int d = 0; d < 4; d++) acc[a][d] = 0.f;
    for (int c = 0; c < 64; c++) {
        float q0 = Qs[c][w4], q1 = Qs[c][w4 + 1], q2 = Qs[c][w4 + 2], q3 = Qs[c][w4 + 3];
        float k0 = Ks[c][j4], k1 = Ks[c][j4 + 1], k2 = Ks[c][j4 + 2], k3 = Ks[c][j4 + 3];
        acc[0][0] += q0 * k0; acc[0][1] += q0 * k1; acc[0][2] += q0 * k2; acc[0][3] += q0 * k3;
        acc[1][0] += q1 * k0; acc[1][1] += q1 * k1; acc[1][2] += q1 * k2; acc[1][3] += q1 * k3;
        acc[2][0] += q2 * k0; acc[2][1] += q2 * k1; acc[2][2] += q2 * k2; acc[2][3] += q2 * k3;
        acc[3][0] += q3 * k0; acc[3][1] += q3 * k1; acc[3][2] += q3 * k2; acc[3][3] += q3 * k3;
    }
#pragma unroll
    for (int a = 0; a < 4; a++) {
        int w = w4 + a;
        float4 o = make_float4(acc[a][0], acc[a][1], acc[a][2], acc[a][3]);
        *(float4*)(attn + (size_t)(((b * 64 + h) * 64 + w)) * 128 + 64 + j4) = o;
    }
}

__global__ void __launch_bounds__(256) softmax_kernel(float* __restrict__ attn)
{
    int gw = (blockIdx.x * blockDim.x + threadIdx.x) >> 5;
    if (gw >= NPIX_) return;
    int lane = threadIdx.x & 31;
    float* row = attn + (size_t)gw * 128;
    float v0 = row[lane], v1 = row[lane + 32], v2 = row[lane + 64], v3 = row[lane + 96];
    float mx = fmaxf(fmaxf(v0, v1), fmaxf(v2, v3));
#pragma unroll
    for (int o = 16; o > 0; o >>= 1) mx = fmaxf(mx, __shfl_xor_sync(0xffffffffu, mx, o));
    v0 = expf(v0 - mx); v1 = expf(v1 - mx); v2 = expf(v2 - mx); v3 = expf(v3 - mx);
    float s = v0 + v1 + v2 + v3;
#pragma unroll
    for (int o = 16; o > 0; o >>= 1) s += __shfl_xor_sync(0xffffffffu, s, o);
    float inv = 1.0f / s;
    row[lane] = v0 * inv; row[lane + 32] = v1 * inv;
    row[lane + 64] = v2 * inv; row[lane + 96] = v3 * inv;
}

__global__ void __launch_bounds__(256) aggH_kernel(
    const float* __restrict__ v, const float* __restrict__ attn,
    const float* __restrict__ fin, float* __restrict__ fout,
    const float* __restrict__ gptr)
{
    const int w = blockIdx.x, b = blockIdx.y, cbk = blockIdx.z * 64;
    __shared__ float Vs[64][65];   // [c][i]
    __shared__ float Am[64][65];   // [h][i]
    const int tid = threadIdx.x;
    for (int l = tid; l < 4096; l += 256) {
        int c = l >> 6, i = l & 63;
        Vs[c][i] = v[(size_t)((b * 512 + cbk + c) * 64 + i) * 64 + w];
    }
    for (int l = tid; l < 4096; l += 256) {
        int h = l >> 6, i = l & 63;
        Am[h][i] = attn[(size_t)(((b * 64 + h) * 64 + w)) * 128 + i];
    }
    __syncthreads();
    const int c4 = (tid & 15) * 4, h4 = (tid >> 4) * 4;
    float acc[4][4];
#pragma unroll
    for (int a = 0; a < 4; a++)
#pragma unroll
        for (int d = 0; d < 4; d++) acc[a][d] = 0.f;
    for (int i = 0; i < 64; i++) {
        float v0 = Vs[c4][i], v1 = Vs[c4 + 1][i], v2 = Vs[c4 + 2][i], v3 = Vs[c4 + 3][i];
        float a0 = Am[h4][i], a1 = Am[h4 + 1][i], a2 = Am[h4 + 2][i], a3 = Am[h4 + 3][i];
        acc[0][0] += v0 * a0; acc[0][1] += v0 * a1; acc[0][2] += v0 * a2; acc[0][3] += v0 * a3;
        acc[1][0] += v1 * a0; acc[1][1] += v1 * a1; acc[1][2] += v1 * a2; acc[1][3] += v1 * a3;
        acc[2][0] += v2 * a0; acc[2][1] += v2 * a1; acc[2][2] += v2 * a2; acc[2][3] += v2 * a3;
        acc[3][0] += v3 * a0; acc[3][1] += v3 * a1; acc[3][2] += v3 * a2; acc[3][3] += v3 * a3;
    }
    const float g = *gptr;
#pragma unroll
    for (int a = 0; a < 4; a++) {
#pragma unroll
        for (int d = 0; d < 4; d++) {
            int h = h4 + d;
            size_t idx = (size_t)((b * 512 + cbk + c4 + a) * 64 + h) * 64 + w;
            fout[idx] = fin[idx] + g * acc[a][d];
        }
    }
}

__global__ void __launch_bounds__(256) aggW_kernel(
    const float* __restrict__ v, const float* __restrict__ attn,
    float* __restrict__ fout, const float* __restrict__ gptr)
{
    const int h = blockIdx.x, b = blockIdx.y, cbk = blockIdx.z * 64;
    __shared__ float Vs[64][65];   // [c][j]
    __shared__ float Am[64][65];   // [w][j]
    const int tid = threadIdx.x;
    for (int l = tid; l < 4096; l += 256) {
        int c = l >> 6, j = l & 63;
        Vs[c][j] = v[(size_t)((b * 512 + cbk + c) * 64 + h) * 64 + j];
    }
    for (int l = tid; l < 4096; l += 256) {
        int w = l >> 6, j = l & 63;
        Am[w][j] = attn[(size_t)(((b * 64 + h) * 64 + w)) * 128 + 64 + j];
    }
    __syncthreads();
    const int c4 = (tid & 15) * 4, w4 = (tid >> 4) * 4;
    float acc[4][4];
#pragma unroll
    for (int a = 0; a < 4; a++)
#pragma unroll
        for (int d = 0; d < 4; d++) acc[a][d] = 0.f;
    for (int j = 0; j < 64; j++) {
        float v0 = Vs[c4][j], v1 = Vs[c4 + 1][j], v2 = Vs[c4 + 2][j], v3 = Vs[c4 + 3][j];
        float a0 = Am[w4][j], a1 = Am[w4 + 1][j], a2 = Am[w4 + 2][j], a3 = Am[w4 + 3][j];
        acc[0][0] += v0 * a0; acc[0][1] += v0 * a1; acc[0][2] += v0 * a2; acc[0][3] += v0 * a3;
        acc[1][0] += v1 * a0; acc[1][1] += v1 * a1; acc[1][2] += v1 * a2; acc[1][3] += v1 * a3;
        acc[2][0] += v2 * a0; acc[2][1] += v2 * a1; acc[2][2] += v2 * a2; acc[2][3] += v2 * a3;
        acc[3][0] += v3 * a0; acc[3][1] += v3 * a1; acc[3][2] += v3 * a2; acc[3][3] += v3 * a3;
    }
    const float g = *gptr;
#pragma unroll
    for (int a = 0; a < 4; a++) {
#pragma unroll
        for (int d = 0; d < 4; d++) {
            int w = w4 + d;
            size_t idx = (size_t)((b * 512 + cbk + c4 + a) * 64 + h) * 64 + w;
            fout[idx] += g * acc[a][d];
        }
    }
}

// ---------------------------------------------------------------------------
// Host: tensor-map encoding via runtime driver-entry-point
// ---------------------------------------------------------------------------
typedef CUresult (*EncodeTiledFn)(
    CUtensorMap*, CUtensorMapDataType, cuuint32_t, void*,
    const cuuint64_t*, const cuuint64_t*, const cuuint32_t*, const cuuint32_t*,
    CUtensorMapInterleave, CUtensorMapSwizzle, CUtensorMapL2promotion,
    CUtensorMapFloatOOBfill);

static EncodeTiledFn get_encode_fn() {
    static EncodeTiledFn fn = nullptr;
    if (!fn) {
        void* p = nullptr;
        cudaDriverEntryPointQueryResult st;
        cudaGetDriverEntryPointByVersion("cuTensorMapEncodeTiled", &p, 12000,
                                         cudaEnableDefault, &st);
        fn = (EncodeTiledFn)p;
    }
    return fn;
}

static void encode_w3d(CUtensorMap* tm, void* ptr,
                       unsigned long long cin, unsigned long long m,
                       unsigned long long taps) {
    cuuint64_t dims[3] = {cin, m, taps};
    cuuint64_t strides[2] = {cin * 2, cin * m * 2};
    cuuint32_t box[3] = {64, 128, 1};
    cuuint32_t es[3] = {1, 1, 1};
    get_encode_fn()(tm, CU_TENSOR_MAP_DATA_TYPE_FLOAT16, 3, ptr, dims, strides,
                    box, es, CU_TENSOR_MAP_INTERLEAVE_NONE,
                    CU_TENSOR_MAP_SWIZZLE_128B,
                    CU_TENSOR_MAP_L2_PROMOTION_L2_128B,
                    CU_TENSOR_MAP_FLOAT_OOB_FILL_NONE);
}

static void encode_x4d(CUtensorMap* tm, void* ptr, unsigned long long C) {
    cuuint64_t dims[4] = {C, 64, 64, 4};
    cuuint64_t strides[3] = {C * 2, 64 * C * 2, 64ull * 64 * C * 2};
    cuuint32_t box[4] = {64, 64, 1, 1};
    cuuint32_t es[4] = {1, 1, 1, 1};
    get_encode_fn()(tm, CU_TENSOR_MAP_DATA_TYPE_FLOAT16, 4, ptr, dims, strides,
                    box, es, CU_TENSOR_MAP_INTERLEAVE_NONE,
                    CU_TENSOR_MAP_SWIZZLE_128B,
                    CU_TENSOR_MAP_L2_PROMOTION_L2_128B,
                    CU_TENSOR_MAP_FLOAT_OOB_FILL_NONE);
}

// ---------------------------------------------------------------------------
// Launch
// ---------------------------------------------------------------------------
extern "C" void kernel_launch(void* const* d_in, const int* in_sizes, int n_in,
                              void* d_out, int out_size)
{
    const float* x     = (const float*)d_in[0];
    const float* c1w   = (const float*)d_in[1];
    const float* bn1g  = (const float*)d_in[2];
    const float* bn1b  = (const float*)d_in[3];
    const float* bn1m  = (const float*)d_in[4];
    const float* bn1v  = (const float*)d_in[5];
    const float* qw    = (const float*)d_in[6];
    const float* qb    = (const float*)d_in[7];
    const float* kw    = (const float*)d_in[8];
    const float* kb    = (const float*)d_in[9];
    const float* vw    = (const float*)d_in[10];
    const float* vb    = (const float*)d_in[11];
    const float* gamma = (const float*)d_in[12];
    const float* c2w   = (const float*)d_in[13];
    const float* bn2g  = (const float*)d_in[14];
    const float* bn2b  = (const float*)d_in[15];
    const float* bn2m  = (const float*)d_in[16];
    const float* bn2v  = (const float*)d_in[17];
    float* out = (float*)d_out;

    float *fA, *fB, *gv, *gqk, *gat, *gbqk;
    __half *xh, *fh, *w1hi, *w1lo, *w2hi, *w2lo, *wqkhi, *wqklo, *wvhi, *wvlo;
    cudaGetSymbolAddress((void**)&fA, g_featsA);
    cudaGetSymbolAddress((void**)&fB, g_featsB);
    cudaGetSymbolAddress((void**)&gv, g_v);
    cudaGetSymbolAddress((void**)&gqk, g_qk);
    cudaGetSymbolAddress((void**)&gat, g_attn);
    cudaGetSymbolAddress((void**)&gbqk, g_bqk);
    cudaGetSymbolAddress((void**)&xh, g_xh);
    cudaGetSymbolAddress((void**)&fh, g_fh);
    cudaGetSymbolAddress((void**)&w1hi, g_w1hi);
    cudaGetSymbolAddress((void**)&w1lo, g_w1lo);
    cudaGetSymbolAddress((void**)&w2hi, g_w2hi);
    cudaGetSymbolAddress((void**)&w2lo, g_w2lo);
    cudaGetSymbolAddress((void**)&wqkhi, g_wqkhi);
    cudaGetSymbolAddress((void**)&wqklo, g_wqklo);
    cudaGetSymbolAddress((void**)&wvhi, g_wvhi);
    cudaGetSymbolAddress((void**)&wvlo, g_wvlo);

    static CUtensorMap tW1hi, tW1lo, tW2hi, tW2lo, tWvhi, tWvlo, tXh, tFh;
    encode_w3d(&tW1hi, w1hi, 2048, 512, 9);
    encode_w3d(&tW1lo, w1lo, 2048, 512, 9);
    encode_w3d(&tW2hi, w2hi, 512, 512, 9);
    encode_w3d(&tW2lo, w2lo, 512, 512, 9);
    encode_w3d(&tWvhi, wvhi, 512, 512, 1);
    encode_w3d(&tWvlo, wvlo, 512, 512, 1);
    encode_x4d(&tXh, xh, 2048);
    encode_x4d(&tFh, fh, 512);

    const int SMEM_TMA = 3 * 65536 + 1024;
    const int SMEM_P1  = 2 * 49152 + 1024;
    cudaFuncSetAttribute(mma_conv_tma<2048, 9, 1>, cudaFuncAttributeMaxDynamicSharedMemorySize, SMEM_TMA);
    cudaFuncSetAttribute(mma_conv_tma<512, 9, 1>,  cudaFuncAttributeMaxDynamicSharedMemorySize, SMEM_TMA);
    cudaFuncSetAttribute(mma_conv_tma<512, 1, 0>,  cudaFuncAttributeMaxDynamicSharedMemorySize, SMEM_TMA);
    cudaFuncSetAttribute(mma_proj_cg1<512>,        cudaFuncAttributeMaxDynamicSharedMemorySize, SMEM_P1);

    // ncu captures OUR launch index 3 -> conv1 stays there
    prep_wconv<<<(512 * 2048 + 255) / 256, 256>>>(c1w, w1hi, w1lo, 512, 2048);   // 0
    prep_act<<<dim3(128, 64, 4), dim3(32, 8)>>>(x, xh, 2048);                    // 1
    prep_wqk<<<256, 256>>>(qw, kw, qb, kb, wqkhi, wqklo, gbqk);                  // 2
    mma_conv_tma<2048, 9, 1><<<dim3(4, 32), 256, SMEM_TMA>>>(                    // 3: conv1
        tW1hi, tW1lo, tXh, bn1g, bn1b, bn1m, bn1v, fA, 512);
    prep_wlin<<<(512 * 512 + 255) / 256, 256>>>(vw, wvhi, wvlo, 512 * 512);      // 4
    prep_wconv<<<(512 * 512 + 255) / 256, 256>>>(c2w, w2hi, w2lo, 512, 512);     // 5

    // --- 2x criss-cross attention ---
    float* cur = fA;
    float* nxt = fB;
    for (int it = 0; it < 2; ++it) {
        prep_act<<<dim3(128, 16, 4), dim3(32, 8)>>>(cur, fh, 512);
        mma_proj_cg1<512><<<dim3(1, 128), 256, SMEM_P1>>>(
            wqkhi, wqklo, fh, gbqk, gqk, 128);
        mma_conv_tma<512, 1, 0><<<dim3(4, 32), 256, SMEM_TMA>>>(
            tWvhi, tWvlo, tFh, vb, nullptr, nullptr, nullptr, gv, 512);
        energyH_kernel<<<dim3(64, 4), 256>>>(gqk, gat);
        energyW_kernel<<<dim3(64, 4), 256>>>(gqk, gat);
        softmax_kernel<<<NPIX_ / 8, 256>>>(gat);
        aggH_kernel<<<dim3(64, 4, 8), 256>>>(gv, gat, cur, nxt, gamma);
        aggW_kernel<<<dim3(64, 4, 8), 256>>>(gv, gat, nxt, gamma);
        float* tmp = cur; cur = nxt; nxt = tmp;
    }

    // --- conv2 + BN + ReLU ---
    prep_act<<<dim3(128, 16, 4), dim3(32, 8)>>>(cur, fh, 512);
    mma_conv_tma<512, 9, 1><<<dim3(4, 32), 256, SMEM_TMA>>>(
        tW2hi, tW2lo, tFh, bn2g, bn2b, bn2m, bn2v, out, 512);
}

// round 12
// speedup vs baseline: 1.1698x; 1.0892x over previous
#include <cuda_runtime.h>
#include <cuda.h>
#include <cuda_fp16.h>
#include <math.h>
#include <stdint.h>

#define HW_   4096
#define NPIX_ 16384

#if defined(__CUDA_ARCH__) && (defined(__CUDA_ARCH_FEAT_SM103_ALL) || defined(__CUDA_ARCH_FEAT_SM100_ALL))
#define HAS_TC 1
#else
#define HAS_TC 0
#endif

#define WSCALE     64.0f
#define INV_WSCALE 0.015625f

// ---------------------------------------------------------------------------
// Scratch (device globals; allocation is forbidden). TMA sources aligned.
// ---------------------------------------------------------------------------
__device__ float g_featsA[4 * 512 * 4096];
__device__ float g_featsB[4 * 512 * 4096];
__device__ float g_v[4 * 512 * 4096];
__device__ float g_qk[4 * 128 * 4096];
__device__ float g_attn[4 * 4096 * 128];
__device__ float g_bqk[128];
__device__ __align__(128) __half g_xh[4 * 4096 * 2048];
__device__ __align__(128) __half g_fh[4 * 4096 * 512];
__device__ __align__(128) __half g_w1hi[9 * 512 * 2048];
__device__ __align__(128) __half g_w1lo[9 * 512 * 2048];
__device__ __align__(128) __half g_w2hi[9 * 512 * 512];
__device__ __align__(128) __half g_w2lo[9 * 512 * 512];
__device__ __align__(128) __half g_wqkhi[128 * 512];
__device__ __align__(128) __half g_wqklo[128 * 512];
__device__ __align__(128) __half g_wvhi[512 * 512];
__device__ __align__(128) __half g_wvlo[512 * 512];

// ---------------------------------------------------------------------------
// Generic helpers
// ---------------------------------------------------------------------------
__device__ __forceinline__ unsigned smem_u32(const void* p) {
    unsigned a;
    asm("{ .reg .u64 t; cvta.to.shared.u64 t, %1; cvt.u32.u64 %0, t; }"
        : "=r"(a) : "l"(p));
    return a;
}
__device__ __forceinline__ unsigned elect_one() {
    unsigned p;
    asm volatile("{ .reg .pred p; elect.sync _|p, 0xFFFFFFFF; selp.b32 %0, 1, 0, p; }"
                 : "=r"(p));
    return p;
}
#define SW128(o) ((o) ^ (((o) >> 3) & 0x70))
__device__ __forceinline__ void mbar_init(unsigned mbar, unsigned cnt) {
    asm volatile("mbarrier.init.shared.b64 [%0], %1;" :: "r"(mbar), "r"(cnt) : "memory");
}
__device__ __forceinline__ void mbar_wait(unsigned mbar, unsigned phase) {
    asm volatile(
        "{\n\t.reg .pred P;\n\t"
        "WL_%=:\n\t"
        "mbarrier.try_wait.parity.acquire.cta.shared::cta.b64 P, [%0], %1, 0x989680;\n\t"
        "@P bra.uni WD_%=;\n\t"
        "bra.uni WL_%=;\n\t"
        "WD_%=:\n\t}"
        :: "r"(mbar), "r"(phase) : "memory");
}
__device__ __forceinline__ void fence_async_shared() {
    asm volatile("fence.proxy.async;" ::: "memory");
}

// ---------------------------------------------------------------------------
// tcgen05 / TMA / cluster helpers (arch-specific pass only)
// ---------------------------------------------------------------------------
#if HAS_TC
static constexpr unsigned long long SMEM_DESC_BASE_SW128 =
    (2ull << 61) | (1ull << 46) | (64ull << 32) | (1ull << 16);
__device__ __forceinline__ unsigned long long make_desc(unsigned addr) {
    return SMEM_DESC_BASE_SW128 | ((unsigned long long)(addr >> 4) & 0x3FFFull);
}
__device__ __forceinline__ void cluster_sync_() {
    asm volatile("barrier.cluster.arrive.aligned;" ::: "memory");
    asm volatile("barrier.cluster.wait.aligned;" ::: "memory");
}
__device__ __forceinline__ void mbar_expect_tx(unsigned mbar, unsigned bytes) {
    asm volatile("mbarrier.arrive.expect_tx.shared.b64 _, [%0], %1;"
                 :: "r"(mbar), "r"(bytes) : "memory");
}
__device__ __forceinline__ void tmem_alloc_cg1(unsigned dst_smem, unsigned ncols) {
    asm volatile("tcgen05.alloc.cta_group::1.sync.aligned.shared::cta.b32 [%0], %1;"
                 :: "r"(dst_smem), "r"(ncols) : "memory");
}
__device__ __forceinline__ void tmem_dealloc_cg1(unsigned tmem, unsigned ncols) {
    asm volatile("tcgen05.dealloc.cta_group::1.sync.aligned.b32 %0, %1;"
                 :: "r"(tmem), "r"(ncols));
}
__device__ __forceinline__ void tmem_alloc_cg2(unsigned dst_smem, unsigned ncols) {
    asm volatile("tcgen05.alloc.cta_group::2.sync.aligned.shared::cta.b32 [%0], %1;"
                 :: "r"(dst_smem), "r"(ncols) : "memory");
}
__device__ __forceinline__ void tmem_dealloc_cg2(unsigned tmem, unsigned ncols) {
    asm volatile("tcgen05.dealloc.cta_group::2.sync.aligned.b32 %0, %1;"
                 :: "r"(tmem), "r"(ncols));
}
__device__ __forceinline__ void tc_relinquish_cg2() {
    asm volatile("tcgen05.relinquish_alloc_permit.cta_group::2.sync.aligned;");
}
__device__ __forceinline__ void tc_commit_cg1(unsigned mbar) {
    asm volatile("tcgen05.commit.cta_group::1.mbarrier::arrive::one.shared::cluster.b64 [%0];"
                 :: "r"(mbar) : "memory");
}
__device__ __forceinline__ void tc_commit_mc_cg2(unsigned mbar, unsigned short mask) {
    asm volatile("tcgen05.commit.cta_group::2.mbarrier::arrive::one.shared::cluster.multicast::cluster.b64 [%0], %1;"
                 :: "r"(mbar), "h"(mask) : "memory");
}
__device__ __forceinline__ void tc_fence_after() {
    asm volatile("tcgen05.fence::after_thread_sync;" ::: "memory");
}
__device__ __forceinline__ void tc_wait_ld() {
    asm volatile("tcgen05.wait::ld.sync.aligned;" ::: "memory");
}
__device__ __forceinline__ void mma_cg1(unsigned d, unsigned long long ad,
                                        unsigned long long bd, unsigned idesc, unsigned en) {
    asm volatile(
        "{\n\t.reg .pred p;\n\tsetp.ne.u32 p, %4, 0;\n\t"
        "tcgen05.mma.cta_group::1.kind::f16 [%0], %1, %2, %3, {%5, %5, %5, %5}, p;\n\t}"
        :: "r"(d), "l"(ad), "l"(bd), "r"(idesc), "r"(en), "r"(0u) : "memory");
}
__device__ __forceinline__ void mma_cg2(unsigned d, unsigned long long ad,
                                        unsigned long long bd, unsigned idesc, unsigned en) {
    asm volatile(
        "{\n\t.reg .pred p;\n\tsetp.ne.u32 p, %4, 0;\n\t"
        "tcgen05.mma.cta_group::2.kind::f16 [%0], %1, %2, %3, "
        "{%5, %5, %5, %5, %5, %5, %5, %5}, p;\n\t}"
        :: "r"(d), "l"(ad), "l"(bd), "r"(idesc), "r"(en), "r"(0u) : "memory");
}
__device__ __forceinline__ void tmem_ld32(unsigned* r, unsigned addr) {
    asm volatile(
        "tcgen05.ld.sync.aligned.32x32b.x32.b32 "
        "{%0, %1, %2, %3, %4, %5, %6, %7, "
        " %8, %9, %10, %11, %12, %13, %14, %15, "
        " %16, %17, %18, %19, %20, %21, %22, %23, "
        " %24, %25, %26, %27, %28, %29, %30, %31}, [%32];"
        : "=r"(r[0]),  "=r"(r[1]),  "=r"(r[2]),  "=r"(r[3]),
          "=r"(r[4]),  "=r"(r[5]),  "=r"(r[6]),  "=r"(r[7]),
          "=r"(r[8]),  "=r"(r[9]),  "=r"(r[10]), "=r"(r[11]),
          "=r"(r[12]), "=r"(r[13]), "=r"(r[14]), "=r"(r[15]),
          "=r"(r[16]), "=r"(r[17]), "=r"(r[18]), "=r"(r[19]),
          "=r"(r[20]), "=r"(r[21]), "=r"(r[22]), "=r"(r[23]),
          "=r"(r[24]), "=r"(r[25]), "=r"(r[26]), "=r"(r[27]),
          "=r"(r[28]), "=r"(r[29]), "=r"(r[30]), "=r"(r[31])
        : "r"(addr));
}
__device__ __forceinline__ void tma3d_cg2(unsigned dst, const CUtensorMap* m,
                                          int x, int y, int z, unsigned bar) {
    asm volatile(
        "{\n\t.reg .b32 lb;\n\tand.b32 lb, %5, 0xFEFFFFFF;\n\t"
        "cp.async.bulk.tensor.3d.cta_group::2.shared::cluster.global"
        ".tile.mbarrier::complete_tx::bytes [%0], [%1, {%2, %3, %4}], [lb];\n\t}"
        :: "r"(dst), "l"(m), "r"(x), "r"(y), "r"(z), "r"(bar) : "memory");
}
__device__ __forceinline__ void tma4d_cg2(unsigned dst, const CUtensorMap* m,
                                          int x, int y, int z, int w, unsigned bar) {
    asm volatile(
        "{\n\t.reg .b32 lb;\n\tand.b32 lb, %6, 0xFEFFFFFF;\n\t"
        "cp.async.bulk.tensor.4d.cta_group::2.shared::cluster.global"
        ".tile.mbarrier::complete_tx::bytes [%0], [%1, {%2, %3, %4, %5}], [lb];\n\t}"
        :: "r"(dst), "l"(m), "r"(x), "r"(y), "r"(z), "r"(w), "r"(bar) : "memory");
}
#endif

// ---------------------------------------------------------------------------
// Prep kernels
// ---------------------------------------------------------------------------
__device__ __forceinline__ void split_half(float x, __half& h, __half& l) {
    h = __float2half(x);
    l = __float2half(x - __half2float(h));
}

__global__ void prep_act(const float* __restrict__ src,
                         __half* __restrict__ dh, int CIN) {
    __shared__ float t[32][33];
    const int b = blockIdx.z, ct = blockIdx.y * 32, pt = blockIdx.x * 32;
    const int tx = threadIdx.x, ty = threadIdx.y;
    for (int i = ty; i < 32; i += 8)
        t[i][tx] = src[((size_t)(b * CIN + ct + i)) * HW_ + pt + tx];
    __syncthreads();
    for (int i = ty; i < 32; i += 8) {
        size_t o = ((size_t)(b * HW_ + pt + i)) * CIN + ct + tx;
        dh[o] = __float2half(t[tx][i]);
    }
}

__global__ void prep_wconv(const float* __restrict__ W,
                           __half* __restrict__ dhi,
                           __half* __restrict__ dlo, int M, int CIN) {
    int idx = blockIdx.x * 256 + threadIdx.x;
    if (idx >= M * CIN) return;
#pragma unroll
    for (int tap = 0; tap < 9; tap++) {
        float x = W[(size_t)idx * 9 + tap] * WSCALE;
        __half h, l;
        split_half(x, h, l);
        size_t o = (size_t)tap * M * CIN + idx;
        dhi[o] = h;
        dlo[o] = l;
    }
}

__global__ void prep_wlin(const float* __restrict__ W,
                          __half* __restrict__ dhi,
                          __half* __restrict__ dlo, int n) {
    int i = blockIdx.x * 256 + threadIdx.x;
    if (i >= n) return;
    __half h, l;
    split_half(W[i] * WSCALE, h, l);
    dhi[i] = h;
    dlo[i] = l;
}

__global__ void prep_wqk(const float* __restrict__ qw, const float* __restrict__ kw,
                         const float* __restrict__ qb, const float* __restrict__ kb,
                         __half* __restrict__ dhi, __half* __restrict__ dlo,
                         float* __restrict__ bias) {
    int i = blockIdx.x * 256 + threadIdx.x;
    if (i < 128) bias[i] = (i < 64) ? qb[i] : kb[i - 64];
    if (i >= 128 * 512) return;
    float x = ((i < 64 * 512) ? qw[i] : kw[i - 64 * 512]) * WSCALE;
    __half h, l;
    split_half(x, h, l);
    dhi[i] = h;
    dlo[i] = l;
}

// ---------------------------------------------------------------------------
// cg2 implicit-conv GEMM, TMA pipeline, warp-specialized control:
//   thread 0   (both CTAs)  : producer — done-waits, expect_tx, TMA issues
//   thread 32  (rank 0 only): consumer — full-waits, MMA dispatch, commit
// ---------------------------------------------------------------------------
template<int CIN, int TAPS, int EPI>
__global__ void __launch_bounds__(256, 1) __cluster_dims__(2, 1, 1)
mma_conv_tma(const __grid_constant__ CUtensorMap tWhi,
             const __grid_constant__ CUtensorMap tWlo,
             const __grid_constant__ CUtensorMap tX,
             const float* __restrict__ e0, const float* __restrict__ e1,
             const float* __restrict__ e2, const float* __restrict__ e3,
             float* __restrict__ Y, int Mtot)
{
#if HAS_TC
    constexpr int NCHUNK = TAPS * (CIN / 64);
    constexpr int NST   = 3;
    constexpr int A_HI  = 0;
    constexpr int A_LO  = 16384;
    constexpr int B_0   = 32768;
    constexpr int STAGE = 65536;
    constexpr unsigned IDESC2 = (1u << 4) | (16u << 17) | (16u << 24);

    extern __shared__ char dyn_smem[];
    __shared__ __align__(8) unsigned long long s_full[NST];
    __shared__ __align__(8) unsigned long long s_done[NST];
    __shared__ unsigned s_tmem[1];

    char* sm = (char*)((((uintptr_t)dyn_smem) + 1023) & ~(uintptr_t)1023);
    const unsigned sbase = smem_u32(sm);

    const int tid  = threadIdx.x;
    const int wid  = tid >> 5;
    const int lane = tid & 31;
    const unsigned rank = blockIdx.x & 1;
    const int m_base = (blockIdx.x >> 1) * 256;
    const int n_base = blockIdx.y * 512;
    const int bb    = n_base >> 12;
    const int sp00  = n_base & 4095;
    const int hrow0 = sp00 >> 6;

    if (wid == 0) tmem_alloc_cg2(smem_u32(&s_tmem[0]), 512);
    if (tid == 0) {
#pragma unroll
        for (int s = 0; s < NST; ++s) {
            mbar_init(smem_u32(&s_full[s]), 1);
            mbar_init(smem_u32(&s_done[s]), 1);
        }
    }
    __syncthreads();
    unsigned tmem;
    asm volatile("ld.shared.b32 %0, [%1];" : "=r"(tmem) : "r"(smem_u32(&s_tmem[0])));
    unsigned fullb[NST], doneb[NST];
#pragma unroll
    for (int s = 0; s < NST; ++s) {
        fullb[s] = smem_u32(&s_full[s]);
        doneb[s] = smem_u32(&s_done[s]);
    }
    cluster_sync_();

    if (tid == 0) {
        // ---- producer ----
        int dph[NST] = {0, 0, 0};
        for (int i = 0; i < NCHUNK; ++i) {
            const int s = i % NST;
            if (i >= NST) { mbar_wait(doneb[s], dph[s]); dph[s] ^= 1; }
            if (rank == 0) mbar_expect_tx(fullb[s], 2 * STAGE);

            const int tap = (TAPS == 1) ? 0 : i / (CIN / 64);
            const int cb  = (TAPS == 1) ? i * 64 : (i % (CIN / 64)) * 64;
            const int dh  = (TAPS == 9) ? (tap / 3 - 1) : 0;
            const int dw  = (TAPS == 9) ? (tap % 3 - 1) : 0;
            const unsigned stg = sbase + s * STAGE;

            tma3d_cg2(stg + A_HI, &tWhi, cb, m_base + (int)rank * 128, tap, fullb[s]);
            tma3d_cg2(stg + A_LO, &tWlo, cb, m_base + (int)rank * 128, tap, fullb[s]);
#pragma unroll
            for (int t = 0; t < 4; ++t)
                tma4d_cg2(stg + B_0 + t * 8192, &tX,
                          cb, dw, hrow0 + 2 * t + (int)rank + dh, bb, fullb[s]);
        }
        // final drain: last chunk's done (its commit proves all prior MMAs done)
        const int sl = (NCHUNK - 1) % NST;
        mbar_wait(doneb[sl], dph[sl]);
    }
    if (rank == 0 && tid == 32) {
        // ---- consumer ----
        int fph[NST] = {0, 0, 0};
        for (int i = 0; i < NCHUNK; ++i) {
            const int s = i % NST;
            mbar_wait(fullb[s], fph[s]); fph[s] ^= 1;
            const unsigned sg = sbase + s * STAGE;
            unsigned long long dAh = make_desc(sg + A_HI);
            unsigned long long dAl = make_desc(sg + A_LO);
#pragma unroll
            for (int t = 0; t < 4; ++t) {
                unsigned d = tmem + t * 128;
                unsigned long long dB = make_desc(sg + B_0 + t * 8192);
#pragma unroll
                for (int kk = 0; kk < 4; ++kk) {
                    unsigned en0 = (i > 0 || kk > 0) ? 1u : 0u;
                    mma_cg2(d, dAh + kk * 2, dB + kk * 2, IDESC2, en0);
                    mma_cg2(d, dAl + kk * 2, dB + kk * 2, IDESC2, 1u);
                }
            }
            tc_commit_mc_cg2(doneb[s], 0x3);
        }
    }
    __syncthreads();
    tc_fence_after();

    // --- epilogue ---
    {
        const int wg = wid >> 2;
        const int mg = m_base + (int)rank * 128 + (wid & 3) * 32 + lane;
        float sc, sh;
        if (EPI == 1) {
            float tt = e0[mg] * rsqrtf(e3[mg] + 1e-5f);
            sc = tt * INV_WSCALE;
            sh = e1[mg] - e2[mg] * tt;
        } else {
            sc = INV_WSCALE;
            sh = e0[mg];
        }
        float* yrow = Y + ((size_t)(bb * Mtot + mg)) * HW_ + sp00;
#pragma unroll
        for (int ti = 0; ti < 2; ++ti) {
            int t = wg * 2 + ti;
#pragma unroll
            for (int cb4 = 0; cb4 < 4; ++cb4) {
                unsigned r[32];
                tmem_ld32(r, tmem + t * 128 + cb4 * 32);
                tc_wait_ld();
#pragma unroll
                for (int j = 0; j < 32; j += 4) {
                    float4 v;
                    v.x = fmaf(__uint_as_float(r[j + 0]), sc, sh);
                    v.y = fmaf(__uint_as_float(r[j + 1]), sc, sh);
                    v.z = fmaf(__uint_as_float(r[j + 2]), sc, sh);
                    v.w = fmaf(__uint_as_float(r[j + 3]), sc, sh);
                    if (EPI == 1) {
                        v.x = fmaxf(v.x, 0.f); v.y = fmaxf(v.y, 0.f);
                        v.z = fmaxf(v.z, 0.f); v.w = fmaxf(v.w, 0.f);
                    }
                    *(float4*)(yrow + t * 128 + cb4 * 32 + j) = v;
                }
            }
        }
    }
    __syncthreads();
    if (wid == 0) {
        tc_relinquish_cg2();
        tmem_dealloc_cg2(tmem, 512);
    }
    cluster_sync_();
#endif
}

// ---------------------------------------------------------------------------
// cg1 GEMM for the stacked q/k projection (M=128)
// ---------------------------------------------------------------------------
template<int CIN>
__global__ void __launch_bounds__(256, 1)
mma_proj_cg1(const __half* __restrict__ Whi, const __half* __restrict__ Wlo,
             const __half* __restrict__ Xh,
             const float* __restrict__ e0, float* __restrict__ Y, int Mtot)
{
#if HAS_TC
    constexpr int A_BYTES = 128 * 128;
    constexpr int B_BYTES = 128 * 128;
    constexpr int STAGE   = 2 * A_BYTES + B_BYTES;
    constexpr int NCHUNK  = CIN / 64;
    constexpr unsigned IDESC = (1u << 4) | (16u << 17) | (8u << 24);

    extern __shared__ char dyn_smem[];
    __shared__ __align__(8) unsigned long long s_mbar[2];
    __shared__ unsigned s_tmem[1];

    char* sm = (char*)((((uintptr_t)dyn_smem) + 1023) & ~(uintptr_t)1023);
    const unsigned sbase = smem_u32(sm);
    const int tid = threadIdx.x;
    const int wid = tid >> 5;
    const int lane = tid & 31;

    if (wid == 0) tmem_alloc_cg1(smem_u32(&s_tmem[0]), 256);
    if (tid == 0) { mbar_init(smem_u32(&s_mbar[0]), 1); mbar_init(smem_u32(&s_mbar[1]), 1); }
    __syncthreads();
    unsigned tmem;
    asm volatile("ld.shared.b32 %0, [%1];" : "=r"(tmem) : "r"(smem_u32(&s_tmem[0])));
    const unsigned mbar[2] = { smem_u32(&s_mbar[0]), smem_u32(&s_mbar[1]) };

    const int n_base = blockIdx.y * 128;
    const int bb  = n_base >> 12;
    const int sp0 = n_base & 4095;
    int ph[2] = {0, 0};

    for (int chunk = 0; chunk < NCHUNK; ++chunk) {
        const int s  = chunk & 1;
        const int cb = chunk * 64;
        if (chunk >= 2) { mbar_wait(mbar[s], ph[s]); ph[s] ^= 1; }

        char* aHi = sm + s * STAGE;
        char* aLo = aHi + A_BYTES;
        char* bH  = aLo + A_BYTES;
#pragma unroll
        for (int u = 0; u < 4; ++u) {
            int l = u * 256 + tid;
            int row = l >> 3, c16 = l & 7;
            size_t go = (size_t)row * CIN + cb + c16 * 8;
            unsigned so = SW128((unsigned)(row * 128 + c16 * 16));
            *(uint4*)(aHi + so) = *(const uint4*)(Whi + go);
            *(uint4*)(aLo + so) = *(const uint4*)(Wlo + go);
        }
#pragma unroll
        for (int u = 0; u < 4; ++u) {
            int l = u * 256 + tid;
            int row = l >> 3, c16 = l & 7;
            size_t go = ((size_t)(bb * HW_ + sp0 + row)) * CIN + cb + c16 * 8;
            unsigned so = SW128((unsigned)(row * 128 + c16 * 16));
            *(uint4*)(bH + so) = *(const uint4*)(Xh + go);
        }
        fence_async_shared();
        __syncthreads();

        if (wid == 0 && elect_one()) {
            unsigned long long dAh = make_desc(sbase + s * STAGE);
            unsigned long long dAl = dAh + (A_BYTES >> 4);
            unsigned long long dB  = make_desc(sbase + s * STAGE + 2 * A_BYTES);
#pragma unroll
            for (int kk = 0; kk < 4; ++kk) {
                unsigned en0 = (chunk > 0 || kk > 0) ? 1u : 0u;
                mma_cg1(tmem, dAh + kk * 2, dB + kk * 2, IDESC, en0);
                mma_cg1(tmem, dAl + kk * 2, dB + kk * 2, IDESC, 1u);
            }
            tc_commit_cg1(mbar[s]);
        }
    }
    {
        int s0 = (NCHUNK - 2) & 1, s1 = (NCHUNK - 1) & 1;
        mbar_wait(mbar[s0], ph[s0]); ph[s0] ^= 1;
        mbar_wait(mbar[s1], ph[s1]); ph[s1] ^= 1;
    }
    tc_fence_after();

    if (wid < 4) {
        const int mg = wid * 32 + lane;
        float sh = e0[mg];
        float* yrow = Y + ((size_t)(bb * Mtot + mg)) * HW_ + sp0;
#pragma unroll
        for (int cb4 = 0; cb4 < 4; ++cb4) {
            unsigned r[32];
            tmem_ld32(r, tmem + cb4 * 32);
            tc_wait_ld();
#pragma unroll
            for (int j = 0; j < 32; j += 4) {
                float4 v;
                v.x = fmaf(__uint_as_float(r[j + 0]), INV_WSCALE, sh);
                v.y = fmaf(__uint_as_float(r[j + 1]), INV_WSCALE, sh);
                v.z = fmaf(__uint_as_float(r[j + 2]), INV_WSCALE, sh);
                v.w = fmaf(__uint_as_float(r[j + 3]), INV_WSCALE, sh);
                *(float4*)(yrow + cb4 * 32 + j) = v;
            }
        }
    }
    __syncthreads();
    if (wid == 0) tmem_dealloc_cg1(tmem, 256);
#endif
}

// ---------------------------------------------------------------------------
// CCA kernels — register-tiled 4x4 outer products (proven R11)
// ---------------------------------------------------------------------------
__global__ void __launch_bounds__(256) energyH_kernel(
    const float* __restrict__ qk, float* __restrict__ attn)
{
    const int w = blockIdx.x, b = blockIdx.y;
    __shared__ float Qs[64][65];
    __shared__ float Ks[64][65];
    const int tid = threadIdx.x;
    for (int l = tid; l < 4096; l += 256) {
        int c = l >> 6, h = l & 63;
        Qs[c][h] = qk[((size_t)(b * 128 + c)) * HW_ + h * 64 + w];
        Ks[c][h] = qk[((size_t)(b * 128 + 64 + c)) * HW_ + h * 64 + w];
    }
    __syncthreads();
    const int i4 = (tid & 15) * 4, h4 = (tid >> 4) * 4;
    float acc[4][4];
#pragma unroll
    for (int a = 0; a < 4; a++)
#pragma unroll
        for (int d = 0; d < 4; d++) acc[a][d] = 0.f;
    for (int c = 0; c < 64; c++) {
        float q0 = Qs[c][h4], q1 = Qs[c][h4 + 1], q2 = Qs[c][h4 + 2], q3 = Qs[c][h4 + 3];
        float k0 = Ks[c][i4], k1 = Ks[c][i4 + 1], k2 = Ks[c][i4 + 2], k3 = Ks[c][i4 + 3];
        acc[0][0] += q0 * k0; acc[0][1] += q0 * k1; acc[0][2] += q0 * k2; acc[0][3] += q0 * k3;
        acc[1][0] += q1 * k0; acc[1][1] += q1 * k1; acc[1][2] += q1 * k2; acc[1][3] += q1 * k3;
        acc[2][0] += q2 * k0; acc[2][1] += q2 * k1; acc[2][2] += q2 * k2; acc[2][3] += q2 * k3;
        acc[3][0] += q3 * k0; acc[3][1] += q3 * k1; acc[3][2] += q3 * k2; acc[3][3] += q3 * k3;
    }
#pragma unroll
    for (int a = 0; a < 4; a++) {
        int h = h4 + a;
        float4 o;
        o.x = acc[a][0] + ((i4 + 0 == h) ? -1000000000.0f : 0.f);
        o.y = acc[a][1] + ((i4 + 1 == h) ? -1000000000.0f : 0.f);
        o.z = acc[a][2] + ((i4 + 2 == h) ? -1000000000.0f : 0.f);
        o.w = acc[a][3] + ((i4 + 3 == h) ? -1000000000.0f : 0.f);
        *(float4*)(attn + (size_t)(((b * 64 + h) * 64 + w)) * 128 + i4) = o;
    }
}

__global__ void __launch_bounds__(256) energyW_kernel(
    const float* __restrict__ qk, float* __restrict__ attn)
{
    const int h = blockIdx.x, b = blockIdx.y;
    __shared__ float Qs[64][65];
    __shared__ float Ks[64][65];
    const int tid = threadIdx.x;
    for (int l = tid; l < 4096; l += 256) {
        int c = l >> 6, w = l & 63;
        Qs[c][w] = qk[((size_t)(b * 128 + c)) * HW_ + h * 64 + w];
        Ks[c][w] = qk[((size_t)(b * 128 + 64 + c)) * HW_ + h * 64 + w];
    }
    __syncthreads();
    const int j4 = (tid & 15) * 4, w4 = (tid >> 4) * 4;
    float acc[4][4];
#pragma unroll
    for (int a = 0; a < 4; a++)
#pragma unroll
        for (int d = 0; d < 4; d++) acc[a][d] = 0.f;
    for (int c = 0; c < 64; c++) {
        float q0 = Qs[c][w4], q1 = Qs[c][w4 + 1], q2 = Qs[c][w4 + 2], q3 = Qs[c][w4 + 3];
        float k0 = Ks[c][j4], k1 = Ks[c][j4 + 1], k2 = Ks[c][j4 + 2], k3 = Ks[c][j4 + 3];
        acc[0][0] += q0 * k0; acc[0][1] += q0 * k1; acc[0][2] += q0 * k2; acc[0][3] += q0 * k3;
        acc[1][0] += q1 * k0; acc[1][1] += q1 * k1; acc[1][2] += q1 * k2; acc[1][3] += q1 * k3;
        acc[2][0] += q2 * k0; acc[2][1] += q2 * k1; acc[2][2] += q2 * k2; acc[2][3] += q2 * k3;
        acc[3][0] += q3 * k0; acc[3][1] += q3 * k1; acc[3][2] += q3 * k2; acc[3][3] += q3 * k3;
    }
#pragma unroll
    for (int a = 0; a < 4; a++) {
        int w = w4 + a;
        float4 o = make_float4(acc[a][0], acc[a][1], acc[a][2], acc[a][3]);
        *(float4*)(attn + (size_t)(((b * 64 + h) * 64 + w)) * 128 + 64 + j4) = o;
    }
}

__global__ void __launch_bounds__(256) softmax_kernel(float* __restrict__ attn)
{
    int gw = (blockIdx.x * blockDim.x + threadIdx.x) >> 5;
    if (gw >= NPIX_) return;
    int lane = threadIdx.x & 31;
    float* row = attn + (size_t)gw * 128;
    float v0 = row[lane], v1 = row[lane + 32], v2 = row[lane + 64], v3 = row[lane + 96];
    float mx = fmaxf(fmaxf(v0, v1), fmaxf(v2, v3));
#pragma unroll
    for (int o = 16; o > 0; o >>= 1) mx = fmaxf(mx, __shfl_xor_sync(0xffffffffu, mx, o));
    v0 = expf(v0 - mx); v1 = expf(v1 - mx); v2 = expf(v2 - mx); v3 = expf(v3 - mx);
    float s = v0 + v1 + v2 + v3;
#pragma unroll
    for (int o = 16; o > 0; o >>= 1) s += __shfl_xor_sync(0xffffffffu, s, o);
    float inv = 1.0f / s;
    row[lane] = v0 * inv; row[lane + 32] = v1 * inv;
    row[lane + 64] = v2 * inv; row[lane + 96] = v3 * inv;
}

__global__ void __launch_bounds__(256) aggH_kernel(
    const float* __restrict__ v, const float* __restrict__ attn,
    const float* __restrict__ fin, float* __restrict__ fout,
    const float* __restrict__ gptr)
{
    const int w = blockIdx.x, b = blockIdx.y, cbk = blockIdx.z * 64;
    __shared__ float Vs[64][65];
    __shared__ float Am[64][65];
    const int tid = threadIdx.x;
    for (int l = tid; l < 4096; l += 256) {
        int c = l >> 6, i = l & 63;
        Vs[c][i] = v[(size_t)((b * 512 + cbk + c) * 64 + i) * 64 + w];
    }
    for (int l = tid; l < 4096; l += 256) {
        int h = l >> 6, i = l & 63;
        Am[h][i] = attn[(size_t)(((b * 64 + h) * 64 + w)) * 128 + i];
    }
    __syncthreads();
    const int c4 = (tid & 15) * 4, h4 = (tid >> 4) * 4;
    float acc[4][4];
#pragma unroll
    for (int a = 0; a < 4; a++)
#pragma unroll
        for (int d = 0; d < 4; d++) acc[a][d] = 0.f;
    for (int i = 0; i < 64; i++) {
        float v0 = Vs[c4][i], v1 = Vs[c4 + 1][i], v2 = Vs[c4 + 2][i], v3 = Vs[c4 + 3][i];
        float a0 = Am[h4][i], a1 = Am[h4 + 1][i], a2 = Am[h4 + 2][i], a3 = Am[h4 + 3][i];
        acc[0][0] += v0 * a0; acc[0][1] += v0 * a1; acc[0][2] += v0 * a2; acc[0][3] += v0 * a3;
        acc[1][0] += v1 * a0; acc[1][1] += v1 * a1; acc[1][2] += v1 * a2; acc[1][3] += v1 * a3;
        acc[2][0] += v2 * a0; acc[2][1] += v2 * a1; acc[2][2] += v2 * a2; acc[2][3] += v2 * a3;
        acc[3][0] += v3 * a0; acc[3][1] += v3 * a1; acc[3][2] += v3 * a2; acc[3][3] += v3 * a3;
    }
    const float g = *gptr;
#pragma unroll
    for (int a = 0; a < 4; a++) {
#pragma unroll
        for (int d = 0; d < 4; d++) {
            int h = h4 + d;
            size_t idx = (size_t)((b * 512 + cbk + c4 + a) * 64 + h) * 64 + w;
            fout[idx] = fin[idx] + g * acc[a][d];
        }
    }
}

__global__ void __launch_bounds__(256) aggW_kernel(
    const float* __restrict__ v, const float* __restrict__ attn,
    float* __restrict__ fout, const float* __restrict__ gptr)
{
    const int h = blockIdx.x, b = blockIdx.y, cbk = blockIdx.z * 64;
    __shared__ float Vs[64][65];
    __shared__ float Am[64][65];
    const int tid = threadIdx.x;
    for (int l = tid; l < 4096; l += 256) {
        int c = l >> 6, j = l & 63;
        Vs[c][j] = v[(size_t)((b * 512 + cbk + c) * 64 + h) * 64 + j];
    }
    for (int l = tid; l < 4096; l += 256) {
        int w = l >> 6, j = l & 63;
        Am[w][j] = attn[(size_t)(((b * 64 + h) * 64 + w)) * 128 + 64 + j];
    }
    __syncthreads();
    const int c4 = (tid & 15) * 4, w4 = (tid >> 4) * 4;
    float acc[4][4];
#pragma unroll
    for (int a = 0; a < 4; a++)
#pragma unroll
        for (int d = 0; d < 4; d++) acc[a][d] = 0.f;
    for (int j = 0; j < 64; j++) {
        float v0 = Vs[c4][j], v1 = Vs[c4 + 1][j], v2 = Vs[c4 + 2][j], v3 = Vs[c4 + 3][j];
        float a0 = Am[w4][j], a1 = Am[w4 + 1][j], a2 = Am[w4 + 2][j], a3 = Am[w4 + 3][j];
        acc[0][0] += v0 * a0; acc[0][1] += v0 * a1; acc[0][2] += v0 * a2; acc[0][3] += v0 * a3;
        acc[1][0] += v1 * a0; acc[1][1] += v1 * a1; acc[1][2] += v1 * a2; acc[1][3] += v1 * a3;
        acc[2][0] += v2 * a0; acc[2][1] += v2 * a1; acc[2][2] += v2 * a2; acc[2][3] += v2 * a3;
        acc[3][0] += v3 * a0; acc[3][1] += v3 * a1; acc[3][2] += v3 * a2; acc[3][3] += v3 * a3;
    }
    const float g = *gptr;
#pragma unroll
    for (int a = 0; a < 4; a++) {
#pragma unroll
        for (int d = 0; d < 4; d++) {
            int w = w4 + d;
            size_t idx = (size_t)((b * 512 + cbk + c4 + a) * 64 + h) * 64 + w;
            fout[idx] += g * acc[a][d];
        }
    }
}

// ---------------------------------------------------------------------------
// Host: tensor-map encoding via runtime driver-entry-point
// ---------------------------------------------------------------------------
typedef CUresult (*EncodeTiledFn)(
    CUtensorMap*, CUtensorMapDataType, cuuint32_t, void*,
    const cuuint64_t*, const cuuint64_t*, const cuuint32_t*, const cuuint32_t*,
    CUtensorMapInterleave, CUtensorMapSwizzle, CUtensorMapL2promotion,
    CUtensorMapFloatOOBfill);

static EncodeTiledFn get_encode_fn() {
    static EncodeTiledFn fn = nullptr;
    if (!fn) {
        void* p = nullptr;
        cudaDriverEntryPointQueryResult st;
        cudaGetDriverEntryPointByVersion("cuTensorMapEncodeTiled", &p, 12000,
                                         cudaEnableDefault, &st);
        fn = (EncodeTiledFn)p;
    }
    return fn;
}

static void encode_w3d(CUtensorMap* tm, void* ptr,
                       unsigned long long cin, unsigned long long m,
                       unsigned long long taps) {
    cuuint64_t dims[3] = {cin, m, taps};
    cuuint64_t strides[2] = {cin * 2, cin * m * 2};
    cuuint32_t box[3] = {64, 128, 1};
    cuuint32_t es[3] = {1, 1, 1};
    get_encode_fn()(tm, CU_TENSOR_MAP_DATA_TYPE_FLOAT16, 3, ptr, dims, strides,
                    box, es, CU_TENSOR_MAP_INTERLEAVE_NONE,
                    CU_TENSOR_MAP_SWIZZLE_128B,
                    CU_TENSOR_MAP_L2_PROMOTION_L2_128B,
                    CU_TENSOR_MAP_FLOAT_OOB_FILL_NONE);
}

static void encode_x4d(CUtensorMap* tm, void* ptr, unsigned long long C) {
    cuuint64_t dims[4] = {C, 64, 64, 4};
    cuuint64_t strides[3] = {C * 2, 64 * C * 2, 64ull * 64 * C * 2};
    cuuint32_t box[4] = {64, 64, 1, 1};
    cuuint32_t es[4] = {1, 1, 1, 1};
    get_encode_fn()(tm, CU_TENSOR_MAP_DATA_TYPE_FLOAT16, 4, ptr, dims, strides,
                    box, es, CU_TENSOR_MAP_INTERLEAVE_NONE,
                    CU_TENSOR_MAP_SWIZZLE_128B,
                    CU_TENSOR_MAP_L2_PROMOTION_L2_128B,
                    CU_TENSOR_MAP_FLOAT_OOB_FILL_NONE);
}

// ---------------------------------------------------------------------------
// Launch
// ---------------------------------------------------------------------------
extern "C" void kernel_launch(void* const* d_in, const int* in_sizes, int n_in,
                              void* d_out, int out_size)
{
    const float* x     = (const float*)d_in[0];
    const float* c1w   = (const float*)d_in[1];
    const float* bn1g  = (const float*)d_in[2];
    const float* bn1b  = (const float*)d_in[3];
    const float* bn1m  = (const float*)d_in[4];
    const float* bn1v  = (const float*)d_in[5];
    const float* qw    = (const float*)d_in[6];
    const float* qb    = (const float*)d_in[7];
    const float* kw    = (const float*)d_in[8];
    const float* kb    = (const float*)d_in[9];
    const float* vw    = (const float*)d_in[10];
    const float* vb    = (const float*)d_in[11];
    const float* gamma = (const float*)d_in[12];
    const float* c2w   = (const float*)d_in[13];
    const float* bn2g  = (const float*)d_in[14];
    const float* bn2b  = (const float*)d_in[15];
    const float* bn2m  = (const float*)d_in[16];
    const float* bn2v  = (const float*)d_in[17];
    float* out = (float*)d_out;

    float *fA, *fB, *gv, *gqk, *gat, *gbqk;
    __half *xh, *fh, *w1hi, *w1lo, *w2hi, *w2lo, *wqkhi, *wqklo, *wvhi, *wvlo;
    cudaGetSymbolAddress((void**)&fA, g_featsA);
    cudaGetSymbolAddress((void**)&fB, g_featsB);
    cudaGetSymbolAddress((void**)&gv, g_v);
    cudaGetSymbolAddress((void**)&gqk, g_qk);
    cudaGetSymbolAddress((void**)&gat, g_attn);
    cudaGetSymbolAddress((void**)&gbqk, g_bqk);
    cudaGetSymbolAddress((void**)&xh, g_xh);
    cudaGetSymbolAddress((void**)&fh, g_fh);
    cudaGetSymbolAddress((void**)&w1hi, g_w1hi);
    cudaGetSymbolAddress((void**)&w1lo, g_w1lo);
    cudaGetSymbolAddress((void**)&w2hi, g_w2hi);
    cudaGetSymbolAddress((void**)&w2lo, g_w2lo);
    cudaGetSymbolAddress((void**)&wqkhi, g_wqkhi);
    cudaGetSymbolAddress((void**)&wqklo, g_wqklo);
    cudaGetSymbolAddress((void**)&wvhi, g_wvhi);
    cudaGetSymbolAddress((void**)&wvlo, g_wvlo);

    static CUtensorMap tW1hi, tW1lo, tW2hi, tW2lo, tWvhi, tWvlo, tXh, tFh;
    encode_w3d(&tW1hi, w1hi, 2048, 512, 9);
    encode_w3d(&tW1lo, w1lo, 2048, 512, 9);
    encode_w3d(&tW2hi, w2hi, 512, 512, 9);
    encode_w3d(&tW2lo, w2lo, 512, 512, 9);
    encode_w3d(&tWvhi, wvhi, 512, 512, 1);
    encode_w3d(&tWvlo, wvlo, 512, 512, 1);
    encode_x4d(&tXh, xh, 2048);
    encode_x4d(&tFh, fh, 512);

    const int SMEM_TMA = 3 * 65536 + 1024;
    const int SMEM_P1  = 2 * 49152 + 1024;
    cudaFuncSetAttribute(mma_conv_tma<2048, 9, 1>, cudaFuncAttributeMaxDynamicSharedMemorySize, SMEM_TMA);
    cudaFuncSetAttribute(mma_conv_tma<512, 9, 1>,  cudaFuncAttributeMaxDynamicSharedMemorySize, SMEM_TMA);
    cudaFuncSetAttribute(mma_conv_tma<512, 1, 0>,  cudaFuncAttributeMaxDynamicSharedMemorySize, SMEM_TMA);
    cudaFuncSetAttribute(mma_proj_cg1<512>,        cudaFuncAttributeMaxDynamicSharedMemorySize, SMEM_P1);

    // ncu captures OUR launch index 3 -> conv1 stays there
    prep_wconv<<<(512 * 2048 + 255) / 256, 256>>>(c1w, w1hi, w1lo, 512, 2048);   // 0
    prep_act<<<dim3(128, 64, 4), dim3(32, 8)>>>(x, xh, 2048);                    // 1
    prep_wqk<<<256, 256>>>(qw, kw, qb, kb, wqkhi, wqklo, gbqk);                  // 2
    mma_conv_tma<2048, 9, 1><<<dim3(4, 32), 256, SMEM_TMA>>>(                    // 3: conv1
        tW1hi, tW1lo, tXh, bn1g, bn1b, bn1m, bn1v, fA, 512);
    prep_wlin<<<(512 * 512 + 255) / 256, 256>>>(vw, wvhi, wvlo, 512 * 512);      // 4
    prep_wconv<<<(512 * 512 + 255) / 256, 256>>>(c2w, w2hi, w2lo, 512, 512);     // 5

    // --- 2x criss-cross attention ---
    float* cur = fA;
    float* nxt = fB;
    for (int it = 0; it < 2; ++it) {
        prep_act<<<dim3(128, 16, 4), dim3(32, 8)>>>(cur, fh, 512);
        mma_proj_cg1<512><<<dim3(1, 128), 256, SMEM_P1>>>(
            wqkhi, wqklo, fh, gbqk, gqk, 128);
        mma_conv_tma<512, 1, 0><<<dim3(4, 32), 256, SMEM_TMA>>>(
            tWvhi, tWvlo, tFh, vb, nullptr, nullptr, nullptr, gv, 512);
        energyH_kernel<<<dim3(64, 4), 256>>>(gqk, gat);
        energyW_kernel<<<dim3(64, 4), 256>>>(gqk, gat);
        softmax_kernel<<<NPIX_ / 8, 256>>>(gat);
        aggH_kernel<<<dim3(64, 4, 8), 256>>>(gv, gat, cur, nxt, gamma);
        aggW_kernel<<<dim3(64, 4, 8), 256>>>(gv, gat, nxt, gamma);
        float* tmp = cur; cur = nxt; nxt = tmp;
    }

    // --- conv2 + BN + ReLU ---
    prep_act<<<dim3(128, 16, 4), dim3(32, 8)>>>(cur, fh, 512);
    mma_conv_tma<512, 9, 1><<<dim3(4, 32), 256, SMEM_TMA>>>(
        tW2hi, tW2lo, tFh, bn2g, bn2b, bn2m, bn2v, out, 512);
}

// round 13
// speedup vs baseline: 1.4004x; 1.1971x over previous
#include <cuda_runtime.h>
#include <cuda.h>
#include <cuda_fp16.h>
#include <math.h>
#include <stdint.h>

#define HW_   4096
#define NPIX_ 16384

#if defined(__CUDA_ARCH__) && (defined(__CUDA_ARCH_FEAT_SM103_ALL) || defined(__CUDA_ARCH_FEAT_SM100_ALL))
#define HAS_TC 1
#else
#define HAS_TC 0
#endif

#define WSCALE     64.0f
#define INV_WSCALE 0.015625f

// ---------------------------------------------------------------------------
// Scratch (device globals; allocation is forbidden). TMA sources aligned.
// ---------------------------------------------------------------------------
__device__ float g_featsA[4 * 512 * 4096];
__device__ float g_featsB[4 * 512 * 4096];
__device__ float g_v[4 * 512 * 4096];
__device__ float g_qk[4 * 128 * 4096];
__device__ float g_attn[4 * 4096 * 128];
__device__ float g_bqk[128];
__device__ __align__(128) __half g_xh[4 * 4096 * 2048];
__device__ __align__(128) __half g_fh[4 * 4096 * 512];
__device__ __align__(128) __half g_w1h[9 * 512 * 2048];
__device__ __align__(128) __half g_w2h[9 * 512 * 512];
__device__ __align__(128) __half g_wqkh[128 * 512];
__device__ __align__(128) __half g_wvh[512 * 512];

// ---------------------------------------------------------------------------
// Generic helpers
// ---------------------------------------------------------------------------
__device__ __forceinline__ unsigned smem_u32(const void* p) {
    unsigned a;
    asm("{ .reg .u64 t; cvta.to.shared.u64 t, %1; cvt.u32.u64 %0, t; }"
        : "=r"(a) : "l"(p));
    return a;
}
__device__ __forceinline__ unsigned elect_one() {
    unsigned p;
    asm volatile("{ .reg .pred p; elect.sync _|p, 0xFFFFFFFF; selp.b32 %0, 1, 0, p; }"
                 : "=r"(p));
    return p;
}
#define SW128(o) ((o) ^ (((o) >> 3) & 0x70))
__device__ __forceinline__ void mbar_init(unsigned mbar, unsigned cnt) {
    asm volatile("mbarrier.init.shared.b64 [%0], %1;" :: "r"(mbar), "r"(cnt) : "memory");
}
__device__ __forceinline__ void mbar_wait(unsigned mbar, unsigned phase) {
    asm volatile(
        "{\n\t.reg .pred P;\n\t"
        "WL_%=:\n\t"
        "mbarrier.try_wait.parity.acquire.cta.shared::cta.b64 P, [%0], %1, 0x989680;\n\t"
        "@P bra.uni WD_%=;\n\t"
        "bra.uni WL_%=;\n\t"
        "WD_%=:\n\t}"
        :: "r"(mbar), "r"(phase) : "memory");
}
__device__ __forceinline__ void fence_async_shared() {
    asm volatile("fence.proxy.async;" ::: "memory");
}

// ---------------------------------------------------------------------------
// tcgen05 / TMA / cluster helpers (arch-specific pass only)
// ---------------------------------------------------------------------------
#if HAS_TC
static constexpr unsigned long long SMEM_DESC_BASE_SW128 =
    (2ull << 61) | (1ull << 46) | (64ull << 32) | (1ull << 16);
__device__ __forceinline__ unsigned long long make_desc(unsigned addr) {
    return SMEM_DESC_BASE_SW128 | ((unsigned long long)(addr >> 4) & 0x3FFFull);
}
__device__ __forceinline__ void cluster_sync_() {
    asm volatile("barrier.cluster.arrive.aligned;" ::: "memory");
    asm volatile("barrier.cluster.wait.aligned;" ::: "memory");
}
__device__ __forceinline__ void mbar_expect_tx(unsigned mbar, unsigned bytes) {
    asm volatile("mbarrier.arrive.expect_tx.shared.b64 _, [%0], %1;"
                 :: "r"(mbar), "r"(bytes) : "memory");
}
__device__ __forceinline__ void tmem_alloc_cg1(unsigned dst_smem, unsigned ncols) {
    asm volatile("tcgen05.alloc.cta_group::1.sync.aligned.shared::cta.b32 [%0], %1;"
                 :: "r"(dst_smem), "r"(ncols) : "memory");
}
__device__ __forceinline__ void tmem_dealloc_cg1(unsigned tmem, unsigned ncols) {
    asm volatile("tcgen05.dealloc.cta_group::1.sync.aligned.b32 %0, %1;"
                 :: "r"(tmem), "r"(ncols));
}
__device__ __forceinline__ void tmem_alloc_cg2(unsigned dst_smem, unsigned ncols) {
    asm volatile("tcgen05.alloc.cta_group::2.sync.aligned.shared::cta.b32 [%0], %1;"
                 :: "r"(dst_smem), "r"(ncols) : "memory");
}
__device__ __forceinline__ void tmem_dealloc_cg2(unsigned tmem, unsigned ncols) {
    asm volatile("tcgen05.dealloc.cta_group::2.sync.aligned.b32 %0, %1;"
                 :: "r"(tmem), "r"(ncols));
}
__device__ __forceinline__ void tc_relinquish_cg2() {
    asm volatile("tcgen05.relinquish_alloc_permit.cta_group::2.sync.aligned;");
}
__device__ __forceinline__ void tc_commit_cg1(unsigned mbar) {
    asm volatile("tcgen05.commit.cta_group::1.mbarrier::arrive::one.shared::cluster.b64 [%0];"
                 :: "r"(mbar) : "memory");
}
__device__ __forceinline__ void tc_commit_mc_cg2(unsigned mbar, unsigned short mask) {
    asm volatile("tcgen05.commit.cta_group::2.mbarrier::arrive::one.shared::cluster.multicast::cluster.b64 [%0], %1;"
                 :: "r"(mbar), "h"(mask) : "memory");
}
__device__ __forceinline__ void tc_fence_after() {
    asm volatile("tcgen05.fence::after_thread_sync;" ::: "memory");
}
__device__ __forceinline__ void tc_wait_ld() {
    asm volatile("tcgen05.wait::ld.sync.aligned;" ::: "memory");
}
__device__ __forceinline__ void mma_cg1(unsigned d, unsigned long long ad,
                                        unsigned long long bd, unsigned idesc, unsigned en) {
    asm volatile(
        "{\n\t.reg .pred p;\n\tsetp.ne.u32 p, %4, 0;\n\t"
        "tcgen05.mma.cta_group::1.kind::f16 [%0], %1, %2, %3, {%5, %5, %5, %5}, p;\n\t}"
        :: "r"(d), "l"(ad), "l"(bd), "r"(idesc), "r"(en), "r"(0u) : "memory");
}
__device__ __forceinline__ void mma_cg2(unsigned d, unsigned long long ad,
                                        unsigned long long bd, unsigned idesc, unsigned en) {
    asm volatile(
        "{\n\t.reg .pred p;\n\tsetp.ne.u32 p, %4, 0;\n\t"
        "tcgen05.mma.cta_group::2.kind::f16 [%0], %1, %2, %3, "
        "{%5, %5, %5, %5, %5, %5, %5, %5}, p;\n\t}"
        :: "r"(d), "l"(ad), "l"(bd), "r"(idesc), "r"(en), "r"(0u) : "memory");
}
__device__ __forceinline__ void tmem_ld32(unsigned* r, unsigned addr) {
    asm volatile(
        "tcgen05.ld.sync.aligned.32x32b.x32.b32 "
        "{%0, %1, %2, %3, %4, %5, %6, %7, "
        " %8, %9, %10, %11, %12, %13, %14, %15, "
        " %16, %17, %18, %19, %20, %21, %22, %23, "
        " %24, %25, %26, %27, %28, %29, %30, %31}, [%32];"
        : "=r"(r[0]),  "=r"(r[1]),  "=r"(r[2]),  "=r"(r[3]),
          "=r"(r[4]),  "=r"(r[5]),  "=r"(r[6]),  "=r"(r[7]),
          "=r"(r[8]),  "=r"(r[9]),  "=r"(r[10]), "=r"(r[11]),
          "=r"(r[12]), "=r"(r[13]), "=r"(r[14]), "=r"(r[15]),
          "=r"(r[16]), "=r"(r[17]), "=r"(r[18]), "=r"(r[19]),
          "=r"(r[20]), "=r"(r[21]), "=r"(r[22]), "=r"(r[23]),
          "=r"(r[24]), "=r"(r[25]), "=r"(r[26]), "=r"(r[27]),
          "=r"(r[28]), "=r"(r[29]), "=r"(r[30]), "=r"(r[31])
        : "r"(addr));
}
__device__ __forceinline__ void tma3d_cg2(unsigned dst, const CUtensorMap* m,
                                          int x, int y, int z, unsigned bar) {
    asm volatile(
        "{\n\t.reg .b32 lb;\n\tand.b32 lb, %5, 0xFEFFFFFF;\n\t"
        "cp.async.bulk.tensor.3d.cta_group::2.shared::cluster.global"
        ".tile.mbarrier::complete_tx::bytes [%0], [%1, {%2, %3, %4}], [lb];\n\t}"
        :: "r"(dst), "l"(m), "r"(x), "r"(y), "r"(z), "r"(bar) : "memory");
}
__device__ __forceinline__ void tma4d_cg2(unsigned dst, const CUtensorMap* m,
                                          int x, int y, int z, int w, unsigned bar) {
    asm volatile(
        "{\n\t.reg .b32 lb;\n\tand.b32 lb, %6, 0xFEFFFFFF;\n\t"
        "cp.async.bulk.tensor.4d.cta_group::2.shared::cluster.global"
        ".tile.mbarrier::complete_tx::bytes [%0], [%1, {%2, %3, %4, %5}], [lb];\n\t}"
        :: "r"(dst), "l"(m), "r"(x), "r"(y), "r"(z), "r"(w), "r"(bar) : "memory");
}
#endif

// ---------------------------------------------------------------------------
// Prep kernels (single fp16 plane)
// ---------------------------------------------------------------------------
__global__ void prep_act(const float* __restrict__ src,
                         __half* __restrict__ dh, int CIN) {
    __shared__ float t[32][33];
    const int b = blockIdx.z, ct = blockIdx.y * 32, pt = blockIdx.x * 32;
    const int tx = threadIdx.x, ty = threadIdx.y;
    for (int i = ty; i < 32; i += 8)
        t[i][tx] = src[((size_t)(b * CIN + ct + i)) * HW_ + pt + tx];
    __syncthreads();
    for (int i = ty; i < 32; i += 8) {
        size_t o = ((size_t)(b * HW_ + pt + i)) * CIN + ct + tx;
        dh[o] = __float2half(t[tx][i]);
    }
}

__global__ void prep_wconv(const float* __restrict__ W,
                           __half* __restrict__ dh, int M, int CIN) {
    int idx = blockIdx.x * 256 + threadIdx.x;
    if (idx >= M * CIN) return;
#pragma unroll
    for (int tap = 0; tap < 9; tap++) {
        size_t o = (size_t)tap * M * CIN + idx;
        dh[o] = __float2half(W[(size_t)idx * 9 + tap] * WSCALE);
    }
}

__global__ void prep_wlin(const float* __restrict__ W,
                          __half* __restrict__ dh, int n) {
    int i = blockIdx.x * 256 + threadIdx.x;
    if (i >= n) return;
    dh[i] = __float2half(W[i] * WSCALE);
}

__global__ void prep_wqk(const float* __restrict__ qw, const float* __restrict__ kw,
                         const float* __restrict__ qb, const float* __restrict__ kb,
                         __half* __restrict__ dh, float* __restrict__ bias) {
    int i = blockIdx.x * 256 + threadIdx.x;
    if (i < 128) bias[i] = (i < 64) ? qb[i] : kb[i - 64];
    if (i >= 128 * 512) return;
    float x = ((i < 64 * 512) ? qw[i] : kw[i - 64 * 512]) * WSCALE;
    dh[i] = __float2half(x);
}

// ---------------------------------------------------------------------------
// cg2 implicit-conv GEMM, TMA pipeline, warp-specialized control,
// fp16 single-plane (16 MMA dispatches / chunk).
// ---------------------------------------------------------------------------
template<int CIN, int TAPS, int EPI>
__global__ void __launch_bounds__(256, 1) __cluster_dims__(2, 1, 1)
mma_conv_tma(const __grid_constant__ CUtensorMap tW,
             const __grid_constant__ CUtensorMap tX,
             const float* __restrict__ e0, const float* __restrict__ e1,
             const float* __restrict__ e2, const float* __restrict__ e3,
             float* __restrict__ Y, int Mtot)
{
#if HAS_TC
    constexpr int NCHUNK = TAPS * (CIN / 64);
    constexpr int NST   = 3;
    constexpr int A_0   = 0;          // 128 rows x 128B = 16KB
    constexpr int B_0   = 16384;      // 4 x 64 rows x 128B = 32KB
    constexpr int STAGE = 49152;
    constexpr unsigned IDESC2 = (1u << 4) | (16u << 17) | (16u << 24);

    extern __shared__ char dyn_smem[];
    __shared__ __align__(8) unsigned long long s_full[NST];
    __shared__ __align__(8) unsigned long long s_done[NST];
    __shared__ unsigned s_tmem[1];

    char* sm = (char*)((((uintptr_t)dyn_smem) + 1023) & ~(uintptr_t)1023);
    const unsigned sbase = smem_u32(sm);

    const int tid  = threadIdx.x;
    const int wid  = tid >> 5;
    const int lane = tid & 31;
    const unsigned rank = blockIdx.x & 1;
    const int m_base = (blockIdx.x >> 1) * 256;
    const int n_base = blockIdx.y * 512;
    const int bb    = n_base >> 12;
    const int sp00  = n_base & 4095;
    const int hrow0 = sp00 >> 6;

    if (wid == 0) tmem_alloc_cg2(smem_u32(&s_tmem[0]), 512);
    if (tid == 0) {
#pragma unroll
        for (int s = 0; s < NST; ++s) {
            mbar_init(smem_u32(&s_full[s]), 1);
            mbar_init(smem_u32(&s_done[s]), 1);
        }
    }
    __syncthreads();
    unsigned tmem;
    asm volatile("ld.shared.b32 %0, [%1];" : "=r"(tmem) : "r"(smem_u32(&s_tmem[0])));
    unsigned fullb[NST], doneb[NST];
#pragma unroll
    for (int s = 0; s < NST; ++s) {
        fullb[s] = smem_u32(&s_full[s]);
        doneb[s] = smem_u32(&s_done[s]);
    }
    cluster_sync_();

    if (tid == 0) {
        // ---- producer ----
        int dph[NST] = {0, 0, 0};
        for (int i = 0; i < NCHUNK; ++i) {
            const int s = i % NST;
            if (i >= NST) { mbar_wait(doneb[s], dph[s]); dph[s] ^= 1; }
            if (rank == 0) mbar_expect_tx(fullb[s], 2 * STAGE);

            const int tap = (TAPS == 1) ? 0 : i / (CIN / 64);
            const int cb  = (TAPS == 1) ? i * 64 : (i % (CIN / 64)) * 64;
            const int dh  = (TAPS == 9) ? (tap / 3 - 1) : 0;
            const int dw  = (TAPS == 9) ? (tap % 3 - 1) : 0;
            const unsigned stg = sbase + s * STAGE;

            tma3d_cg2(stg + A_0, &tW, cb, m_base + (int)rank * 128, tap, fullb[s]);
#pragma unroll
            for (int t = 0; t < 4; ++t)
                tma4d_cg2(stg + B_0 + t * 8192, &tX,
                          cb, dw, hrow0 + 2 * t + (int)rank + dh, bb, fullb[s]);
        }
        const int sl = (NCHUNK - 1) % NST;
        mbar_wait(doneb[sl], dph[sl]);
    }
    if (rank == 0 && tid == 32) {
        // ---- consumer ----
        int fph[NST] = {0, 0, 0};
        for (int i = 0; i < NCHUNK; ++i) {
            const int s = i % NST;
            mbar_wait(fullb[s], fph[s]); fph[s] ^= 1;
            const unsigned sg = sbase + s * STAGE;
            unsigned long long dA = make_desc(sg + A_0);
#pragma unroll
            for (int t = 0; t < 4; ++t) {
                unsigned d = tmem + t * 128;
                unsigned long long dB = make_desc(sg + B_0 + t * 8192);
#pragma unroll
                for (int kk = 0; kk < 4; ++kk) {
                    unsigned en0 = (i > 0 || kk > 0) ? 1u : 0u;
                    mma_cg2(d, dA + kk * 2, dB + kk * 2, IDESC2, en0);
                }
            }
            tc_commit_mc_cg2(doneb[s], 0x3);
        }
    }
    __syncthreads();
    tc_fence_after();

    // --- epilogue ---
    {
        const int wg = wid >> 2;
        const int mg = m_base + (int)rank * 128 + (wid & 3) * 32 + lane;
        float sc, sh;
        if (EPI == 1) {
            float tt = e0[mg] * rsqrtf(e3[mg] + 1e-5f);
            sc = tt * INV_WSCALE;
            sh = e1[mg] - e2[mg] * tt;
        } else {
            sc = INV_WSCALE;
            sh = e0[mg];
        }
        float* yrow = Y + ((size_t)(bb * Mtot + mg)) * HW_ + sp00;
#pragma unroll
        for (int ti = 0; ti < 2; ++ti) {
            int t = wg * 2 + ti;
#pragma unroll
            for (int cb4 = 0; cb4 < 4; ++cb4) {
                unsigned r[32];
                tmem_ld32(r, tmem + t * 128 + cb4 * 32);
                tc_wait_ld();
#pragma unroll
                for (int j = 0; j < 32; j += 4) {
                    float4 v;
                    v.x = fmaf(__uint_as_float(r[j + 0]), sc, sh);
                    v.y = fmaf(__uint_as_float(r[j + 1]), sc, sh);
                    v.z = fmaf(__uint_as_float(r[j + 2]), sc, sh);
                    v.w = fmaf(__uint_as_float(r[j + 3]), sc, sh);
                    if (EPI == 1) {
                        v.x = fmaxf(v.x, 0.f); v.y = fmaxf(v.y, 0.f);
                        v.z = fmaxf(v.z, 0.f); v.w = fmaxf(v.w, 0.f);
                    }
                    *(float4*)(yrow + t * 128 + cb4 * 32 + j) = v;
                }
            }
        }
    }
    __syncthreads();
    if (wid == 0) {
        tc_relinquish_cg2();
        tmem_dealloc_cg2(tmem, 512);
    }
    cluster_sync_();
#endif
}

// ---------------------------------------------------------------------------
// cg1 GEMM for the stacked q/k projection (M=128), fp16 single-plane
// ---------------------------------------------------------------------------
template<int CIN>
__global__ void __launch_bounds__(256, 1)
mma_proj_cg1(const __half* __restrict__ Wh, const __half* __restrict__ Xh,
             const float* __restrict__ e0, float* __restrict__ Y, int Mtot)
{
#if HAS_TC
    constexpr int A_BYTES = 128 * 128;
    constexpr int B_BYTES = 128 * 128;
    constexpr int STAGE   = A_BYTES + B_BYTES;   // 32KB
    constexpr int NCHUNK  = CIN / 64;
    constexpr unsigned IDESC = (1u << 4) | (16u << 17) | (8u << 24);

    extern __shared__ char dyn_smem[];
    __shared__ __align__(8) unsigned long long s_mbar[2];
    __shared__ unsigned s_tmem[1];

    char* sm = (char*)((((uintptr_t)dyn_smem) + 1023) & ~(uintptr_t)1023);
    const unsigned sbase = smem_u32(sm);
    const int tid = threadIdx.x;
    const int wid = tid >> 5;
    const int lane = tid & 31;

    if (wid == 0) tmem_alloc_cg1(smem_u32(&s_tmem[0]), 256);
    if (tid == 0) { mbar_init(smem_u32(&s_mbar[0]), 1); mbar_init(smem_u32(&s_mbar[1]), 1); }
    __syncthreads();
    unsigned tmem;
    asm volatile("ld.shared.b32 %0, [%1];" : "=r"(tmem) : "r"(smem_u32(&s_tmem[0])));
    const unsigned mbar[2] = { smem_u32(&s_mbar[0]), smem_u32(&s_mbar[1]) };

    const int n_base = blockIdx.y * 128;
    const int bb  = n_base >> 12;
    const int sp0 = n_base & 4095;
    int ph[2] = {0, 0};

    for (int chunk = 0; chunk < NCHUNK; ++chunk) {
        const int s  = chunk & 1;
        const int cb = chunk * 64;
        if (chunk >= 2) { mbar_wait(mbar[s], ph[s]); ph[s] ^= 1; }

        char* aH = sm + s * STAGE;
        char* bH = aH + A_BYTES;
#pragma unroll
        for (int u = 0; u < 4; ++u) {
            int l = u * 256 + tid;
            int row = l >> 3, c16 = l & 7;
            size_t go = (size_t)row * CIN + cb + c16 * 8;
            unsigned so = SW128((unsigned)(row * 128 + c16 * 16));
            *(uint4*)(aH + so) = *(const uint4*)(Wh + go);
        }
#pragma unroll
        for (int u = 0; u < 4; ++u) {
            int l = u * 256 + tid;
            int row = l >> 3, c16 = l & 7;
            size_t go = ((size_t)(bb * HW_ + sp0 + row)) * CIN + cb + c16 * 8;
            unsigned so = SW128((unsigned)(row * 128 + c16 * 16));
            *(uint4*)(bH + so) = *(const uint4*)(Xh + go);
        }
        fence_async_shared();
        __syncthreads();

        if (wid == 0 && elect_one()) {
            unsigned long long dA = make_desc(sbase + s * STAGE);
            unsigned long long dB = make_desc(sbase + s * STAGE + A_BYTES);
#pragma unroll
            for (int kk = 0; kk < 4; ++kk) {
                unsigned en0 = (chunk > 0 || kk > 0) ? 1u : 0u;
                mma_cg1(tmem, dA + kk * 2, dB + kk * 2, IDESC, en0);
            }
            tc_commit_cg1(mbar[s]);
        }
    }
    {
        int s0 = (NCHUNK - 2) & 1, s1 = (NCHUNK - 1) & 1;
        mbar_wait(mbar[s0], ph[s0]); ph[s0] ^= 1;
        mbar_wait(mbar[s1], ph[s1]); ph[s1] ^= 1;
    }
    tc_fence_after();

    if (wid < 4) {
        const int mg = wid * 32 + lane;
        float sh = e0[mg];
        float* yrow = Y + ((size_t)(bb * Mtot + mg)) * HW_ + sp0;
#pragma unroll
        for (int cb4 = 0; cb4 < 4; ++cb4) {
            unsigned r[32];
            tmem_ld32(r, tmem + cb4 * 32);
            tc_wait_ld();
#pragma unroll
            for (int j = 0; j < 32; j += 4) {
                float4 v;
                v.x = fmaf(__uint_as_float(r[j + 0]), INV_WSCALE, sh);
                v.y = fmaf(__uint_as_float(r[j + 1]), INV_WSCALE, sh);
                v.z = fmaf(__uint_as_float(r[j + 2]), INV_WSCALE, sh);
                v.w = fmaf(__uint_as_float(r[j + 3]), INV_WSCALE, sh);
                *(float4*)(yrow + cb4 * 32 + j) = v;
            }
        }
    }
    __syncthreads();
    if (wid == 0) tmem_dealloc_cg1(tmem, 256);
#endif
}

// ---------------------------------------------------------------------------
// CCA kernels — register-tiled 4x4 outer products (proven R11/R12)
// ---------------------------------------------------------------------------
__global__ void __launch_bounds__(256) energyH_kernel(
    const float* __restrict__ qk, float* __restrict__ attn)
{
    const int w = blockIdx.x, b = blockIdx.y;
    __shared__ float Qs[64][65];
    __shared__ float Ks[64][65];
    const int tid = threadIdx.x;
    for (int l = tid; l < 4096; l += 256) {
        int c = l >> 6, h = l & 63;
        Qs[c][h] = qk[((size_t)(b * 128 + c)) * HW_ + h * 64 + w];
        Ks[c][h] = qk[((size_t)(b * 128 + 64 + c)) * HW_ + h * 64 + w];
    }
    __syncthreads();
    const int i4 = (tid & 15) * 4, h4 = (tid >> 4) * 4;
    float acc[4][4];
#pragma unroll
    for (int a = 0; a < 4; a++)
#pragma unroll
        for (int d = 0; d < 4; d++) acc[a][d] = 0.f;
    for (int c = 0; c < 64; c++) {
        float q0 = Qs[c][h4], q1 = Qs[c][h4 + 1], q2 = Qs[c][h4 + 2], q3 = Qs[c][h4 + 3];
        float k0 = Ks[c][i4], k1 = Ks[c][i4 + 1], k2 = Ks[c][i4 + 2], k3 = Ks[c][i4 + 3];
        acc[0][0] += q0 * k0; acc[0][1] += q0 * k1; acc[0][2] += q0 * k2; acc[0][3] += q0 * k3;
        acc[1][0] += q1 * k0; acc[1][1] += q1 * k1; acc[1][2] += q1 * k2; acc[1][3] += q1 * k3;
        acc[2][0] += q2 * k0; acc[2][1] += q2 * k1; acc[2][2] += q2 * k2; acc[2][3] += q2 * k3;
        acc[3][0] += q3 * k0; acc[3][1] += q3 * k1; acc[3][2] += q3 * k2; acc[3][3] += q3 * k3;
    }
#pragma unroll
    for (int a = 0; a < 4; a++) {
        int h = h4 + a;
        float4 o;
        o.x = acc[a][0] + ((i4 + 0 == h) ? -1000000000.0f : 0.f);
        o.y = acc[a][1] + ((i4 + 1 == h) ? -1000000000.0f : 0.f);
        o.z = acc[a][2] + ((i4 + 2 == h) ? -1000000000.0f : 0.f);
        o.w = acc[a][3] + ((i4 + 3 == h) ? -1000000000.0f : 0.f);
        *(float4*)(attn + (size_t)(((b * 64 + h) * 64 + w)) * 128 + i4) = o;
    }
}

__global__ void __launch_bounds__(256) energyW_kernel(
    const float* __restrict__ qk, float* __restrict__ attn)
{
    const int h = blockIdx.x, b = blockIdx.y;
    __shared__ float Qs[64][65];
    __shared__ float Ks[64][65];
    const int tid = threadIdx.x;
    for (int l = tid; l < 4096; l += 256) {
        int c = l >> 6, w = l & 63;
        Qs[c][w] = qk[((size_t)(b * 128 + c)) * HW_ + h * 64 + w];
        Ks[c][w] = qk[((size_t)(b * 128 + 64 + c)) * HW_ + h * 64 + w];
    }
    __syncthreads();
    const int j4 = (tid & 15) * 4, w4 = (tid >> 4) * 4;
    float acc[4][4];
#pragma unroll
    for (int a = 0; a < 4; a++)
#pragma unroll
        for (int d = 0; d < 4; d++) acc[a][d] = 0.f;
    for (int c = 0; c < 64; c++) {
        float q0 = Qs[c][w4], q1 = Qs[c][w4 + 1], q2 = Qs[c][w4 + 2], q3 = Qs[c][w4 + 3];
        float k0 = Ks[c][j4], k1 = Ks[c][j4 + 1], k2 = Ks[c][j4 + 2], k3 = Ks[c][j4 + 3];
        acc[0][0] += q0 * k0; acc[0][1] += q0 * k1; acc[0][2] += q0 * k2; acc[0][3] += q0 * k3;
        acc[1][0] += q1 * k0; acc[1][1] += q1 * k1; acc[1][2] += q1 * k2; acc[1][3] += q1 * k3;
        acc[2][0] += q2 * k0; acc[2][1] += q2 * k1; acc[2][2] += q2 * k2; acc[2][3] += q2 * k3;
        acc[3][0] += q3 * k0; acc[3][1] += q3 * k1; acc[3][2] += q3 * k2; acc[3][3] += q3 * k3;
    }
#pragma unroll
    for (int a = 0; a < 4; a++) {
        int w = w4 + a;
        float4 o = make_float4(acc[a][0], acc[a][1], acc[a][2], acc[a][3]);
        *(float4*)(attn + (size_t)(((b * 64 + h) * 64 + w)) * 128 + 64 + j4) = o;
    }
}

__global__ void __launch_bounds__(256) softmax_kernel(float* __restrict__ attn)
{
    int gw = (blockIdx.x * blockDim.x + threadIdx.x) >> 5;
    if (gw >= NPIX_) return;
    int lane = threadIdx.x & 31;
    float* row = attn + (size_t)gw * 128;
    float v0 = row[lane], v1 = row[lane + 32], v2 = row[lane + 64], v3 = row[lane + 96];
    float mx = fmaxf(fmaxf(v0, v1), fmaxf(v2, v3));
#pragma unroll
    for (int o = 16; o > 0; o >>= 1) mx = fmaxf(mx, __shfl_xor_sync(0xffffffffu, mx, o));
    v0 = expf(v0 - mx); v1 = expf(v1 - mx); v2 = expf(v2 - mx); v3 = expf(v3 - mx);
    float s = v0 + v1 + v2 + v3;
#pragma unroll
    for (int o = 16; o > 0; o >>= 1) s += __shfl_xor_sync(0xffffffffu, s, o);
    float inv = 1.0f / s;
    row[lane] = v0 * inv; row[lane + 32] = v1 * inv;
    row[lane + 64] = v2 * inv; row[lane + 96] = v3 * inv;
}

__global__ void __launch_bounds__(256) aggH_kernel(
    const float* __restrict__ v, const float* __restrict__ attn,
    const float* __restrict__ fin, float* __restrict__ fout,
    const float* __restrict__ gptr)
{
    const int w = blockIdx.x, b = blockIdx.y, cbk = blockIdx.z * 64;
    __shared__ float Vs[64][65];
    __shared__ float Am[64][65];
    const int tid = threadIdx.x;
    for (int l = tid; l < 4096; l += 256) {
        int c = l >> 6, i = l & 63;
        Vs[c][i] = v[(size_t)((b * 512 + cbk + c) * 64 + i) * 64 + w];
    }
    for (int l = tid; l < 4096; l += 256) {
        int h = l >> 6, i = l & 63;
        Am[h][i] = attn[(size_t)(((b * 64 + h) * 64 + w)) * 128 + i];
    }
    __syncthreads();
    const int c4 = (tid & 15) * 4, h4 = (tid >> 4) * 4;
    float acc[4][4];
#pragma unroll
    for (int a = 0; a < 4; a++)
#pragma unroll
        for (int d = 0; d < 4; d++) acc[a][d] = 0.f;
    for (int i = 0; i < 64; i++) {
        float v0 = Vs[c4][i], v1 = Vs[c4 + 1][i], v2 = Vs[c4 + 2][i], v3 = Vs[c4 + 3][i];
        float a0 = Am[h4][i], a1 = Am[h4 + 1][i], a2 = Am[h4 + 2][i], a3 = Am[h4 + 3][i];
        acc[0][0] += v0 * a0; acc[0][1] += v0 * a1; acc[0][2] += v0 * a2; acc[0][3] += v0 * a3;
        acc[1][0] += v1 * a0; acc[1][1] += v1 * a1; acc[1][2] += v1 * a2; acc[1][3] += v1 * a3;
        acc[2][0] += v2 * a0; acc[2][1] += v2 * a1; acc[2][2] += v2 * a2; acc[2][3] += v2 * a3;
        acc[3][0] += v3 * a0; acc[3][1] += v3 * a1; acc[3][2] += v3 * a2; acc[3][3] += v3 * a3;
    }
    const float g = *gptr;
#pragma unroll
    for (int a = 0; a < 4; a++) {
#pragma unroll
        for (int d = 0; d < 4; d++) {
            int h = h4 + d;
            size_t idx = (size_t)((b * 512 + cbk + c4 + a) * 64 + h) * 64 + w;
            fout[idx] = fin[idx] + g * acc[a][d];
        }
    }
}

// aggW: final residual add + fused NHWC fp16 emit (feeds next GEMM stage)
__global__ void __launch_bounds__(256) aggW_kernel(
    const float* __restrict__ v, const float* __restrict__ attn,
    float* __restrict__ fout, const float* __restrict__ gptr,
    __half* __restrict__ fh)
{
    const int h = blockIdx.x, b = blockIdx.y, cbk = blockIdx.z * 64;
    __shared__ float Vs[64][65];
    __shared__ float Am[64][65];
    const int tid = threadIdx.x;
    for (int l = tid; l < 4096; l += 256) {
        int c = l >> 6, j = l & 63;
        Vs[c][j] = v[(size_t)((b * 512 + cbk + c) * 64 + h) * 64 + j];
    }
    for (int l = tid; l < 4096; l += 256) {
        int w = l >> 6, j = l & 63;
        Am[w][j] = attn[(size_t)(((b * 64 + h) * 64 + w)) * 128 + 64 + j];
    }
    __syncthreads();
    const int c4 = (tid & 15) * 4, w4 = (tid >> 4) * 4;
    float acc[4][4];
#pragma unroll
    for (int a = 0; a < 4; a++)
#pragma unroll
        for (int d = 0; d < 4; d++) acc[a][d] = 0.f;
    for (int j = 0; j < 64; j++) {
        float v0 = Vs[c4][j], v1 = Vs[c4 + 1][j], v2 = Vs[c4 + 2][j], v3 = Vs[c4 + 3][j];
        float a0 = Am[w4][j], a1 = Am[w4 + 1][j], a2 = Am[w4 + 2][j], a3 = Am[w4 + 3][j];
        acc[0][0] += v0 * a0; acc[0][1] += v0 * a1; acc[0][2] += v0 * a2; acc[0][3] += v0 * a3;
        acc[1][0] += v1 * a0; acc[1][1] += v1 * a1; acc[1][2] += v1 * a2; acc[1][3] += v1 * a3;
        acc[2][0] += v2 * a0; acc[2][1] += v2 * a1; acc[2][2] += v2 * a2; acc[2][3] += v2 * a3;
        acc[3][0] += v3 * a0; acc[3][1] += v3 * a1; acc[3][2] += v3 * a2; acc[3][3] += v3 * a3;
    }
    const float g = *gptr;
#pragma unroll
    for (int d = 0; d < 4; d++) {
        int w = w4 + d;
        float val[4];
#pragma unroll
        for (int a = 0; a < 4; a++) {
            size_t idx = (size_t)((b * 512 + cbk + c4 + a) * 64 + h) * 64 + w;
            val[a] = fout[idx] + g * acc[a][d];
            fout[idx] = val[a];
        }
        // NHWC fp16: consecutive channels contiguous -> one 8B store
        __half2 p0 = __floats2half2_rn(val[0], val[1]);
        __half2 p1 = __floats2half2_rn(val[2], val[3]);
        size_t o = ((size_t)(b * HW_ + h * 64 + w)) * 512 + cbk + c4;
        *(__half2*)(fh + o)     = p0;
        *(__half2*)(fh + o + 2) = p1;
    }
}

// ---------------------------------------------------------------------------
// Host: tensor-map encoding via runtime driver-entry-point
// ---------------------------------------------------------------------------
typedef CUresult (*EncodeTiledFn)(
    CUtensorMap*, CUtensorMapDataType, cuuint32_t, void*,
    const cuuint64_t*, const cuuint64_t*, const cuuint32_t*, const cuuint32_t*,
    CUtensorMapInterleave, CUtensorMapSwizzle, CUtensorMapL2promotion,
    CUtensorMapFloatOOBfill);

static EncodeTiledFn get_encode_fn() {
    static EncodeTiledFn fn = nullptr;
    if (!fn) {
        void* p = nullptr;
        cudaDriverEntryPointQueryResult st;
        cudaGetDriverEntryPointByVersion("cuTensorMapEncodeTiled", &p, 12000,
                                         cudaEnableDefault, &st);
        fn = (EncodeTiledFn)p;
    }
    return fn;
}

static void encode_w3d(CUtensorMap* tm, void* ptr,
                       unsigned long long cin, unsigned long long m,
                       unsigned long long taps) {
    cuuint64_t dims[3] = {cin, m, taps};
    cuuint64_t strides[2] = {cin * 2, cin * m * 2};
    cuuint32_t box[3] = {64, 128, 1};
    cuuint32_t es[3] = {1, 1, 1};
    get_encode_fn()(tm, CU_TENSOR_MAP_DATA_TYPE_FLOAT16, 3, ptr, dims, strides,
                    box, es, CU_TENSOR_MAP_INTERLEAVE_NONE,
                    CU_TENSOR_MAP_SWIZZLE_128B,
                    CU_TENSOR_MAP_L2_PROMOTION_L2_128B,
                    CU_TENSOR_MAP_FLOAT_OOB_FILL_NONE);
}

static void encode_x4d(CUtensorMap* tm, void* ptr, unsigned long long C) {
    cuuint64_t dims[4] = {C, 64, 64, 4};
    cuuint64_t strides[3] = {C * 2, 64 * C * 2, 64ull * 64 * C * 2};
    cuuint32_t box[4] = {64, 64, 1, 1};
    cuuint32_t es[4] = {1, 1, 1, 1};
    get_encode_fn()(tm, CU_TENSOR_MAP_DATA_TYPE_FLOAT16, 4, ptr, dims, strides,
                    box, es, CU_TENSOR_MAP_INTERLEAVE_NONE,
                    CU_TENSOR_MAP_SWIZZLE_128B,
                    CU_TENSOR_MAP_L2_PROMOTION_L2_128B,
                    CU_TENSOR_MAP_FLOAT_OOB_FILL_NONE);
}

// ---------------------------------------------------------------------------
// Launch
// ---------------------------------------------------------------------------
extern "C" void kernel_launch(void* const* d_in, const int* in_sizes, int n_in,
                              void* d_out, int out_size)
{
    const float* x     = (const float*)d_in[0];
    const float* c1w   = (const float*)d_in[1];
    const float* bn1g  = (const float*)d_in[2];
    const float* bn1b  = (const float*)d_in[3];
    const float* bn1m  = (const float*)d_in[4];
    const float* bn1v  = (const float*)d_in[5];
    const float* qw    = (const float*)d_in[6];
    const float* qb    = (const float*)d_in[7];
    const float* kw    = (const float*)d_in[8];
    const float* kb    = (const float*)d_in[9];
    const float* vw    = (const float*)d_in[10];
    const float* vb    = (const float*)d_in[11];
    const float* gamma = (const float*)d_in[12];
    const float* c2w   = (const float*)d_in[13];
    const float* bn2g  = (const float*)d_in[14];
    const float* bn2b  = (const float*)d_in[15];
    const float* bn2m  = (const float*)d_in[16];
    const float* bn2v  = (const float*)d_in[17];
    float* out = (float*)d_out;

    float *fA, *fB, *gv, *gqk, *gat, *gbqk;
    __half *xh, *fh, *w1h, *w2h, *wqkh, *wvh;
    cudaGetSymbolAddress((void**)&fA, g_featsA);
    cudaGetSymbolAddress((void**)&fB, g_featsB);
    cudaGetSymbolAddress((void**)&gv, g_v);
    cudaGetSymbolAddress((void**)&gqk, g_qk);
    cudaGetSymbolAddress((void**)&gat, g_attn);
    cudaGetSymbolAddress((void**)&gbqk, g_bqk);
    cudaGetSymbolAddress((void**)&xh, g_xh);
    cudaGetSymbolAddress((void**)&fh, g_fh);
    cudaGetSymbolAddress((void**)&w1h, g_w1h);
    cudaGetSymbolAddress((void**)&w2h, g_w2h);
    cudaGetSymbolAddress((void**)&wqkh, g_wqkh);
    cudaGetSymbolAddress((void**)&wvh, g_wvh);

    static CUtensorMap tW1, tW2, tWv, tXh, tFh;
    encode_w3d(&tW1, w1h, 2048, 512, 9);
    encode_w3d(&tW2, w2h, 512, 512, 9);
    encode_w3d(&tWv, wvh, 512, 512, 1);
    encode_x4d(&tXh, xh, 2048);
    encode_x4d(&tFh, fh, 512);

    const int SMEM_TMA = 3 * 49152 + 1024;   // 148480
    const int SMEM_P1  = 2 * 32768 + 1024;   //  66560
    cudaFuncSetAttribute(mma_conv_tma<2048, 9, 1>, cudaFuncAttributeMaxDynamicSharedMemorySize, SMEM_TMA);
    cudaFuncSetAttribute(mma_conv_tma<512, 9, 1>,  cudaFuncAttributeMaxDynamicSharedMemorySize, SMEM_TMA);
    cudaFuncSetAttribute(mma_conv_tma<512, 1, 0>,  cudaFuncAttributeMaxDynamicSharedMemorySize, SMEM_TMA);
    cudaFuncSetAttribute(mma_proj_cg1<512>,        cudaFuncAttributeMaxDynamicSharedMemorySize, SMEM_P1);

    // ncu captures OUR launch index 3 -> conv1 stays there
    prep_wconv<<<(512 * 2048 + 255) / 256, 256>>>(c1w, w1h, 512, 2048);          // 0
    prep_act<<<dim3(128, 64, 4), dim3(32, 8)>>>(x, xh, 2048);                    // 1
    prep_wqk<<<256, 256>>>(qw, kw, qb, kb, wqkh, gbqk);                          // 2
    mma_conv_tma<2048, 9, 1><<<dim3(4, 32), 256, SMEM_TMA>>>(                    // 3: conv1
        tW1, tXh, bn1g, bn1b, bn1m, bn1v, fA, 512);
    prep_wlin<<<(512 * 512 + 255) / 256, 256>>>(vw, wvh, 512 * 512);             // 4
    prep_wconv<<<(512 * 512 + 255) / 256, 256>>>(c2w, w2h, 512, 512);            // 5

    // --- 2x criss-cross attention ---
    float* cur = fA;
    float* nxt = fB;
    for (int it = 0; it < 2; ++it) {
        if (it == 0)  // conv1 output -> fh; later iterations: aggW fuses the emit
            prep_act<<<dim3(128, 16, 4), dim3(32, 8)>>>(cur, fh, 512);
        mma_proj_cg1<512><<<dim3(1, 128), 256, SMEM_P1>>>(
            wqkh, fh, gbqk, gqk, 128);
        mma_conv_tma<512, 1, 0><<<dim3(4, 32), 256, SMEM_TMA>>>(
            tWv, tFh, vb, nullptr, nullptr, nullptr, gv, 512);
        energyH_kernel<<<dim3(64, 4), 256>>>(gqk, gat);
        energyW_kernel<<<dim3(64, 4), 256>>>(gqk, gat);
        softmax_kernel<<<NPIX_ / 8, 256>>>(gat);
        aggH_kernel<<<dim3(64, 4, 8), 256>>>(gv, gat, cur, nxt, gamma);
        aggW_kernel<<<dim3(64, 4, 8), 256>>>(gv, gat, nxt, gamma, fh);
        float* tmp = cur; cur = nxt; nxt = tmp;
    }

    // --- conv2 + BN + ReLU (reads fh emitted by the last aggW) ---
    mma_conv_tma<512, 9, 1><<<dim3(4, 32), 256, SMEM_TMA>>>(
        tW2, tFh, bn2g, bn2b, bn2m, bn2v, out, 512);
}

// round 14
// speedup vs baseline: 1.7444x; 1.2456x over previous
#include <cuda_runtime.h>
#include <cuda.h>
#include <cuda_fp16.h>
#include <math.h>
#include <stdint.h>

#define HW_   4096
#define NPIX_ 16384

#if defined(__CUDA_ARCH__) && (defined(__CUDA_ARCH_FEAT_SM103_ALL) || defined(__CUDA_ARCH_FEAT_SM100_ALL))
#define HAS_TC 1
#else
#define HAS_TC 0
#endif

#define WSCALE     64.0f
#define INV_WSCALE 0.015625f

// ---------------------------------------------------------------------------
// Scratch (device globals; allocation is forbidden). TMA sources aligned.
// ---------------------------------------------------------------------------
__device__ float g_featsA[4 * 512 * 4096];
__device__ float g_featsB[4 * 512 * 4096];
__device__ float g_v[4 * 512 * 4096];
__device__ float g_qk[4 * 128 * 4096];
__device__ float g_attn[4 * 4096 * 128];
__device__ float g_bqk[128];
__device__ __align__(128) __half g_xh[4 * 4096 * 2048];
__device__ __align__(128) __half g_fh[4 * 4096 * 512];
__device__ __align__(128) __half g_w1h[9 * 512 * 2048];
__device__ __align__(128) __half g_w2h[9 * 512 * 512];
__device__ __align__(128) __half g_wqkh[128 * 512];
__device__ __align__(128) __half g_wvh[512 * 512];

// ---------------------------------------------------------------------------
// Generic helpers
// ---------------------------------------------------------------------------
__device__ __forceinline__ unsigned smem_u32(const void* p) {
    unsigned a;
    asm("{ .reg .u64 t; cvta.to.shared.u64 t, %1; cvt.u32.u64 %0, t; }"
        : "=r"(a) : "l"(p));
    return a;
}
__device__ __forceinline__ unsigned elect_one() {
    unsigned p;
    asm volatile("{ .reg .pred p; elect.sync _|p, 0xFFFFFFFF; selp.b32 %0, 1, 0, p; }"
                 : "=r"(p));
    return p;
}
#define SW128(o) ((o) ^ (((o) >> 3) & 0x70))
__device__ __forceinline__ void mbar_init(unsigned mbar, unsigned cnt) {
    asm volatile("mbarrier.init.shared.b64 [%0], %1;" :: "r"(mbar), "r"(cnt) : "memory");
}
__device__ __forceinline__ void mbar_wait(unsigned mbar, unsigned phase) {
    asm volatile(
        "{\n\t.reg .pred P;\n\t"
        "WL_%=:\n\t"
        "mbarrier.try_wait.parity.acquire.cta.shared::cta.b64 P, [%0], %1, 0x989680;\n\t"
        "@P bra.uni WD_%=;\n\t"
        "bra.uni WL_%=;\n\t"
        "WD_%=:\n\t}"
        :: "r"(mbar), "r"(phase) : "memory");
}
__device__ __forceinline__ void fence_async_shared() {
    asm volatile("fence.proxy.async;" ::: "memory");
}

// ---------------------------------------------------------------------------
// tcgen05 / TMA / cluster helpers (arch-specific pass only)
// ---------------------------------------------------------------------------
#if HAS_TC
static constexpr unsigned long long SMEM_DESC_BASE_SW128 =
    (2ull << 61) | (1ull << 46) | (64ull << 32) | (1ull << 16);
__device__ __forceinline__ unsigned long long make_desc(unsigned addr) {
    return SMEM_DESC_BASE_SW128 | ((unsigned long long)(addr >> 4) & 0x3FFFull);
}
__device__ __forceinline__ void cluster_sync_() {
    asm volatile("barrier.cluster.arrive.aligned;" ::: "memory");
    asm volatile("barrier.cluster.wait.aligned;" ::: "memory");
}
__device__ __forceinline__ void mbar_expect_tx(unsigned mbar, unsigned bytes) {
    asm volatile("mbarrier.arrive.expect_tx.shared.b64 _, [%0], %1;"
                 :: "r"(mbar), "r"(bytes) : "memory");
}
__device__ __forceinline__ void tmem_alloc_cg1(unsigned dst_smem, unsigned ncols) {
    asm volatile("tcgen05.alloc.cta_group::1.sync.aligned.shared::cta.b32 [%0], %1;"
                 :: "r"(dst_smem), "r"(ncols) : "memory");
}
__device__ __forceinline__ void tmem_dealloc_cg1(unsigned tmem, unsigned ncols) {
    asm volatile("tcgen05.dealloc.cta_group::1.sync.aligned.b32 %0, %1;"
                 :: "r"(tmem), "r"(ncols));
}
__device__ __forceinline__ void tmem_alloc_cg2(unsigned dst_smem, unsigned ncols) {
    asm volatile("tcgen05.alloc.cta_group::2.sync.aligned.shared::cta.b32 [%0], %1;"
                 :: "r"(dst_smem), "r"(ncols) : "memory");
}
__device__ __forceinline__ void tmem_dealloc_cg2(unsigned tmem, unsigned ncols) {
    asm volatile("tcgen05.dealloc.cta_group::2.sync.aligned.b32 %0, %1;"
                 :: "r"(tmem), "r"(ncols));
}
__device__ __forceinline__ void tc_relinquish_cg2() {
    asm volatile("tcgen05.relinquish_alloc_permit.cta_group::2.sync.aligned;");
}
__device__ __forceinline__ void tc_commit_cg1(unsigned mbar) {
    asm volatile("tcgen05.commit.cta_group::1.mbarrier::arrive::one.shared::cluster.b64 [%0];"
                 :: "r"(mbar) : "memory");
}
__device__ __forceinline__ void tc_commit_mc_cg2(unsigned mbar, unsigned short mask) {
    asm volatile("tcgen05.commit.cta_group::2.mbarrier::arrive::one.shared::cluster.multicast::cluster.b64 [%0], %1;"
                 :: "r"(mbar), "h"(mask) : "memory");
}
__device__ __forceinline__ void tc_fence_after() {
    asm volatile("tcgen05.fence::after_thread_sync;" ::: "memory");
}
__device__ __forceinline__ void tc_wait_ld() {
    asm volatile("tcgen05.wait::ld.sync.aligned;" ::: "memory");
}
__device__ __forceinline__ void mma_cg1(unsigned d, unsigned long long ad,
                                        unsigned long long bd, unsigned idesc, unsigned en) {
    asm volatile(
        "{\n\t.reg .pred p;\n\tsetp.ne.u32 p, %4, 0;\n\t"
        "tcgen05.mma.cta_group::1.kind::f16 [%0], %1, %2, %3, {%5, %5, %5, %5}, p;\n\t}"
        :: "r"(d), "l"(ad), "l"(bd), "r"(idesc), "r"(en), "r"(0u) : "memory");
}
__device__ __forceinline__ void mma_cg2(unsigned d, unsigned long long ad,
                                        unsigned long long bd, unsigned idesc, unsigned en) {
    asm volatile(
        "{\n\t.reg .pred p;\n\tsetp.ne.u32 p, %4, 0;\n\t"
        "tcgen05.mma.cta_group::2.kind::f16 [%0], %1, %2, %3, "
        "{%5, %5, %5, %5, %5, %5, %5, %5}, p;\n\t}"
        :: "r"(d), "l"(ad), "l"(bd), "r"(idesc), "r"(en), "r"(0u) : "memory");
}
__device__ __forceinline__ void tmem_ld32(unsigned* r, unsigned addr) {
    asm volatile(
        "tcgen05.ld.sync.aligned.32x32b.x32.b32 "
        "{%0, %1, %2, %3, %4, %5, %6, %7, "
        " %8, %9, %10, %11, %12, %13, %14, %15, "
        " %16, %17, %18, %19, %20, %21, %22, %23, "
        " %24, %25, %26, %27, %28, %29, %30, %31}, [%32];"
        : "=r"(r[0]),  "=r"(r[1]),  "=r"(r[2]),  "=r"(r[3]),
          "=r"(r[4]),  "=r"(r[5]),  "=r"(r[6]),  "=r"(r[7]),
          "=r"(r[8]),  "=r"(r[9]),  "=r"(r[10]), "=r"(r[11]),
          "=r"(r[12]), "=r"(r[13]), "=r"(r[14]), "=r"(r[15]),
          "=r"(r[16]), "=r"(r[17]), "=r"(r[18]), "=r"(r[19]),
          "=r"(r[20]), "=r"(r[21]), "=r"(r[22]), "=r"(r[23]),
          "=r"(r[24]), "=r"(r[25]), "=r"(r[26]), "=r"(r[27]),
          "=r"(r[28]), "=r"(r[29]), "=r"(r[30]), "=r"(r[31])
        : "r"(addr));
}
__device__ __forceinline__ void tma3d_cg2(unsigned dst, const CUtensorMap* m,
                                          int x, int y, int z, unsigned bar) {
    asm volatile(
        "{\n\t.reg .b32 lb;\n\tand.b32 lb, %5, 0xFEFFFFFF;\n\t"
        "cp.async.bulk.tensor.3d.cta_group::2.shared::cluster.global"
        ".tile.mbarrier::complete_tx::bytes [%0], [%1, {%2, %3, %4}], [lb];\n\t}"
        :: "r"(dst), "l"(m), "r"(x), "r"(y), "r"(z), "r"(bar) : "memory");
}
__device__ __forceinline__ void tma4d_cg2(unsigned dst, const CUtensorMap* m,
                                          int x, int y, int z, int w, unsigned bar) {
    asm volatile(
        "{\n\t.reg .b32 lb;\n\tand.b32 lb, %6, 0xFEFFFFFF;\n\t"
        "cp.async.bulk.tensor.4d.cta_group::2.shared::cluster.global"
        ".tile.mbarrier::complete_tx::bytes [%0], [%1, {%2, %3, %4, %5}], [lb];\n\t}"
        :: "r"(dst), "l"(m), "r"(x), "r"(y), "r"(z), "r"(w), "r"(bar) : "memory");
}
#endif

// ---------------------------------------------------------------------------
// Prep kernels (single fp16 plane)
// ---------------------------------------------------------------------------
__global__ void prep_act(const float* __restrict__ src,
                         __half* __restrict__ dh, int CIN) {
    __shared__ float t[32][33];
    const int b = blockIdx.z, ct = blockIdx.y * 32, pt = blockIdx.x * 32;
    const int tx = threadIdx.x, ty = threadIdx.y;
    for (int i = ty; i < 32; i += 8)
        t[i][tx] = src[((size_t)(b * CIN + ct + i)) * HW_ + pt + tx];
    __syncthreads();
    for (int i = ty; i < 32; i += 8) {
        size_t o = ((size_t)(b * HW_ + pt + i)) * CIN + ct + tx;
        dh[o] = __float2half(t[tx][i]);
    }
}

__global__ void prep_wconv(const float* __restrict__ W,
                           __half* __restrict__ dh, int M, int CIN) {
    int idx = blockIdx.x * 256 + threadIdx.x;
    if (idx >= M * CIN) return;
#pragma unroll
    for (int tap = 0; tap < 9; tap++) {
        size_t o = (size_t)tap * M * CIN + idx;
        dh[o] = __float2half(W[(size_t)idx * 9 + tap] * WSCALE);
    }
}

__global__ void prep_wlin(const float* __restrict__ W,
                          __half* __restrict__ dh, int n) {
    int i = blockIdx.x * 256 + threadIdx.x;
    if (i >= n) return;
    dh[i] = __float2half(W[i] * WSCALE);
}

__global__ void prep_wqk(const float* __restrict__ qw, const float* __restrict__ kw,
                         const float* __restrict__ qb, const float* __restrict__ kb,
                         __half* __restrict__ dh, float* __restrict__ bias) {
    int i = blockIdx.x * 256 + threadIdx.x;
    if (i < 128) bias[i] = (i < 64) ? qb[i] : kb[i - 64];
    if (i >= 128 * 512) return;
    float x = ((i < 64 * 512) ? qw[i] : kw[i - 64 * 512]) * WSCALE;
    dh[i] = __float2half(x);
}

// ---------------------------------------------------------------------------
// cg2 implicit-conv GEMM, TMA pipeline, warp-specialized control (R13 proven)
// ---------------------------------------------------------------------------
template<int CIN, int TAPS, int EPI>
__global__ void __launch_bounds__(256, 1) __cluster_dims__(2, 1, 1)
mma_conv_tma(const __grid_constant__ CUtensorMap tW,
             const __grid_constant__ CUtensorMap tX,
             const float* __restrict__ e0, const float* __restrict__ e1,
             const float* __restrict__ e2, const float* __restrict__ e3,
             float* __restrict__ Y, int Mtot)
{
#if HAS_TC
    constexpr int NCHUNK = TAPS * (CIN / 64);
    constexpr int NST   = 3;
    constexpr int A_0   = 0;
    constexpr int B_0   = 16384;
    constexpr int STAGE = 49152;
    constexpr unsigned IDESC2 = (1u << 4) | (16u << 17) | (16u << 24);

    extern __shared__ char dyn_smem[];
    __shared__ __align__(8) unsigned long long s_full[NST];
    __shared__ __align__(8) unsigned long long s_done[NST];
    __shared__ unsigned s_tmem[1];

    char* sm = (char*)((((uintptr_t)dyn_smem) + 1023) & ~(uintptr_t)1023);
    const unsigned sbase = smem_u32(sm);

    const int tid  = threadIdx.x;
    const int wid  = tid >> 5;
    const int lane = tid & 31;
    const unsigned rank = blockIdx.x & 1;
    const int m_base = (blockIdx.x >> 1) * 256;
    const int n_base = blockIdx.y * 512;
    const int bb    = n_base >> 12;
    const int sp00  = n_base & 4095;
    const int hrow0 = sp00 >> 6;

    if (wid == 0) tmem_alloc_cg2(smem_u32(&s_tmem[0]), 512);
    if (tid == 0) {
#pragma unroll
        for (int s = 0; s < NST; ++s) {
            mbar_init(smem_u32(&s_full[s]), 1);
            mbar_init(smem_u32(&s_done[s]), 1);
        }
    }
    __syncthreads();
    unsigned tmem;
    asm volatile("ld.shared.b32 %0, [%1];" : "=r"(tmem) : "r"(smem_u32(&s_tmem[0])));
    unsigned fullb[NST], doneb[NST];
#pragma unroll
    for (int s = 0; s < NST; ++s) {
        fullb[s] = smem_u32(&s_full[s]);
        doneb[s] = smem_u32(&s_done[s]);
    }
    cluster_sync_();

    if (tid == 0) {
        // ---- producer ----
        int dph[NST] = {0, 0, 0};
        for (int i = 0; i < NCHUNK; ++i) {
            const int s = i % NST;
            if (i >= NST) { mbar_wait(doneb[s], dph[s]); dph[s] ^= 1; }
            if (rank == 0) mbar_expect_tx(fullb[s], 2 * STAGE);

            const int tap = (TAPS == 1) ? 0 : i / (CIN / 64);
            const int cb  = (TAPS == 1) ? i * 64 : (i % (CIN / 64)) * 64;
            const int dh  = (TAPS == 9) ? (tap / 3 - 1) : 0;
            const int dw  = (TAPS == 9) ? (tap % 3 - 1) : 0;
            const unsigned stg = sbase + s * STAGE;

            tma3d_cg2(stg + A_0, &tW, cb, m_base + (int)rank * 128, tap, fullb[s]);
#pragma unroll
            for (int t = 0; t < 4; ++t)
                tma4d_cg2(stg + B_0 + t * 8192, &tX,
                          cb, dw, hrow0 + 2 * t + (int)rank + dh, bb, fullb[s]);
        }
        const int sl = (NCHUNK - 1) % NST;
        mbar_wait(doneb[sl], dph[sl]);
    }
    if (rank == 0 && tid == 32) {
        // ---- consumer ----
        int fph[NST] = {0, 0, 0};
        for (int i = 0; i < NCHUNK; ++i) {
            const int s = i % NST;
            mbar_wait(fullb[s], fph[s]); fph[s] ^= 1;
            const unsigned sg = sbase + s * STAGE;
            unsigned long long dA = make_desc(sg + A_0);
#pragma unroll
            for (int t = 0; t < 4; ++t) {
                unsigned d = tmem + t * 128;
                unsigned long long dB = make_desc(sg + B_0 + t * 8192);
#pragma unroll
                for (int kk = 0; kk < 4; ++kk) {
                    unsigned en0 = (i > 0 || kk > 0) ? 1u : 0u;
                    mma_cg2(d, dA + kk * 2, dB + kk * 2, IDESC2, en0);
                }
            }
            tc_commit_mc_cg2(doneb[s], 0x3);
        }
    }
    __syncthreads();
    tc_fence_after();

    // --- epilogue ---
    {
        const int wg = wid >> 2;
        const int mg = m_base + (int)rank * 128 + (wid & 3) * 32 + lane;
        float sc, sh;
        if (EPI == 1) {
            float tt = e0[mg] * rsqrtf(e3[mg] + 1e-5f);
            sc = tt * INV_WSCALE;
            sh = e1[mg] - e2[mg] * tt;
        } else {
            sc = INV_WSCALE;
            sh = e0[mg];
        }
        float* yrow = Y + ((size_t)(bb * Mtot + mg)) * HW_ + sp00;
#pragma unroll
        for (int ti = 0; ti < 2; ++ti) {
            int t = wg * 2 + ti;
#pragma unroll
            for (int cb4 = 0; cb4 < 4; ++cb4) {
                unsigned r[32];
                tmem_ld32(r, tmem + t * 128 + cb4 * 32);
                tc_wait_ld();
#pragma unroll
                for (int j = 0; j < 32; j += 4) {
                    float4 v;
                    v.x = fmaf(__uint_as_float(r[j + 0]), sc, sh);
                    v.y = fmaf(__uint_as_float(r[j + 1]), sc, sh);
                    v.z = fmaf(__uint_as_float(r[j + 2]), sc, sh);
                    v.w = fmaf(__uint_as_float(r[j + 3]), sc, sh);
                    if (EPI == 1) {
                        v.x = fmaxf(v.x, 0.f); v.y = fmaxf(v.y, 0.f);
                        v.z = fmaxf(v.z, 0.f); v.w = fmaxf(v.w, 0.f);
                    }
                    *(float4*)(yrow + t * 128 + cb4 * 32 + j) = v;
                }
            }
        }
    }
    __syncthreads();
    if (wid == 0) {
        tc_relinquish_cg2();
        tmem_dealloc_cg2(tmem, 512);
    }
    cluster_sync_();
#endif
}

// ---------------------------------------------------------------------------
// cg1 GEMM for the stacked q/k projection (M=128), fp16 single-plane
// ---------------------------------------------------------------------------
template<int CIN>
__global__ void __launch_bounds__(256, 1)
mma_proj_cg1(const __half* __restrict__ Wh, const __half* __restrict__ Xh,
             const float* __restrict__ e0, float* __restrict__ Y, int Mtot)
{
#if HAS_TC
    constexpr int A_BYTES = 128 * 128;
    constexpr int B_BYTES = 128 * 128;
    constexpr int STAGE   = A_BYTES + B_BYTES;
    constexpr int NCHUNK  = CIN / 64;
    constexpr unsigned IDESC = (1u << 4) | (16u << 17) | (8u << 24);

    extern __shared__ char dyn_smem[];
    __shared__ __align__(8) unsigned long long s_mbar[2];
    __shared__ unsigned s_tmem[1];

    char* sm = (char*)((((uintptr_t)dyn_smem) + 1023) & ~(uintptr_t)1023);
    const unsigned sbase = smem_u32(sm);
    const int tid = threadIdx.x;
    const int wid = tid >> 5;
    const int lane = tid & 31;

    if (wid == 0) tmem_alloc_cg1(smem_u32(&s_tmem[0]), 256);
    if (tid == 0) { mbar_init(smem_u32(&s_mbar[0]), 1); mbar_init(smem_u32(&s_mbar[1]), 1); }
    __syncthreads();
    unsigned tmem;
    asm volatile("ld.shared.b32 %0, [%1];" : "=r"(tmem) : "r"(smem_u32(&s_tmem[0])));
    const unsigned mbar[2] = { smem_u32(&s_mbar[0]), smem_u32(&s_mbar[1]) };

    const int n_base = blockIdx.y * 128;
    const int bb  = n_base >> 12;
    const int sp0 = n_base & 4095;
    int ph[2] = {0, 0};

    for (int chunk = 0; chunk < NCHUNK; ++chunk) {
        const int s  = chunk & 1;
        const int cb = chunk * 64;
        if (chunk >= 2) { mbar_wait(mbar[s], ph[s]); ph[s] ^= 1; }

        char* aH = sm + s * STAGE;
        char* bH = aH + A_BYTES;
#pragma unroll
        for (int u = 0; u < 4; ++u) {
            int l = u * 256 + tid;
            int row = l >> 3, c16 = l & 7;
            size_t go = (size_t)row * CIN + cb + c16 * 8;
            unsigned so = SW128((unsigned)(row * 128 + c16 * 16));
            *(uint4*)(aH + so) = *(const uint4*)(Wh + go);
        }
#pragma unroll
        for (int u = 0; u < 4; ++u) {
            int l = u * 256 + tid;
            int row = l >> 3, c16 = l & 7;
            size_t go = ((size_t)(bb * HW_ + sp0 + row)) * CIN + cb + c16 * 8;
            unsigned so = SW128((unsigned)(row * 128 + c16 * 16));
            *(uint4*)(bH + so) = *(const uint4*)(Xh + go);
        }
        fence_async_shared();
        __syncthreads();

        if (wid == 0 && elect_one()) {
            unsigned long long dA = make_desc(sbase + s * STAGE);
            unsigned long long dB = make_desc(sbase + s * STAGE + A_BYTES);
#pragma unroll
            for (int kk = 0; kk < 4; ++kk) {
                unsigned en0 = (chunk > 0 || kk > 0) ? 1u : 0u;
                mma_cg1(tmem, dA + kk * 2, dB + kk * 2, IDESC, en0);
            }
            tc_commit_cg1(mbar[s]);
        }
    }
    {
        int s0 = (NCHUNK - 2) & 1, s1 = (NCHUNK - 1) & 1;
        mbar_wait(mbar[s0], ph[s0]); ph[s0] ^= 1;
        mbar_wait(mbar[s1], ph[s1]); ph[s1] ^= 1;
    }
    tc_fence_after();

    if (wid < 4) {
        const int mg = wid * 32 + lane;
        float sh = e0[mg];
        float* yrow = Y + ((size_t)(bb * Mtot + mg)) * HW_ + sp0;
#pragma unroll
        for (int cb4 = 0; cb4 < 4; ++cb4) {
            unsigned r[32];
            tmem_ld32(r, tmem + cb4 * 32);
            tc_wait_ld();
#pragma unroll
            for (int j = 0; j < 32; j += 4) {
                float4 v;
                v.x = fmaf(__uint_as_float(r[j + 0]), INV_WSCALE, sh);
                v.y = fmaf(__uint_as_float(r[j + 1]), INV_WSCALE, sh);
                v.z = fmaf(__uint_as_float(r[j + 2]), INV_WSCALE, sh);
                v.w = fmaf(__uint_as_float(r[j + 3]), INV_WSCALE, sh);
                *(float4*)(yrow + cb4 * 32 + j) = v;
            }
        }
    }
    __syncthreads();
    if (wid == 0) tmem_dealloc_cg1(tmem, 256);
#endif
}

// ---------------------------------------------------------------------------
// CCA kernels
// ---------------------------------------------------------------------------
__global__ void __launch_bounds__(256) energyH_kernel(
    const float* __restrict__ qk, float* __restrict__ attn)
{
    const int w = blockIdx.x, b = blockIdx.y;
    __shared__ float Qs[64][65];
    __shared__ float Ks[64][65];
    const int tid = threadIdx.x;
    for (int l = tid; l < 4096; l += 256) {
        int c = l >> 6, h = l & 63;
        Qs[c][h] = qk[((size_t)(b * 128 + c)) * HW_ + h * 64 + w];
        Ks[c][h] = qk[((size_t)(b * 128 + 64 + c)) * HW_ + h * 64 + w];
    }
    __syncthreads();
    const int i4 = (tid & 15) * 4, h4 = (tid >> 4) * 4;
    float acc[4][4];
#pragma unroll
    for (int a = 0; a < 4; a++)
#pragma unroll
        for (int d = 0; d < 4; d++) acc[a][d] = 0.f;
    for (int c = 0; c < 64; c++) {
        float q0 = Qs[c][h4], q1 = Qs[c][h4 + 1], q2 = Qs[c][h4 + 2], q3 = Qs[c][h4 + 3];
        float k0 = Ks[c][i4], k1 = Ks[c][i4 + 1], k2 = Ks[c][i4 + 2], k3 = Ks[c][i4 + 3];
        acc[0][0] += q0 * k0; acc[0][1] += q0 * k1; acc[0][2] += q0 * k2; acc[0][3] += q0 * k3;
        acc[1][0] += q1 * k0; acc[1][1] += q1 * k1; acc[1][2] += q1 * k2; acc[1][3] += q1 * k3;
        acc[2][0] += q2 * k0; acc[2][1] += q2 * k1; acc[2][2] += q2 * k2; acc[2][3] += q2 * k3;
        acc[3][0] += q3 * k0; acc[3][1] += q3 * k1; acc[3][2] += q3 * k2; acc[3][3] += q3 * k3;
    }
#pragma unroll
    for (int a = 0; a < 4; a++) {
        int h = h4 + a;
        float4 o;
        o.x = acc[a][0] + ((i4 + 0 == h) ? -1000000000.0f : 0.f);
        o.y = acc[a][1] + ((i4 + 1 == h) ? -1000000000.0f : 0.f);
        o.z = acc[a][2] + ((i4 + 2 == h) ? -1000000000.0f : 0.f);
        o.w = acc[a][3] + ((i4 + 3 == h) ? -1000000000.0f : 0.f);
        *(float4*)(attn + (size_t)(((b * 64 + h) * 64 + w)) * 128 + i4) = o;
    }
}

__global__ void __launch_bounds__(256) energyW_kernel(
    const float* __restrict__ qk, float* __restrict__ attn)
{
    const int h = blockIdx.x, b = blockIdx.y;
    __shared__ float Qs[64][65];
    __shared__ float Ks[64][65];
    const int tid = threadIdx.x;
    for (int l = tid; l < 4096; l += 256) {
        int c = l >> 6, w = l & 63;
        Qs[c][w] = qk[((size_t)(b * 128 + c)) * HW_ + h * 64 + w];
        Ks[c][w] = qk[((size_t)(b * 128 + 64 + c)) * HW_ + h * 64 + w];
    }
    __syncthreads();
    const int j4 = (tid & 15) * 4, w4 = (tid >> 4) * 4;
    float acc[4][4];
#pragma unroll
    for (int a = 0; a < 4; a++)
#pragma unroll
        for (int d = 0; d < 4; d++) acc[a][d] = 0.f;
    for (int c = 0; c < 64; c++) {
        float q0 = Qs[c][w4], q1 = Qs[c][w4 + 1], q2 = Qs[c][w4 + 2], q3 = Qs[c][w4 + 3];
        float k0 = Ks[c][j4], k1 = Ks[c][j4 + 1], k2 = Ks[c][j4 + 2], k3 = Ks[c][j4 + 3];
        acc[0][0] += q0 * k0; acc[0][1] += q0 * k1; acc[0][2] += q0 * k2; acc[0][3] += q0 * k3;
        acc[1][0] += q1 * k0; acc[1][1] += q1 * k1; acc[1][2] += q1 * k2; acc[1][3] += q1 * k3;
        acc[2][0] += q2 * k0; acc[2][1] += q2 * k1; acc[2][2] += q2 * k2; acc[2][3] += q2 * k3;
        acc[3][0] += q3 * k0; acc[3][1] += q3 * k1; acc[3][2] += q3 * k2; acc[3][3] += q3 * k3;
    }
#pragma unroll
    for (int a = 0; a < 4; a++) {
        int w = w4 + a;
        float4 o = make_float4(acc[a][0], acc[a][1], acc[a][2], acc[a][3]);
        *(float4*)(attn + (size_t)(((b * 64 + h) * 64 + w)) * 128 + 64 + j4) = o;
    }
}

__global__ void __launch_bounds__(256) softmax_kernel(float* __restrict__ attn)
{
    int gw = (blockIdx.x * blockDim.x + threadIdx.x) >> 5;
    if (gw >= NPIX_) return;
    int lane = threadIdx.x & 31;
    float* row = attn + (size_t)gw * 128;
    float v0 = row[lane], v1 = row[lane + 32], v2 = row[lane + 64], v3 = row[lane + 96];
    float mx = fmaxf(fmaxf(v0, v1), fmaxf(v2, v3));
#pragma unroll
    for (int o = 16; o > 0; o >>= 1) mx = fmaxf(mx, __shfl_xor_sync(0xffffffffu, mx, o));
    v0 = expf(v0 - mx); v1 = expf(v1 - mx); v2 = expf(v2 - mx); v3 = expf(v3 - mx);
    float s = v0 + v1 + v2 + v3;
#pragma unroll
    for (int o = 16; o > 0; o >>= 1) s += __shfl_xor_sync(0xffffffffu, s, o);
    float inv = 1.0f / s;
    row[lane] = v0 * inv; row[lane + 32] = v1 * inv;
    row[lane + 64] = v2 * inv; row[lane + 96] = v3 * inv;
}

// aggH — w-tiled, fully coalesced: CTA = (w-block of 4, b, c-block of 16)
__global__ void __launch_bounds__(256) aggH_kernel(
    const float* __restrict__ v, const float* __restrict__ attn,
    const float* __restrict__ fin, float* __restrict__ fout,
    const float* __restrict__ gptr)
{
    const int w0 = blockIdx.x * 4, b = blockIdx.y, c0 = blockIdx.z * 16;
    __shared__ float4 Vs4[16][64];    // [c][i] packed over w (16KB)
    __shared__ float4 Am2[64][65];    // [h][i] packed over w, padded (66.6KB)
    const int tid = threadIdx.x;

    // V: float4 over w, contiguous gmem
    for (int l = tid; l < 16 * 64; l += 256) {
        int c = l >> 6, i = l & 63;
        Vs4[c][i] = *(const float4*)(v + ((size_t)((b * 512 + c0 + c) * 64 + i)) * 64 + w0);
    }
    // attn: 4 coalesced scalar rows (over i), register-packed into w-float4
    for (int l = tid; l < 64 * 64; l += 256) {
        int i = l & 63, h = l >> 6;
        const float* base = attn + (size_t)(((b * 64 + h) * 64 + w0)) * 128 + i;
        float4 a;
        a.x = base[0];
        a.y = base[128];
        a.z = base[256];
        a.w = base[384];
        Am2[h][i] = a;
    }
    __syncthreads();

    const int cg = (tid >> 6) * 4;   // 4 c-groups of 4
    const int h  = tid & 63;
    float4 acc[4];
#pragma unroll
    for (int a = 0; a < 4; a++) acc[a] = make_float4(0.f, 0.f, 0.f, 0.f);

    for (int i = 0; i < 64; i++) {
        float4 am = Am2[h][i];
#pragma unroll
        for (int a = 0; a < 4; a++) {
            float4 vv = Vs4[cg + a][i];
            acc[a].x += vv.x * am.x;
            acc[a].y += vv.y * am.y;
            acc[a].z += vv.z * am.z;
            acc[a].w += vv.w * am.w;
        }
    }
    const float g = *gptr;
#pragma unroll
    for (int a = 0; a < 4; a++) {
        size_t idx = ((size_t)((b * 512 + c0 + cg + a) * 64 + h)) * 64 + w0;
        float4 fi = *(const float4*)(fin + idx);
        float4 o;
        o.x = fi.x + g * acc[a].x;
        o.y = fi.y + g * acc[a].y;
        o.z = fi.z + g * acc[a].z;
        o.w = fi.w + g * acc[a].w;
        *(float4*)(fout + idx) = o;
    }
}

// aggW: final residual add + fused NHWC fp16 emit (proven R13)
__global__ void __launch_bounds__(256) aggW_kernel(
    const float* __restrict__ v, const float* __restrict__ attn,
    float* __restrict__ fout, const float* __restrict__ gptr,
    __half* __restrict__ fh)
{
    const int h = blockIdx.x, b = blockIdx.y, cbk = blockIdx.z * 64;
    __shared__ float Vs[64][65];
    __shared__ float Am[64][65];
    const int tid = threadIdx.x;
    for (int l = tid; l < 4096; l += 256) {
        int c = l >> 6, j = l & 63;
        Vs[c][j] = v[(size_t)((b * 512 + cbk + c) * 64 + h) * 64 + j];
    }
    for (int l = tid; l < 4096; l += 256) {
        int w = l >> 6, j = l & 63;
        Am[w][j] = attn[(size_t)(((b * 64 + h) * 64 + w)) * 128 + 64 + j];
    }
    __syncthreads();
    const int c4 = (tid & 15) * 4, w4 = (tid >> 4) * 4;
    float acc[4][4];
#pragma unroll
    for (int a = 0; a < 4; a++)
#pragma unroll
        for (int d = 0; d < 4; d++) acc[a][d] = 0.f;
    for (int j = 0; j < 64; j++) {
        float v0 = Vs[c4][j], v1 = Vs[c4 + 1][j], v2 = Vs[c4 + 2][j], v3 = Vs[c4 + 3][j];
        float a0 = Am[w4][j], a1 = Am[w4 + 1][j], a2 = Am[w4 + 2][j], a3 = Am[w4 + 3][j];
        acc[0][0] += v0 * a0; acc[0][1] += v0 * a1; acc[0][2] += v0 * a2; acc[0][3] += v0 * a3;
        acc[1][0] += v1 * a0; acc[1][1] += v1 * a1; acc[1][2] += v1 * a2; acc[1][3] += v1 * a3;
        acc[2][0] += v2 * a0; acc[2][1] += v2 * a1; acc[2][2] += v2 * a2; acc[2][3] += v2 * a3;
        acc[3][0] += v3 * a0; acc[3][1] += v3 * a1; acc[3][2] += v3 * a2; acc[3][3] += v3 * a3;
    }
    const float g = *gptr;
#pragma unroll
    for (int d = 0; d < 4; d++) {
        int w = w4 + d;
        float val[4];
#pragma unroll
        for (int a = 0; a < 4; a++) {
            size_t idx = (size_t)((b * 512 + cbk + c4 + a) * 64 + h) * 64 + w;
            val[a] = fout[idx] + g * acc[a][d];
            fout[idx] = val[a];
        }
        __half2 p0 = __floats2half2_rn(val[0], val[1]);
        __half2 p1 = __floats2half2_rn(val[2], val[3]);
        size_t o = ((size_t)(b * HW_ + h * 64 + w)) * 512 + cbk + c4;
        *(__half2*)(fh + o)     = p0;
        *(__half2*)(fh + o + 2) = p1;
    }
}

// ---------------------------------------------------------------------------
// Host: tensor-map encoding via runtime driver-entry-point
// ---------------------------------------------------------------------------
typedef CUresult (*EncodeTiledFn)(
    CUtensorMap*, CUtensorMapDataType, cuuint32_t, void*,
    const cuuint64_t*, const cuuint64_t*, const cuuint32_t*, const cuuint32_t*,
    CUtensorMapInterleave, CUtensorMapSwizzle, CUtensorMapL2promotion,
    CUtensorMapFloatOOBfill);

static EncodeTiledFn get_encode_fn() {
    static EncodeTiledFn fn = nullptr;
    if (!fn) {
        void* p = nullptr;
        cudaDriverEntryPointQueryResult st;
        cudaGetDriverEntryPointByVersion("cuTensorMapEncodeTiled", &p, 12000,
                                         cudaEnableDefault, &st);
        fn = (EncodeTiledFn)p;
    }
    return fn;
}

static void encode_w3d(CUtensorMap* tm, void* ptr,
                       unsigned long long cin, unsigned long long m,
                       unsigned long long taps) {
    cuuint64_t dims[3] = {cin, m, taps};
    cuuint64_t strides[2] = {cin * 2, cin * m * 2};
    cuuint32_t box[3] = {64, 128, 1};
    cuuint32_t es[3] = {1, 1, 1};
    get_encode_fn()(tm, CU_TENSOR_MAP_DATA_TYPE_FLOAT16, 3, ptr, dims, strides,
                    box, es, CU_TENSOR_MAP_INTERLEAVE_NONE,
                    CU_TENSOR_MAP_SWIZZLE_128B,
                    CU_TENSOR_MAP_L2_PROMOTION_L2_128B,
                    CU_TENSOR_MAP_FLOAT_OOB_FILL_NONE);
}

static void encode_x4d(CUtensorMap* tm, void* ptr, unsigned long long C) {
    cuuint64_t dims[4] = {C, 64, 64, 4};
    cuuint64_t strides[3] = {C * 2, 64 * C * 2, 64ull * 64 * C * 2};
    cuuint32_t box[4] = {64, 64, 1, 1};
    cuuint32_t es[4] = {1, 1, 1, 1};
    get_encode_fn()(tm, CU_TENSOR_MAP_DATA_TYPE_FLOAT16, 4, ptr, dims, strides,
                    box, es, CU_TENSOR_MAP_INTERLEAVE_NONE,
                    CU_TENSOR_MAP_SWIZZLE_128B,
                    CU_TENSOR_MAP_L2_PROMOTION_L2_128B,
                    CU_TENSOR_MAP_FLOAT_OOB_FILL_NONE);
}

// ---------------------------------------------------------------------------
// Launch
// ---------------------------------------------------------------------------
extern "C" void kernel_launch(void* const* d_in, const int* in_sizes, int n_in,
                              void* d_out, int out_size)
{
    const float* x     = (const float*)d_in[0];
    const float* c1w   = (const float*)d_in[1];
    const float* bn1g  = (const float*)d_in[2];
    const float* bn1b  = (const float*)d_in[3];
    const float* bn1m  = (const float*)d_in[4];
    const float* bn1v  = (const float*)d_in[5];
    const float* qw    = (const float*)d_in[6];
    const float* qb    = (const float*)d_in[7];
    const float* kw    = (const float*)d_in[8];
    const float* kb    = (const float*)d_in[9];
    const float* vw    = (const float*)d_in[10];
    const float* vb    = (const float*)d_in[11];
    const float* gamma = (const float*)d_in[12];
    const float* c2w   = (const float*)d_in[13];
    const float* bn2g  = (const float*)d_in[14];
    const float* bn2b  = (const float*)d_in[15];
    const float* bn2m  = (const float*)d_in[16];
    const float* bn2v  = (const float*)d_in[17];
    float* out = (float*)d_out;

    float *fA, *fB, *gv, *gqk, *gat, *gbqk;
    __half *xh, *fh, *w1h, *w2h, *wqkh, *wvh;
    cudaGetSymbolAddress((void**)&fA, g_featsA);
    cudaGetSymbolAddress((void**)&fB, g_featsB);
    cudaGetSymbolAddress((void**)&gv, g_v);
    cudaGetSymbolAddress((void**)&gqk, g_qk);
    cudaGetSymbolAddress((void**)&gat, g_attn);
    cudaGetSymbolAddress((void**)&gbqk, g_bqk);
    cudaGetSymbolAddress((void**)&xh, g_xh);
    cudaGetSymbolAddress((void**)&fh, g_fh);
    cudaGetSymbolAddress((void**)&w1h, g_w1h);
    cudaGetSymbolAddress((void**)&w2h, g_w2h);
    cudaGetSymbolAddress((void**)&wqkh, g_wqkh);
    cudaGetSymbolAddress((void**)&wvh, g_wvh);

    static CUtensorMap tW1, tW2, tWv, tXh, tFh;
    encode_w3d(&tW1, w1h, 2048, 512, 9);
    encode_w3d(&tW2, w2h, 512, 512, 9);
    encode_w3d(&tWv, wvh, 512, 512, 1);
    encode_x4d(&tXh, xh, 2048);
    encode_x4d(&tFh, fh, 512);

    const int SMEM_TMA = 3 * 49152 + 1024;
    const int SMEM_P1  = 2 * 32768 + 1024;
    cudaFuncSetAttribute(mma_conv_tma<2048, 9, 1>, cudaFuncAttributeMaxDynamicSharedMemorySize, SMEM_TMA);
    cudaFuncSetAttribute(mma_conv_tma<512, 9, 1>,  cudaFuncAttributeMaxDynamicSharedMemorySize, SMEM_TMA);
    cudaFuncSetAttribute(mma_conv_tma<512, 1, 0>,  cudaFuncAttributeMaxDynamicSharedMemorySize, SMEM_TMA);
    cudaFuncSetAttribute(mma_proj_cg1<512>,        cudaFuncAttributeMaxDynamicSharedMemorySize, SMEM_P1);

    // ncu captures OUR launch index 3 -> conv1 stays there
    prep_wconv<<<(512 * 2048 + 255) / 256, 256>>>(c1w, w1h, 512, 2048);          // 0
    prep_act<<<dim3(128, 64, 4), dim3(32, 8)>>>(x, xh, 2048);                    // 1
    prep_wqk<<<256, 256>>>(qw, kw, qb, kb, wqkh, gbqk);                          // 2
    mma_conv_tma<2048, 9, 1><<<dim3(4, 32), 256, SMEM_TMA>>>(                    // 3: conv1
        tW1, tXh, bn1g, bn1b, bn1m, bn1v, fA, 512);
    prep_wlin<<<(512 * 512 + 255) / 256, 256>>>(vw, wvh, 512 * 512);             // 4
    prep_wconv<<<(512 * 512 + 255) / 256, 256>>>(c2w, w2h, 512, 512);            // 5

    // --- 2x criss-cross attention ---
    float* cur = fA;
    float* nxt = fB;
    for (int it = 0; it < 2; ++it) {
        if (it == 0)
            prep_act<<<dim3(128, 16, 4), dim3(32, 8)>>>(cur, fh, 512);
        mma_proj_cg1<512><<<dim3(1, 128), 256, SMEM_P1>>>(
            wqkh, fh, gbqk, gqk, 128);
        mma_conv_tma<512, 1, 0><<<dim3(4, 32), 256, SMEM_TMA>>>(
            tWv, tFh, vb, nullptr, nullptr, nullptr, gv, 512);
        energyH_kernel<<<dim3(64, 4), 256>>>(gqk, gat);
        energyW_kernel<<<dim3(64, 4), 256>>>(gqk, gat);
        softmax_kernel<<<NPIX_ / 8, 256>>>(gat);
        aggH_kernel<<<dim3(16, 4, 32), 256>>>(gv, gat, cur, nxt, gamma);
        aggW_kernel<<<dim3(64, 4, 8), 256>>>(gv, gat, nxt, gamma, fh);
        float* tmp = cur; cur = nxt; nxt = tmp;
    }

    // --- conv2 + BN + ReLU ---
    mma_conv_tma<512, 9, 1><<<dim3(4, 32), 256, SMEM_TMA>>>(
        tW2, tFh, bn2g, bn2b, bn2m, bn2v, out, 512);
}

// round 16
// speedup vs baseline: 1.7987x; 1.0311x over previous
#include <cuda_runtime.h>
#include <cuda.h>
#include <cuda_fp16.h>
#include <math.h>
#include <stdint.h>

#define HW_   4096
#define NPIX_ 16384

#if defined(__CUDA_ARCH__) && (defined(__CUDA_ARCH_FEAT_SM103_ALL) || defined(__CUDA_ARCH_FEAT_SM100_ALL))
#define HAS_TC 1
#else
#define HAS_TC 0
#endif

#define WSCALE     64.0f
#define INV_WSCALE 0.015625f

// ---------------------------------------------------------------------------
// Scratch (device globals; allocation is forbidden). TMA sources aligned.
// ---------------------------------------------------------------------------
__device__ float g_featsA[4 * 512 * 4096];
__device__ float g_featsB[4 * 512 * 4096];
__device__ float g_v[4 * 512 * 4096];
__device__ float g_qk[4 * 128 * 4096];
__device__ float g_attn[4 * 4096 * 128];
__device__ float g_bqk[128];
__device__ __align__(128) __half g_xh[4 * 4096 * 2048];
__device__ __align__(128) __half g_fh[4 * 4096 * 512];
__device__ __align__(128) __half g_w1h[9 * 512 * 2048];
__device__ __align__(128) __half g_w2h[9 * 512 * 512];
__device__ __align__(128) __half g_wqkh[128 * 512];
__device__ __align__(128) __half g_wvh[512 * 512];

// ---------------------------------------------------------------------------
// Generic helpers
// ---------------------------------------------------------------------------
__device__ __forceinline__ unsigned smem_u32(const void* p) {
    unsigned a;
    asm("{ .reg .u64 t; cvta.to.shared.u64 t, %1; cvt.u32.u64 %0, t; }"
        : "=r"(a) : "l"(p));
    return a;
}
__device__ __forceinline__ unsigned elect_one() {
    unsigned p;
    asm volatile("{ .reg .pred p; elect.sync _|p, 0xFFFFFFFF; selp.b32 %0, 1, 0, p; }"
                 : "=r"(p));
    return p;
}
#define SW128(o) ((o) ^ (((o) >> 3) & 0x70))
__device__ __forceinline__ void mbar_init(unsigned mbar, unsigned cnt) {
    asm volatile("mbarrier.init.shared.b64 [%0], %1;" :: "r"(mbar), "r"(cnt) : "memory");
}
__device__ __forceinline__ void mbar_wait(unsigned mbar, unsigned phase) {
    asm volatile(
        "{\n\t.reg .pred P;\n\t"
        "WL_%=:\n\t"
        "mbarrier.try_wait.parity.acquire.cta.shared::cta.b64 P, [%0], %1, 0x989680;\n\t"
        "@P bra.uni WD_%=;\n\t"
        "bra.uni WL_%=;\n\t"
        "WD_%=:\n\t}"
        :: "r"(mbar), "r"(phase) : "memory");
}
__device__ __forceinline__ void fence_async_shared() {
    asm volatile("fence.proxy.async;" ::: "memory");
}

// ---------------------------------------------------------------------------
// tcgen05 / TMA / cluster helpers (arch-specific pass only)
// ---------------------------------------------------------------------------
#if HAS_TC
static constexpr unsigned long long SMEM_DESC_BASE_SW128 =
    (2ull << 61) | (1ull << 46) | (64ull << 32) | (1ull << 16);
__device__ __forceinline__ unsigned long long make_desc(unsigned addr) {
    return SMEM_DESC_BASE_SW128 | ((unsigned long long)(addr >> 4) & 0x3FFFull);
}
__device__ __forceinline__ void cluster_sync_() {
    asm volatile("barrier.cluster.arrive.aligned;" ::: "memory");
    asm volatile("barrier.cluster.wait.aligned;" ::: "memory");
}
__device__ __forceinline__ void mbar_expect_tx(unsigned mbar, unsigned bytes) {
    asm volatile("mbarrier.arrive.expect_tx.shared.b64 _, [%0], %1;"
                 :: "r"(mbar), "r"(bytes) : "memory");
}
__device__ __forceinline__ void tmem_alloc_cg1(unsigned dst_smem, unsigned ncols) {
    asm volatile("tcgen05.alloc.cta_group::1.sync.aligned.shared::cta.b32 [%0], %1;"
                 :: "r"(dst_smem), "r"(ncols) : "memory");
}
__device__ __forceinline__ void tmem_dealloc_cg1(unsigned tmem, unsigned ncols) {
    asm volatile("tcgen05.dealloc.cta_group::1.sync.aligned.b32 %0, %1;"
                 :: "r"(tmem), "r"(ncols));
}
__device__ __forceinline__ void tmem_alloc_cg2(unsigned dst_smem, unsigned ncols) {
    asm volatile("tcgen05.alloc.cta_group::2.sync.aligned.shared::cta.b32 [%0], %1;"
                 :: "r"(dst_smem), "r"(ncols) : "memory");
}
__device__ __forceinline__ void tmem_dealloc_cg2(unsigned tmem, unsigned ncols) {
    asm volatile("tcgen05.dealloc.cta_group::2.sync.aligned.b32 %0, %1;"
                 :: "r"(tmem), "r"(ncols));
}
__device__ __forceinline__ void tc_relinquish_cg2() {
    asm volatile("tcgen05.relinquish_alloc_permit.cta_group::2.sync.aligned;");
}
__device__ __forceinline__ void tc_commit_cg1(unsigned mbar) {
    asm volatile("tcgen05.commit.cta_group::1.mbarrier::arrive::one.shared::cluster.b64 [%0];"
                 :: "r"(mbar) : "memory");
}
__device__ __forceinline__ void tc_commit_mc_cg2(unsigned mbar, unsigned short mask) {
    asm volatile("tcgen05.commit.cta_group::2.mbarrier::arrive::one.shared::cluster.multicast::cluster.b64 [%0], %1;"
                 :: "r"(mbar), "h"(mask) : "memory");
}
__device__ __forceinline__ void tc_fence_after() {
    asm volatile("tcgen05.fence::after_thread_sync;" ::: "memory");
}
__device__ __forceinline__ void tc_wait_ld() {
    asm volatile("tcgen05.wait::ld.sync.aligned;" ::: "memory");
}
__device__ __forceinline__ void mma_cg1(unsigned d, unsigned long long ad,
                                        unsigned long long bd, unsigned idesc, unsigned en) {
    asm volatile(
        "{\n\t.reg .pred p;\n\tsetp.ne.u32 p, %4, 0;\n\t"
        "tcgen05.mma.cta_group::1.kind::f16 [%0], %1, %2, %3, {%5, %5, %5, %5}, p;\n\t}"
        :: "r"(d), "l"(ad), "l"(bd), "r"(idesc), "r"(en), "r"(0u) : "memory");
}
__device__ __forceinline__ void mma_cg2(unsigned d, unsigned long long ad,
                                        unsigned long long bd, unsigned idesc, unsigned en) {
    asm volatile(
        "{\n\t.reg .pred p;\n\tsetp.ne.u32 p, %4, 0;\n\t"
        "tcgen05.mma.cta_group::2.kind::f16 [%0], %1, %2, %3, "
        "{%5, %5, %5, %5, %5, %5, %5, %5}, p;\n\t}"
        :: "r"(d), "l"(ad), "l"(bd), "r"(idesc), "r"(en), "r"(0u) : "memory");
}
__device__ __forceinline__ void tmem_ld32(unsigned* r, unsigned addr) {
    asm volatile(
        "tcgen05.ld.sync.aligned.32x32b.x32.b32 "
        "{%0, %1, %2, %3, %4, %5, %6, %7, "
        " %8, %9, %10, %11, %12, %13, %14, %15, "
        " %16, %17, %18, %19, %20, %21, %22, %23, "
        " %24, %25, %26, %27, %28, %29, %30, %31}, [%32];"
        : "=r"(r[0]),  "=r"(r[1]),  "=r"(r[2]),  "=r"(r[3]),
          "=r"(r[4]),  "=r"(r[5]),  "=r"(r[6]),  "=r"(r[7]),
          "=r"(r[8]),  "=r"(r[9]),  "=r"(r[10]), "=r"(r[11]),
          "=r"(r[12]), "=r"(r[13]), "=r"(r[14]), "=r"(r[15]),
          "=r"(r[16]), "=r"(r[17]), "=r"(r[18]), "=r"(r[19]),
          "=r"(r[20]), "=r"(r[21]), "=r"(r[22]), "=r"(r[23]),
          "=r"(r[24]), "=r"(r[25]), "=r"(r[26]), "=r"(r[27]),
          "=r"(r[28]), "=r"(r[29]), "=r"(r[30]), "=r"(r[31])
        : "r"(addr));
}
__device__ __forceinline__ void tma3d_cg2(unsigned dst, const CUtensorMap* m,
                                          int x, int y, int z, unsigned bar) {
    asm volatile(
        "{\n\t.reg .b32 lb;\n\tand.b32 lb, %5, 0xFEFFFFFF;\n\t"
        "cp.async.bulk.tensor.3d.cta_group::2.shared::cluster.global"
        ".tile.mbarrier::complete_tx::bytes [%0], [%1, {%2, %3, %4}], [lb];\n\t}"
        :: "r"(dst), "l"(m), "r"(x), "r"(y), "r"(z), "r"(bar) : "memory");
}
__device__ __forceinline__ void tma4d_cg2(unsigned dst, const CUtensorMap* m,
                                          int x, int y, int z, int w, unsigned bar) {
    asm volatile(
        "{\n\t.reg .b32 lb;\n\tand.b32 lb, %6, 0xFEFFFFFF;\n\t"
        "cp.async.bulk.tensor.4d.cta_group::2.shared::cluster.global"
        ".tile.mbarrier::complete_tx::bytes [%0], [%1, {%2, %3, %4, %5}], [lb];\n\t}"
        :: "r"(dst), "l"(m), "r"(x), "r"(y), "r"(z), "r"(w), "r"(bar) : "memory");
}
#endif

// ---------------------------------------------------------------------------
// Prep kernels (single fp16 plane)
// ---------------------------------------------------------------------------
__global__ void prep_act(const float* __restrict__ src,
                         __half* __restrict__ dh, int CIN) {
    __shared__ float t[32][33];
    const int b = blockIdx.z, ct = blockIdx.y * 32, pt = blockIdx.x * 32;
    const int tx = threadIdx.x, ty = threadIdx.y;
    for (int i = ty; i < 32; i += 8)
        t[i][tx] = src[((size_t)(b * CIN + ct + i)) * HW_ + pt + tx];
    __syncthreads();
    for (int i = ty; i < 32; i += 8) {
        size_t o = ((size_t)(b * HW_ + pt + i)) * CIN + ct + tx;
        dh[o] = __float2half(t[tx][i]);
    }
}

__global__ void prep_wconv(const float* __restrict__ W,
                           __half* __restrict__ dh, int M, int CIN) {
    int idx = blockIdx.x * 256 + threadIdx.x;
    if (idx >= M * CIN) return;
#pragma unroll
    for (int tap = 0; tap < 9; tap++) {
        size_t o = (size_t)tap * M * CIN + idx;
        dh[o] = __float2half(W[(size_t)idx * 9 + tap] * WSCALE);
    }
}

__global__ void prep_wlin(const float* __restrict__ W,
                          __half* __restrict__ dh, int n) {
    int i = blockIdx.x * 256 + threadIdx.x;
    if (i >= n) return;
    dh[i] = __float2half(W[i] * WSCALE);
}

__global__ void prep_wqk(const float* __restrict__ qw, const float* __restrict__ kw,
                         const float* __restrict__ qb, const float* __restrict__ kb,
                         __half* __restrict__ dh, float* __restrict__ bias) {
    int i = blockIdx.x * 256 + threadIdx.x;
    if (i < 128) bias[i] = (i < 64) ? qb[i] : kb[i - 64];
    if (i >= 128 * 512) return;
    float x = ((i < 64 * 512) ? qw[i] : kw[i - 64 * 512]) * WSCALE;
    dh[i] = __float2half(x);
}

// ---------------------------------------------------------------------------
// cg2 implicit-conv GEMM, TMA pipeline, warp-specialized control,
// K-chunk = 128. FIX vs R15: en0 must NOT depend on t (each TMEM region
// t is its own accumulator and must be initialized at i==0,half==0,kk==0).
// ---------------------------------------------------------------------------
template<int CIN, int TAPS, int EPI>
__global__ void __launch_bounds__(256, 1) __cluster_dims__(2, 1, 1)
mma_conv_tma(const __grid_constant__ CUtensorMap tW,
             const __grid_constant__ CUtensorMap tX,
             const float* __restrict__ e0, const float* __restrict__ e1,
             const float* __restrict__ e2, const float* __restrict__ e3,
             float* __restrict__ Y, int Mtot)
{
#if HAS_TC
    constexpr int NCHUNK = TAPS * (CIN / 128);
    constexpr int NST   = 2;
    constexpr int A_0   = 0;
    constexpr int B_0   = 32768;
    constexpr int STAGE = 98304;
    constexpr unsigned IDESC2 = (1u << 4) | (16u << 17) | (16u << 24);

    extern __shared__ char dyn_smem[];
    __shared__ __align__(8) unsigned long long s_full[NST];
    __shared__ __align__(8) unsigned long long s_done[NST];
    __shared__ unsigned s_tmem[1];

    char* sm = (char*)((((uintptr_t)dyn_smem) + 1023) & ~(uintptr_t)1023);
    const unsigned sbase = smem_u32(sm);

    const int tid  = threadIdx.x;
    const int wid  = tid >> 5;
    const int lane = tid & 31;
    const unsigned rank = blockIdx.x & 1;
    const int m_base = (blockIdx.x >> 1) * 256;
    const int n_base = blockIdx.y * 512;
    const int bb    = n_base >> 12;
    const int sp00  = n_base & 4095;
    const int hrow0 = sp00 >> 6;

    if (wid == 0) tmem_alloc_cg2(smem_u32(&s_tmem[0]), 512);
    if (tid == 0) {
#pragma unroll
        for (int s = 0; s < NST; ++s) {
            mbar_init(smem_u32(&s_full[s]), 1);
            mbar_init(smem_u32(&s_done[s]), 1);
        }
    }
    __syncthreads();
    unsigned tmem;
    asm volatile("ld.shared.b32 %0, [%1];" : "=r"(tmem) : "r"(smem_u32(&s_tmem[0])));
    unsigned fullb[NST], doneb[NST];
#pragma unroll
    for (int s = 0; s < NST; ++s) {
        fullb[s] = smem_u32(&s_full[s]);
        doneb[s] = smem_u32(&s_done[s]);
    }
    cluster_sync_();

    if (tid == 0) {
        // ---- producer ----
        int dph[NST] = {0, 0};
        for (int i = 0; i < NCHUNK; ++i) {
            const int s = i % NST;
            if (i >= NST) { mbar_wait(doneb[s], dph[s]); dph[s] ^= 1; }
            if (rank == 0) mbar_expect_tx(fullb[s], 2 * STAGE);

            const int tap = (TAPS == 1) ? 0 : i / (CIN / 128);
            const int cb  = (TAPS == 1) ? i * 128 : (i % (CIN / 128)) * 128;
            const int dh  = (TAPS == 9) ? (tap / 3 - 1) : 0;
            const int dw  = (TAPS == 9) ? (tap % 3 - 1) : 0;
            const unsigned stg = sbase + s * STAGE;

            tma3d_cg2(stg + A_0,         &tW, cb,      m_base + (int)rank * 128, tap, fullb[s]);
            tma3d_cg2(stg + A_0 + 16384, &tW, cb + 64, m_base + (int)rank * 128, tap, fullb[s]);
#pragma unroll
            for (int half = 0; half < 2; ++half)
#pragma unroll
                for (int t = 0; t < 4; ++t)
                    tma4d_cg2(stg + B_0 + half * 32768 + t * 8192, &tX,
                              cb + half * 64, dw,
                              hrow0 + 2 * t + (int)rank + dh, bb, fullb[s]);
        }
        const int sl = (NCHUNK - 1) % NST;
        mbar_wait(doneb[sl], dph[sl]);
    }
    if (rank == 0 && tid == 32) {
        // ---- consumer ----
        int fph[NST] = {0, 0};
        for (int i = 0; i < NCHUNK; ++i) {
            const int s = i % NST;
            mbar_wait(fullb[s], fph[s]); fph[s] ^= 1;
            const unsigned sg = sbase + s * STAGE;
#pragma unroll
            for (int t = 0; t < 4; ++t) {
                unsigned d = tmem + t * 128;
#pragma unroll
                for (int half = 0; half < 2; ++half) {
                    unsigned long long dA = make_desc(sg + A_0 + half * 16384);
                    unsigned long long dB = make_desc(sg + B_0 + half * 32768 + t * 8192);
#pragma unroll
                    for (int kk = 0; kk < 4; ++kk) {
                        // FIX: no 't' term — every TMEM region initialized at chunk 0
                        unsigned en0 = (i > 0 || half > 0 || kk > 0) ? 1u : 0u;
                        mma_cg2(d, dA + kk * 2, dB + kk * 2, IDESC2, en0);
                    }
                }
            }
            tc_commit_mc_cg2(doneb[s], 0x3);
        }
    }
    __syncthreads();
    tc_fence_after();

    // --- epilogue ---
    {
        const int wg = wid >> 2;
        const int mg = m_base + (int)rank * 128 + (wid & 3) * 32 + lane;
        float sc, sh;
        if (EPI == 1) {
            float tt = e0[mg] * rsqrtf(e3[mg] + 1e-5f);
            sc = tt * INV_WSCALE;
            sh = e1[mg] - e2[mg] * tt;
        } else {
            sc = INV_WSCALE;
            sh = e0[mg];
        }
        float* yrow = Y + ((size_t)(bb * Mtot + mg)) * HW_ + sp00;
#pragma unroll
        for (int ti = 0; ti < 2; ++ti) {
            int t = wg * 2 + ti;
#pragma unroll
            for (int cb4 = 0; cb4 < 4; ++cb4) {
                unsigned r[32];
                tmem_ld32(r, tmem + t * 128 + cb4 * 32);
                tc_wait_ld();
#pragma unroll
                for (int j = 0; j < 32; j += 4) {
                    float4 v;
                    v.x = fmaf(__uint_as_float(r[j + 0]), sc, sh);
                    v.y = fmaf(__uint_as_float(r[j + 1]), sc, sh);
                    v.z = fmaf(__uint_as_float(r[j + 2]), sc, sh);
                    v.w = fmaf(__uint_as_float(r[j + 3]), sc, sh);
                    if (EPI == 1) {
                        v.x = fmaxf(v.x, 0.f); v.y = fmaxf(v.y, 0.f);
                        v.z = fmaxf(v.z, 0.f); v.w = fmaxf(v.w, 0.f);
                    }
                    *(float4*)(yrow + t * 128 + cb4 * 32 + j) = v;
                }
            }
        }
    }
    __syncthreads();
    if (wid == 0) {
        tc_relinquish_cg2();
        tmem_dealloc_cg2(tmem, 512);
    }
    cluster_sync_();
#endif
}

// ---------------------------------------------------------------------------
// cg1 GEMM for the stacked q/k projection (M=128), fp16 single-plane (R13)
// ---------------------------------------------------------------------------
template<int CIN>
__global__ void __launch_bounds__(256, 1)
mma_proj_cg1(const __half* __restrict__ Wh, const __half* __restrict__ Xh,
             const float* __restrict__ e0, float* __restrict__ Y, int Mtot)
{
#if HAS_TC
    constexpr int A_BYTES = 128 * 128;
    constexpr int B_BYTES = 128 * 128;
    constexpr int STAGE   = A_BYTES + B_BYTES;
    constexpr int NCHUNK  = CIN / 64;
    constexpr unsigned IDESC = (1u << 4) | (16u << 17) | (8u << 24);

    extern __shared__ char dyn_smem[];
    __shared__ __align__(8) unsigned long long s_mbar[2];
    __shared__ unsigned s_tmem[1];

    char* sm = (char*)((((uintptr_t)dyn_smem) + 1023) & ~(uintptr_t)1023);
    const unsigned sbase = smem_u32(sm);
    const int tid = threadIdx.x;
    const int wid = tid >> 5;
    const int lane = tid & 31;

    if (wid == 0) tmem_alloc_cg1(smem_u32(&s_tmem[0]), 256);
    if (tid == 0) { mbar_init(smem_u32(&s_mbar[0]), 1); mbar_init(smem_u32(&s_mbar[1]), 1); }
    __syncthreads();
    unsigned tmem;
    asm volatile("ld.shared.b32 %0, [%1];" : "=r"(tmem) : "r"(smem_u32(&s_tmem[0])));
    const unsigned mbar[2] = { smem_u32(&s_mbar[0]), smem_u32(&s_mbar[1]) };

    const int n_base = blockIdx.y * 128;
    const int bb  = n_base >> 12;
    const int sp0 = n_base & 4095;
    int ph[2] = {0, 0};

    for (int chunk = 0; chunk < NCHUNK; ++chunk) {
        const int s  = chunk & 1;
        const int cb = chunk * 64;
        if (chunk >= 2) { mbar_wait(mbar[s], ph[s]); ph[s] ^= 1; }

        char* aH = sm + s * STAGE;
        char* bH = aH + A_BYTES;
#pragma unroll
        for (int u = 0; u < 4; ++u) {
            int l = u * 256 + tid;
            int row = l >> 3, c16 = l & 7;
            size_t go = (size_t)row * CIN + cb + c16 * 8;
            unsigned so = SW128((unsigned)(row * 128 + c16 * 16));
            *(uint4*)(aH + so) = *(const uint4*)(Wh + go);
        }
#pragma unroll
        for (int u = 0; u < 4; ++u) {
            int l = u * 256 + tid;
            int row = l >> 3, c16 = l & 7;
            size_t go = ((size_t)(bb * HW_ + sp0 + row)) * CIN + cb + c16 * 8;
            unsigned so = SW128((unsigned)(row * 128 + c16 * 16));
            *(uint4*)(bH + so) = *(const uint4*)(Xh + go);
        }
        fence_async_shared();
        __syncthreads();

        if (wid == 0 && elect_one()) {
            unsigned long long dA = make_desc(sbase + s * STAGE);
            unsigned long long dB = make_desc(sbase + s * STAGE + A_BYTES);
#pragma unroll
            for (int kk = 0; kk < 4; ++kk) {
                unsigned en0 = (chunk > 0 || kk > 0) ? 1u : 0u;
                mma_cg1(tmem, dA + kk * 2, dB + kk * 2, IDESC, en0);
            }
            tc_commit_cg1(mbar[s]);
        }
    }
    {
        int s0 = (NCHUNK - 2) & 1, s1 = (NCHUNK - 1) & 1;
        mbar_wait(mbar[s0], ph[s0]); ph[s0] ^= 1;
        mbar_wait(mbar[s1], ph[s1]); ph[s1] ^= 1;
    }
    tc_fence_after();

    if (wid < 4) {
        const int mg = wid * 32 + lane;
        float sh = e0[mg];
        float* yrow = Y + ((size_t)(bb * Mtot + mg)) * HW_ + sp0;
#pragma unroll
        for (int cb4 = 0; cb4 < 4; ++cb4) {
            unsigned r[32];
            tmem_ld32(r, tmem + cb4 * 32);
            tc_wait_ld();
#pragma unroll
            for (int j = 0; j < 32; j += 4) {
                float4 v;
                v.x = fmaf(__uint_as_float(r[j + 0]), INV_WSCALE, sh);
                v.y = fmaf(__uint_as_float(r[j + 1]), INV_WSCALE, sh);
                v.z = fmaf(__uint_as_float(r[j + 2]), INV_WSCALE, sh);
                v.w = fmaf(__uint_as_float(r[j + 3]), INV_WSCALE, sh);
                *(float4*)(yrow + cb4 * 32 + j) = v;
            }
        }
    }
    __syncthreads();
    if (wid == 0) tmem_dealloc_cg1(tmem, 256);
#endif
}

// ---------------------------------------------------------------------------
// CCA kernels (R14 proven)
// ---------------------------------------------------------------------------
__global__ void __launch_bounds__(256) energyH_kernel(
    const float* __restrict__ qk, float* __restrict__ attn)
{
    const int w = blockIdx.x, b = blockIdx.y;
    __shared__ float Qs[64][65];
    __shared__ float Ks[64][65];
    const int tid = threadIdx.x;
    for (int l = tid; l < 4096; l += 256) {
        int c = l >> 6, h = l & 63;
        Qs[c][h] = qk[((size_t)(b * 128 + c)) * HW_ + h * 64 + w];
        Ks[c][h] = qk[((size_t)(b * 128 + 64 + c)) * HW_ + h * 64 + w];
    }
    __syncthreads();
    const int i4 = (tid & 15) * 4, h4 = (tid >> 4) * 4;
    float acc[4][4];
#pragma unroll
    for (int a = 0; a < 4; a++)
#pragma unroll
        for (int d = 0; d < 4; d++) acc[a][d] = 0.f;
    for (int c = 0; c < 64; c++) {
        float q0 = Qs[c][h4], q1 = Qs[c][h4 + 1], q2 = Qs[c][h4 + 2], q3 = Qs[c][h4 + 3];
        float k0 = Ks[c][i4], k1 = Ks[c][i4 + 1], k2 = Ks[c][i4 + 2], k3 = Ks[c][i4 + 3];
        acc[0][0] += q0 * k0; acc[0][1] += q0 * k1; acc[0][2] += q0 * k2; acc[0][3] += q0 * k3;
        acc[1][0] += q1 * k0; acc[1][1] += q1 * k1; acc[1][2] += q1 * k2; acc[1][3] += q1 * k3;
        acc[2][0] += q2 * k0; acc[2][1] += q2 * k1; acc[2][2] += q2 * k2; acc[2][3] += q2 * k3;
        acc[3][0] += q3 * k0; acc[3][1] += q3 * k1; acc[3][2] += q3 * k2; acc[3][3] += q3 * k3;
    }
#pragma unroll
    for (int a = 0; a < 4; a++) {
        int h = h4 + a;
        float4 o;
        o.x = acc[a][0] + ((i4 + 0 == h) ? -1000000000.0f : 0.f);
        o.y = acc[a][1] + ((i4 + 1 == h) ? -1000000000.0f : 0.f);
        o.z = acc[a][2] + ((i4 + 2 == h) ? -1000000000.0f : 0.f);
        o.w = acc[a][3] + ((i4 + 3 == h) ? -1000000000.0f : 0.f);
        *(float4*)(attn + (size_t)(((b * 64 + h) * 64 + w)) * 128 + i4) = o;
    }
}

__global__ void __launch_bounds__(256) energyW_kernel(
    const float* __restrict__ qk, float* __restrict__ attn)
{
    const int h = blockIdx.x, b = blockIdx.y;
    __shared__ float Qs[64][65];
    __shared__ float Ks[64][65];
    const int tid = threadIdx.x;
    for (int l = tid; l < 4096; l += 256) {
        int c = l >> 6, w = l & 63;
        Qs[c][w] = qk[((size_t)(b * 128 + c)) * HW_ + h * 64 + w];
        Ks[c][w] = qk[((size_t)(b * 128 + 64 + c)) * HW_ + h * 64 + w];
    }
    __syncthreads();
    const int j4 = (tid & 15) * 4, w4 = (tid >> 4) * 4;
    float acc[4][4];
#pragma unroll
    for (int a = 0; a < 4; a++)
#pragma unroll
        for (int d = 0; d < 4; d++) acc[a][d] = 0.f;
    for (int c = 0; c < 64; c++) {
        float q0 = Qs[c][w4], q1 = Qs[c][w4 + 1], q2 = Qs[c][w4 + 2], q3 = Qs[c][w4 + 3];
        float k0 = Ks[c][j4], k1 = Ks[c][j4 + 1], k2 = Ks[c][j4 + 2], k3 = Ks[c][j4 + 3];
        acc[0][0] += q0 * k0; acc[0][1] += q0 * k1; acc[0][2] += q0 * k2; acc[0][3] += q0 * k3;
        acc[1][0] += q1 * k0; acc[1][1] += q1 * k1; acc[1][2] += q1 * k2; acc[1][3] += q1 * k3;
        acc[2][0] += q2 * k0; acc[2][1] += q2 * k1; acc[2][2] += q2 * k2; acc[2][3] += q2 * k3;
        acc[3][0] += q3 * k0; acc[3][1] += q3 * k1; acc[3][2] += q3 * k2; acc[3][3] += q3 * k3;
    }
#pragma unroll
    for (int a = 0; a < 4; a++) {
        int w = w4 + a;
        float4 o = make_float4(acc[a][0], acc[a][1], acc[a][2], acc[a][3]);
        *(float4*)(attn + (size_t)(((b * 64 + h) * 64 + w)) * 128 + 64 + j4) = o;
    }
}

__global__ void __launch_bounds__(256) softmax_kernel(float* __restrict__ attn)
{
    int gw = (blockIdx.x * blockDim.x + threadIdx.x) >> 5;
    if (gw >= NPIX_) return;
    int lane = threadIdx.x & 31;
    float* row = attn + (size_t)gw * 128;
    float v0 = row[lane], v1 = row[lane + 32], v2 = row[lane + 64], v3 = row[lane + 96];
    float mx = fmaxf(fmaxf(v0, v1), fmaxf(v2, v3));
#pragma unroll
    for (int o = 16; o > 0; o >>= 1) mx = fmaxf(mx, __shfl_xor_sync(0xffffffffu, mx, o));
    v0 = expf(v0 - mx); v1 = expf(v1 - mx); v2 = expf(v2 - mx); v3 = expf(v3 - mx);
    float s = v0 + v1 + v2 + v3;
#pragma unroll
    for (int o = 16; o > 0; o >>= 1) s += __shfl_xor_sync(0xffffffffu, s, o);
    float inv = 1.0f / s;
    row[lane] = v0 * inv; row[lane + 32] = v1 * inv;
    row[lane + 64] = v2 * inv; row[lane + 96] = v3 * inv;
}

// aggH — w-tiled, fully coalesced (R14 proven)
__global__ void __launch_bounds__(256) aggH_kernel(
    const float* __restrict__ v, const float* __restrict__ attn,
    const float* __restrict__ fin, float* __restrict__ fout,
    const float* __restrict__ gptr)
{
    const int w0 = blockIdx.x * 4, b = blockIdx.y, c0 = blockIdx.z * 16;
    __shared__ float4 Vs4[16][64];
    __shared__ float4 Am2[64][65];
    const int tid = threadIdx.x;

    for (int l = tid; l < 16 * 64; l += 256) {
        int c = l >> 6, i = l & 63;
        Vs4[c][i] = *(const float4*)(v + ((size_t)((b * 512 + c0 + c) * 64 + i)) * 64 + w0);
    }
    for (int l = tid; l < 64 * 64; l += 256) {
        int i = l & 63, h = l >> 6;
        const float* base = attn + (size_t)(((b * 64 + h) * 64 + w0)) * 128 + i;
        float4 a;
        a.x = base[0];
        a.y = base[128];
        a.z = base[256];
        a.w = base[384];
        Am2[h][i] = a;
    }
    __syncthreads();

    const int cg = (tid >> 6) * 4;
    const int h  = tid & 63;
    float4 acc[4];
#pragma unroll
    for (int a = 0; a < 4; a++) acc[a] = make_float4(0.f, 0.f, 0.f, 0.f);

    for (int i = 0; i < 64; i++) {
        float4 am = Am2[h][i];
#pragma unroll
        for (int a = 0; a < 4; a++) {
            float4 vv = Vs4[cg + a][i];
            acc[a].x += vv.x * am.x;
            acc[a].y += vv.y * am.y;
            acc[a].z += vv.z * am.z;
            acc[a].w += vv.w * am.w;
        }
    }
    const float g = *gptr;
#pragma unroll
    for (int a = 0; a < 4; a++) {
        size_t idx = ((size_t)((b * 512 + c0 + cg + a) * 64 + h)) * 64 + w0;
        float4 fi = *(const float4*)(fin + idx);
        float4 o;
        o.x = fi.x + g * acc[a].x;
        o.y = fi.y + g * acc[a].y;
        o.z = fi.z + g * acc[a].z;
        o.w = fi.w + g * acc[a].w;
        *(float4*)(fout + idx) = o;
    }
}

// aggW: final residual add + fused NHWC fp16 emit (R13 proven)
__global__ void __launch_bounds__(256) aggW_kernel(
    const float* __restrict__ v, const float* __restrict__ attn,
    float* __restrict__ fout, const float* __restrict__ gptr,
    __half* __restrict__ fh)
{
    const int h = blockIdx.x, b = blockIdx.y, cbk = blockIdx.z * 64;
    __shared__ float Vs[64][65];
    __shared__ float Am[64][65];
    const int tid = threadIdx.x;
    for (int l = tid; l < 4096; l += 256) {
        int c = l >> 6, j = l & 63;
        Vs[c][j] = v[(size_t)((b * 512 + cbk + c) * 64 + h) * 64 + j];
    }
    for (int l = tid; l < 4096; l += 256) {
        int w = l >> 6, j = l & 63;
        Am[w][j] = attn[(size_t)(((b * 64 + h) * 64 + w)) * 128 + 64 + j];
    }
    __syncthreads();
    const int c4 = (tid & 15) * 4, w4 = (tid >> 4) * 4;
    float acc[4][4];
#pragma unroll
    for (int a = 0; a < 4; a++)
#pragma unroll
        for (int d = 0; d < 4; d++) acc[a][d] = 0.f;
    for (int j = 0; j < 64; j++) {
        float v0 = Vs[c4][j], v1 = Vs[c4 + 1][j], v2 = Vs[c4 + 2][j], v3 = Vs[c4 + 3][j];
        float a0 = Am[w4][j], a1 = Am[w4 + 1][j], a2 = Am[w4 + 2][j], a3 = Am[w4 + 3][j];
        acc[0][0] += v0 * a0; acc[0][1] += v0 * a1; acc[0][2] += v0 * a2; acc[0][3] += v0 * a3;
        acc[1][0] += v1 * a0; acc[1][1] += v1 * a1; acc[1][2] += v1 * a2; acc[1][3] += v1 * a3;
        acc[2][0] += v2 * a0; acc[2][1] += v2 * a1; acc[2][2] += v2 * a2; acc[2][3] += v2 * a3;
        acc[3][0] += v3 * a0; acc[3][1] += v3 * a1; acc[3][2] += v3 * a2; acc[3][3] += v3 * a3;
    }
    const float g = *gptr;
#pragma unroll
    for (int d = 0; d < 4; d++) {
        int w = w4 + d;
        float val[4];
#pragma unroll
        for (int a = 0; a < 4; a++) {
            size_t idx = (size_t)((b * 512 + cbk + c4 + a) * 64 + h) * 64 + w;
            val[a] = fout[idx] + g * acc[a][d];
            fout[idx] = val[a];
        }
        __half2 p0 = __floats2half2_rn(val[0], val[1]);
        __half2 p1 = __floats2half2_rn(val[2], val[3]);
        size_t o = ((size_t)(b * HW_ + h * 64 + w)) * 512 + cbk + c4;
        *(__half2*)(fh + o)     = p0;
        *(__half2*)(fh + o + 2) = p1;
    }
}

// ---------------------------------------------------------------------------
// Host: tensor-map encoding via runtime driver-entry-point
// ---------------------------------------------------------------------------
typedef CUresult (*EncodeTiledFn)(
    CUtensorMap*, CUtensorMapDataType, cuuint32_t, void*,
    const cuuint64_t*, const cuuint64_t*, const cuuint32_t*, const cuuint32_t*,
    CUtensorMapInterleave, CUtensorMapSwizzle, CUtensorMapL2promotion,
    CUtensorMapFloatOOBfill);

static EncodeTiledFn get_encode_fn() {
    static EncodeTiledFn fn = nullptr;
    if (!fn) {
        void* p = nullptr;
        cudaDriverEntryPointQueryResult st;
        cudaGetDriverEntryPointByVersion("cuTensorMapEncodeTiled", &p, 12000,
                                         cudaEnableDefault, &st);
        fn = (EncodeTiledFn)p;
    }
    return fn;
}

static void encode_w3d(CUtensorMap* tm, void* ptr,
                       unsigned long long cin, unsigned long long m,
                       unsigned long long taps) {
    cuuint64_t dims[3] = {cin, m, taps};
    cuuint64_t strides[2] = {cin * 2, cin * m * 2};
    cuuint32_t box[3] = {64, 128, 1};
    cuuint32_t es[3] = {1, 1, 1};
    get_encode_fn()(tm, CU_TENSOR_MAP_DATA_TYPE_FLOAT16, 3, ptr, dims, strides,
                    box, es, CU_TENSOR_MAP_INTERLEAVE_NONE,
                    CU_TENSOR_MAP_SWIZZLE_128B,
                    CU_TENSOR_MAP_L2_PROMOTION_L2_128B,
                    CU_TENSOR_MAP_FLOAT_OOB_FILL_NONE);
}

static void encode_x4d(CUtensorMap* tm, void* ptr, unsigned long long C) {
    cuuint64_t dims[4] = {C, 64, 64, 4};
    cuuint64_t strides[3] = {C * 2, 64 * C * 2, 64ull * 64 * C * 2};
    cuuint32_t box[4] = {64, 64, 1, 1};
    cuuint32_t es[4] = {1, 1, 1, 1};
    get_encode_fn()(tm, CU_TENSOR_MAP_DATA_TYPE_FLOAT16, 4, ptr, dims, strides,
                    box, es, CU_TENSOR_MAP_INTERLEAVE_NONE,
                    CU_TENSOR_MAP_SWIZZLE_128B,
                    CU_TENSOR_MAP_L2_PROMOTION_L2_128B,
                    CU_TENSOR_MAP_FLOAT_OOB_FILL_NONE);
}

// ---------------------------------------------------------------------------
// Launch
// ---------------------------------------------------------------------------
extern "C" void kernel_launch(void* const* d_in, const int* in_sizes, int n_in,
                              void* d_out, int out_size)
{
    const float* x     = (const float*)d_in[0];
    const float* c1w   = (const float*)d_in[1];
    const float* bn1g  = (const float*)d_in[2];
    const float* bn1b  = (const float*)d_in[3];
    const float* bn1m  = (const float*)d_in[4];
    const float* bn1v  = (const float*)d_in[5];
    const float* qw    = (const float*)d_in[6];
    const float* qb    = (const float*)d_in[7];
    const float* kw    = (const float*)d_in[8];
    const float* kb    = (const float*)d_in[9];
    const float* vw    = (const float*)d_in[10];
    const float* vb    = (const float*)d_in[11];
    const float* gamma = (const float*)d_in[12];
    const float* c2w   = (const float*)d_in[13];
    const float* bn2g  = (const float*)d_in[14];
    const float* bn2b  = (const float*)d_in[15];
    const float* bn2m  = (const float*)d_in[16];
    const float* bn2v  = (const float*)d_in[17];
    float* out = (float*)d_out;

    float *fA, *fB, *gv, *gqk, *gat, *gbqk;
    __half *xh, *fh, *w1h, *w2h, *wqkh, *wvh;
    cudaGetSymbolAddress((void**)&fA, g_featsA);
    cudaGetSymbolAddress((void**)&fB, g_featsB);
    cudaGetSymbolAddress((void**)&gv, g_v);
    cudaGetSymbolAddress((void**)&gqk, g_qk);
    cudaGetSymbolAddress((void**)&gat, g_attn);
    cudaGetSymbolAddress((void**)&gbqk, g_bqk);
    cudaGetSymbolAddress((void**)&xh, g_xh);
    cudaGetSymbolAddress((void**)&fh, g_fh);
    cudaGetSymbolAddress((void**)&w1h, g_w1h);
    cudaGetSymbolAddress((void**)&w2h, g_w2h);
    cudaGetSymbolAddress((void**)&wqkh, g_wqkh);
    cudaGetSymbolAddress((void**)&wvh, g_wvh);

    static CUtensorMap tW1, tW2, tWv, tXh, tFh;
    encode_w3d(&tW1, w1h, 2048, 512, 9);
    encode_w3d(&tW2, w2h, 512, 512, 9);
    encode_w3d(&tWv, wvh, 512, 512, 1);
    encode_x4d(&tXh, xh, 2048);
    encode_x4d(&tFh, fh, 512);

    const int SMEM_TMA = 2 * 98304 + 1024;
    const int SMEM_P1  = 2 * 32768 + 1024;
    cudaFuncSetAttribute(mma_conv_tma<2048, 9, 1>, cudaFuncAttributeMaxDynamicSharedMemorySize, SMEM_TMA);
    cudaFuncSetAttribute(mma_conv_tma<512, 9, 1>,  cudaFuncAttributeMaxDynamicSharedMemorySize, SMEM_TMA);
    cudaFuncSetAttribute(mma_conv_tma<512, 1, 0>,  cudaFuncAttributeMaxDynamicSharedMemorySize, SMEM_TMA);
    cudaFuncSetAttribute(mma_proj_cg1<512>,        cudaFuncAttributeMaxDynamicSharedMemorySize, SMEM_P1);

    // ncu captures OUR launch index 3 -> conv1 stays there
    prep_wconv<<<(512 * 2048 + 255) / 256, 256>>>(c1w, w1h, 512, 2048);          // 0
    prep_act<<<dim3(128, 64, 4), dim3(32, 8)>>>(x, xh, 2048);                    // 1
    prep_wqk<<<256, 256>>>(qw, kw, qb, kb, wqkh, gbqk);                          // 2
    mma_conv_tma<2048, 9, 1><<<dim3(4, 32), 256, SMEM_TMA>>>(                    // 3: conv1
        tW1, tXh, bn1g, bn1b, bn1m, bn1v, fA, 512);
    prep_wlin<<<(512 * 512 + 255) / 256, 256>>>(vw, wvh, 512 * 512);             // 4
    prep_wconv<<<(512 * 512 + 255) / 256, 256>>>(c2w, w2h, 512, 512);            // 5

    // --- 2x criss-cross attention ---
    float* cur = fA;
    float* nxt = fB;
    for (int it = 0; it < 2; ++it) {
        if (it == 0)
            prep_act<<<dim3(128, 16, 4), dim3(32, 8)>>>(cur, fh, 512);
        mma_proj_cg1<512><<<dim3(1, 128), 256, SMEM_P1>>>(
            wqkh, fh, gbqk, gqk, 128);
        mma_conv_tma<512, 1, 0><<<dim3(4, 32), 256, SMEM_TMA>>>(
            tWv, tFh, vb, nullptr, nullptr, nullptr, gv, 512);
        energyH_kernel<<<dim3(64, 4), 256>>>(gqk, gat);
        energyW_kernel<<<dim3(64, 4), 256>>>(gqk, gat);
        softmax_kernel<<<NPIX_ / 8, 256>>>(gat);
        aggH_kernel<<<dim3(16, 4, 32), 256>>>(gv, gat, cur, nxt, gamma);
        aggW_kernel<<<dim3(64, 4, 8), 256>>>(gv, gat, nxt, gamma, fh);
        float* tmp = cur; cur = nxt; nxt = tmp;
    }

    // --- conv2 + BN + ReLU ---
    mma_conv_tma<512, 9, 1><<<dim3(4, 32), 256, SMEM_TMA>>>(
        tW2, tFh, bn2g, bn2b, bn2m, bn2v, out, 512);
}